// round 8
// baseline (speedup 1.0000x reference)
#include <cuda_runtime.h>
#include <cuda_bf16.h>
#include <math.h>
#include <stdint.h>

#define BATCH 8
#define SEQL 1024
#define DMODEL 512
#define NHEAD 8
#define DHEAD 64
#define DFF 2048
#define NLAYER 6
#define BL (BATCH * SEQL)   // 8192
#define QKVS 1536           // fused QKV row stride

typedef __nv_bfloat16 bf16;

// ---------------- scratch (device globals: no allocs allowed) -------------
__device__ __align__(128) float g_x[BL * DMODEL];
__device__ __align__(128) bf16  g_hh[BL * DMODEL];
__device__ __align__(128) bf16  g_hl[BL * DMODEL];
__device__ __align__(128) bf16  g_qkvh[BL * QKVS];
__device__ __align__(128) bf16  g_qkvl[BL * QKVS];
__device__ __align__(128) bf16  g_fh[BL * DFF];
__device__ __align__(128) bf16  g_fl[BL * DFF];

// weight regions (all [K][N] row-major, bf16 hi/lo split)
#define SZ_QKV (NLAYER * DMODEL * QKVS)
#define SZ_WO  (NLAYER * DMODEL * DMODEL)
#define SZ_W1  (NLAYER * DMODEL * DFF)
#define SZ_W2  (NLAYER * DFF * DMODEL)
#define OFF_QKV 0
#define OFF_WO  (OFF_QKV + SZ_QKV)
#define OFF_W1  (OFF_WO + SZ_WO)
#define OFF_W2  (OFF_W1 + SZ_W1)
#define WTOT    (OFF_W2 + SZ_W2)
__device__ __align__(128) bf16  g_wh[WTOT];
__device__ __align__(128) bf16  g_wl[WTOT];

// ---------------- helpers --------------------------------------------------
__device__ __forceinline__ void cp16(uint32_t s, const void* g) {
    asm volatile("cp.async.cg.shared.global [%0], [%1], 16;\n" :: "r"(s), "l"(g));
}
__device__ __forceinline__ void cp_commit() {
    asm volatile("cp.async.commit_group;\n" ::: "memory");
}
template <int N_>
__device__ __forceinline__ void cp_wait() {
    asm volatile("cp.async.wait_group %0;\n" :: "n"(N_) : "memory");
}
__device__ __forceinline__ void ldsm4(uint32_t* r, uint32_t addr) {
    asm volatile("ldmatrix.sync.aligned.m8n8.x4.shared.b16 {%0,%1,%2,%3}, [%4];"
                 : "=r"(r[0]), "=r"(r[1]), "=r"(r[2]), "=r"(r[3]) : "r"(addr));
}
__device__ __forceinline__ void ldsm4t(uint32_t* r, uint32_t addr) {
    asm volatile("ldmatrix.sync.aligned.m8n8.x4.trans.shared.b16 {%0,%1,%2,%3}, [%4];"
                 : "=r"(r[0]), "=r"(r[1]), "=r"(r[2]), "=r"(r[3]) : "r"(addr));
}
__device__ __forceinline__ void mma16816(float* c, const uint32_t* a, const uint32_t* b) {
    asm volatile(
        "mma.sync.aligned.m16n8k16.row.col.f32.bf16.bf16.f32 "
        "{%0,%1,%2,%3}, {%4,%5,%6,%7}, {%8,%9}, {%0,%1,%2,%3};"
        : "+f"(c[0]), "+f"(c[1]), "+f"(c[2]), "+f"(c[3])
        : "r"(a[0]), "r"(a[1]), "r"(a[2]), "r"(a[3]), "r"(b[0]), "r"(b[1]));
}
__device__ __forceinline__ uint32_t packbf(bf16 a, bf16 b) {
    return ((uint32_t)__bfloat16_as_ushort(b) << 16) | __bfloat16_as_ushort(a);
}
__device__ __forceinline__ void split2(float a, float b, uint32_t& hi, uint32_t& lo) {
    bf16 ha = __float2bfloat16_rn(a), hb = __float2bfloat16_rn(b);
    bf16 la = __float2bfloat16_rn(a - __bfloat162float(ha));
    bf16 lb = __float2bfloat16_rn(b - __bfloat162float(hb));
    hi = packbf(ha, hb);
    lo = packbf(la, lb);
}

// ---------------- positional embedding + add ------------------------------
__global__ void k_pos(const float* __restrict__ xin, float* __restrict__ xout) {
    int idx = blockIdx.x * 256 + threadIdx.x;
    if (idx >= BL * DMODEL) return;
    int d = idx % DMODEL;
    int l = (idx / DMODEL) % SEQL;
    int half = DMODEL / 2;
    int i = (d < half) ? d : d - half;
    float inv = powf(10000.0f, -2.0f * (float)i / (float)DMODEL);
    float ang = (float)l * inv;
    float pe = (d < half) ? sinf(ang) : cosf(ang);
    xout[idx] = xin[idx] + pe;
}

// ---------------- ONE combined weight split kernel -------------------------
__global__ void __launch_bounds__(256) k_wsplit(
    const float* __restrict__ Wq, const float* __restrict__ Wk,
    const float* __restrict__ Wv, const float* __restrict__ Wo,
    const float* __restrict__ w1, const float* __restrict__ w2,
    bf16* __restrict__ dh, bf16* __restrict__ dl) {
    uint32_t idx = (blockIdx.x * 256 + threadIdx.x) * 4;
    if (idx >= WTOT) return;
    const float* src;
    if (idx < OFF_WO) {
        uint32_t rel = idx;
        uint32_t l = rel / (DMODEL * QKVS);
        uint32_t r2 = rel - l * (DMODEL * QKVS);
        uint32_t k = r2 / QKVS;
        uint32_t j = r2 - k * QKVS;
        uint32_t sel = j >> 9;
        uint32_t jj = j & 511;
        const float* W = (sel == 0) ? Wq : (sel == 1) ? Wk : Wv;
        src = W + (size_t)l * DMODEL * DMODEL + (size_t)k * DMODEL + jj;
    } else if (idx < OFF_W1) {
        src = Wo + (idx - OFF_WO);
    } else if (idx < OFF_W2) {
        src = w1 + (idx - OFF_W1);
    } else {
        src = w2 + (idx - OFF_W2);
    }
    float4 v = *(const float4*)src;
    uint32_t h0, l0, h1, l1;
    split2(v.x, v.y, h0, l0);
    split2(v.z, v.w, h1, l1);
    uint32_t* hp = (uint32_t*)(dh + idx);
    uint32_t* lp = (uint32_t*)(dl + idx);
    hp[0] = h0; hp[1] = h1;
    lp[0] = l0; lp[1] = l1;
}

// ---------------- layernorm -> split bf16 output --------------------------
__global__ void __launch_bounds__(128) k_ln(const float* __restrict__ x,
                                            const float* __restrict__ g,
                                            const float* __restrict__ b,
                                            bf16* __restrict__ ohi,
                                            bf16* __restrict__ olo) {
    int row = blockIdx.x;
    int tid = threadIdx.x;
    const float4* xr = (const float4*)(x + (size_t)row * DMODEL);
    float4 v = xr[tid];
    __shared__ float sh[4];

    float s = v.x + v.y + v.z + v.w;
    for (int o = 16; o; o >>= 1) s += __shfl_xor_sync(0xffffffffu, s, o);
    if ((tid & 31) == 0) sh[tid >> 5] = s;
    __syncthreads();
    float mean = (sh[0] + sh[1] + sh[2] + sh[3]) * (1.0f / DMODEL);
    __syncthreads();

    float dx0 = v.x - mean, dx1 = v.y - mean, dx2 = v.z - mean, dx3 = v.w - mean;
    float s2 = dx0 * dx0 + dx1 * dx1 + dx2 * dx2 + dx3 * dx3;
    for (int o = 16; o; o >>= 1) s2 += __shfl_xor_sync(0xffffffffu, s2, o);
    if ((tid & 31) == 0) sh[tid >> 5] = s2;
    __syncthreads();
    float var = (sh[0] + sh[1] + sh[2] + sh[3]) * (1.0f / DMODEL);
    float r = rsqrtf(var + 1e-3f);

    float4 gg = ((const float4*)g)[tid];
    float4 bb = ((const float4*)b)[tid];
    float o0 = dx0 * r * gg.x + bb.x;
    float o1 = dx1 * r * gg.y + bb.y;
    float o2 = dx2 * r * gg.z + bb.z;
    float o3 = dx3 * r * gg.w + bb.w;

    uint32_t h0, l0, h1, l1;
    split2(o0, o1, h0, l0);
    split2(o2, o3, h1, l1);
    size_t off = (size_t)row * DMODEL + tid * 4;
    uint32_t* hp = (uint32_t*)(ohi + off);
    uint32_t* lp = (uint32_t*)(olo + off);
    hp[0] = h0; hp[1] = h1;
    lp[0] = l0; lp[1] = l1;
}

// ---------------- bf16x3 HMMA GEMM: 128x128 tile, GBK=32, 3-stage ----------
// Term-pass ordering: all hi*hi, then hi*lo, then lo*hi -> accumulator reuse
// distance of 8 independent MMAs (hides HMMA RAW latency).
#define GBM 128
#define GBN 128
#define GBK 32
#define NSTAGE 3
#define STAGE_ELEMS (2 * GBM * GBK + 2 * GBK * GBN)   // 16384 bf16 = 32 KB
#define STAGE_BYTES (STAGE_ELEMS * 2)
#define SOFF_AH 0
#define SOFF_AL (GBM * GBK)
#define SOFF_BH (2 * GBM * GBK)
#define SOFF_BL (2 * GBM * GBK + GBK * GBN)
#define GSMEM (NSTAGE * STAGE_BYTES)                  // 98304 bytes

template <bool BIAS, bool RELU, bool RES, bool SPLIT>
__global__ void __launch_bounds__(256, 2) k_mm(
    const bf16* __restrict__ Ah, const bf16* __restrict__ Al,
    const bf16* __restrict__ Bh, const bf16* __restrict__ Bl,
    const float* __restrict__ bias, const float* __restrict__ res,
    float* __restrict__ Cf, bf16* __restrict__ Ch, bf16* __restrict__ Cl,
    int M, int N, int K) {
    extern __shared__ bf16 sm[];
    int tid = threadIdx.x;
    int lane = tid & 31, wid = tid >> 5;
    int wm = wid >> 2;            // 0..1  (64 rows)
    int wn = wid & 3;             // 0..3  (32 cols)
    int m0 = blockIdx.y * GBM, n0 = blockIdx.x * GBN;
    uint32_t smbase = (uint32_t)__cvta_generic_to_shared(sm);

    float acc[4][4][4];
#pragma unroll
    for (int i = 0; i < 4; i++)
#pragma unroll
        for (int j = 0; j < 4; j++)
#pragma unroll
            for (int q = 0; q < 4; q++) acc[i][j][q] = 0.0f;

    int nk = K / GBK;

    auto load_stage = [&](int kt) {
        int buf = kt % NSTAGE;
        uint32_t sb = smbase + (uint32_t)buf * STAGE_BYTES;
#pragma unroll
        for (int p = 0; p < 2; p++) {       // A: 128 rows x 4 16B-chunks
            int f = p * 256 + tid;
            int r = f >> 2, c = f & 3;
            uint32_t dst = (uint32_t)(r * GBK + ((c ^ ((r >> 1) & 3)) << 3));
            size_t src = (size_t)(m0 + r) * K + kt * GBK + (c << 3);
            cp16(sb + (SOFF_AH + dst) * 2, Ah + src);
            cp16(sb + (SOFF_AL + dst) * 2, Al + src);
        }
#pragma unroll
        for (int p = 0; p < 2; p++) {       // B: 32 k-rows x 16 16B-chunks
            int f = p * 256 + tid;
            int k = f >> 4, c = f & 15;
            int cs = (c & 8) | ((c ^ (k & 7)) & 7);
            uint32_t dst = (uint32_t)(k * GBN + (cs << 3));
            size_t src = (size_t)(kt * GBK + k) * N + n0 + (c << 3);
            cp16(sb + (SOFF_BH + dst) * 2, Bh + src);
            cp16(sb + (SOFF_BL + dst) * 2, Bl + src);
        }
        cp_commit();
    };

    load_stage(0);
    if (nk > 1) load_stage(1);

    for (int kt = 0; kt < nk; kt++) {
        if (kt == nk - 1) cp_wait<0>();
        else              cp_wait<1>();
        __syncthreads();        // rendezvous: all compute(kt-1) done, stage kt visible
        if (kt + 2 < nk) load_stage(kt + 2);
        uint32_t sb = smbase + (uint32_t)(kt % NSTAGE) * STAGE_BYTES;

#pragma unroll
        for (int ks = 0; ks < GBK / 16; ks++) {
            // A frags: 4 m-tiles, hi+lo
            uint32_t ah[4][4], al[4][4];
#pragma unroll
            for (int mt = 0; mt < 4; mt++) {
                int row = wm * 64 + mt * 16 + (lane & 15);
                int kc = ks * 2 + (lane >> 4);           // 16B-chunk 0..3
                uint32_t off = (uint32_t)(row * GBK + ((kc ^ ((row >> 1) & 3)) << 3)) * 2;
                ldsm4(ah[mt], sb + SOFF_AH * 2 + off);
                ldsm4(al[mt], sb + SOFF_AL * 2 + off);
            }
#pragma unroll
            for (int np = 0; np < 2; np++) {
                uint32_t bh[2][2], bl[2][2];
                {
                    int krow = ks * 16 + (lane & 15);
                    int nc = wn * 4 + np * 2 + (lane >> 4);     // 16B-chunk 0..15
                    int ncs = (nc & 8) | ((nc ^ (krow & 7)) & 7);
                    uint32_t off = (uint32_t)(krow * GBN + (ncs << 3)) * 2;
                    uint32_t r[4];
                    ldsm4t(r, sb + SOFF_BH * 2 + off);
                    bh[0][0] = r[0]; bh[0][1] = r[1];
                    bh[1][0] = r[2]; bh[1][1] = r[3];
                    ldsm4t(r, sb + SOFF_BL * 2 + off);
                    bl[0][0] = r[0]; bl[0][1] = r[1];
                    bl[1][0] = r[2]; bl[1][1] = r[3];
                }
                // term pass 1: hi * hi  (8 independent accs before reuse)
#pragma unroll
                for (int mt = 0; mt < 4; mt++)
#pragma unroll
                    for (int j = 0; j < 2; j++)
                        mma16816(acc[mt][np * 2 + j], ah[mt], bh[j]);
                // term pass 2: hi * lo
#pragma unroll
                for (int mt = 0; mt < 4; mt++)
#pragma unroll
                    for (int j = 0; j < 2; j++)
                        mma16816(acc[mt][np * 2 + j], ah[mt], bl[j]);
                // term pass 3: lo * hi
#pragma unroll
                for (int mt = 0; mt < 4; mt++)
#pragma unroll
                    for (int j = 0; j < 2; j++)
                        mma16816(acc[mt][np * 2 + j], al[mt], bh[j]);
            }
        }
        // no bottom barrier: next iteration's top barrier protects buffer reuse
    }

#pragma unroll
    for (int mt = 0; mt < 4; mt++)
#pragma unroll
        for (int nt = 0; nt < 4; nt++) {
            int rbase = m0 + wm * 64 + mt * 16 + (lane >> 2);
            int cbase = n0 + wn * 32 + nt * 8 + (lane & 3) * 2;
#pragma unroll
            for (int half = 0; half < 2; half++) {
                int r = rbase + half * 8;
                float c0 = acc[mt][nt][half * 2 + 0];
                float c1 = acc[mt][nt][half * 2 + 1];
                size_t off = (size_t)r * N + cbase;
                if (BIAS) { c0 += bias[cbase]; c1 += bias[cbase + 1]; }
                if (RES)  { float2 rv = *(const float2*)(res + off); c0 += rv.x; c1 += rv.y; }
                if (RELU) { c0 = fmaxf(c0, 0.f); c1 = fmaxf(c1, 0.f); }
                if (SPLIT) {
                    uint32_t hi, lo;
                    split2(c0, c1, hi, lo);
                    *(uint32_t*)(Ch + off) = hi;
                    *(uint32_t*)(Cl + off) = lo;
                } else {
                    *(float2*)(Cf + off) = make_float2(c0, c1);
                }
            }
        }
}

// ---------------- tensor-core flash attention (reads fused QKV buffer) -----
#define FBR 128
#define FBC 64
#define FQ_H 0
#define FQ_L (FBR * 64)
#define FKV0 (2 * FBR * 64)
#define FKV_STRIDE (4 * FBC * 64)
#define FK_H 0
#define FK_L (FBC * 64)
#define FV_H (2 * FBC * 64)
#define FV_L (3 * FBC * 64)
#define FSMEM ((2 * FBR * 64 + 2 * FKV_STRIDE) * 2)

__global__ void __launch_bounds__(256, 1) k_fattn(
    const bf16* __restrict__ QKVh, const bf16* __restrict__ QKVl,
    const int* __restrict__ lengths,
    bf16* __restrict__ Oh, bf16* __restrict__ Ol) {
    extern __shared__ bf16 sm[];
    uint32_t smb = (uint32_t)__cvta_generic_to_shared(sm);
    int b = blockIdx.z, h = blockIdx.y, qt = blockIdx.x;
    int len = lengths[b];
    int tid = threadIdx.x, lane = tid & 31, wid = tid >> 5;
    size_t qrow0 = (size_t)(b * SEQL + qt * FBR);
    size_t hoff = (size_t)h * DHEAD;

    auto load_kv = [&](int kt, int stg) {
        uint32_t sb = smb + (uint32_t)(FKV0 + stg * FKV_STRIDE) * 2;
        int kb = kt * FBC;
#pragma unroll
        for (int p = 0; p < 2; p++) {
            int f = p * 256 + tid;
            int r = f >> 3, c = f & 7;
            uint32_t d = (uint32_t)((r * 64 + ((c ^ (r & 7)) << 3)) * 2);
            size_t src = (size_t)(b * SEQL + kb + r) * QKVS + hoff + (c << 3);
            cp16(sb + FK_H * 2 + d, QKVh + src + 512);
            cp16(sb + FK_L * 2 + d, QKVl + src + 512);
            cp16(sb + FV_H * 2 + d, QKVh + src + 1024);
            cp16(sb + FV_L * 2 + d, QKVl + src + 1024);
        }
        cp_commit();
    };

    load_kv(0, 0);

#pragma unroll
    for (int p = 0; p < 4; p++) {
        int f = p * 256 + tid;
        int r = f >> 3, c = f & 7;
        uint32_t d = (uint32_t)(r * 64 + ((c ^ (r & 7)) << 3));
        size_t src = (qrow0 + r) * QKVS + hoff + (c << 3);
        *(uint4*)(sm + FQ_H + d) = *(const uint4*)(QKVh + src);
        *(uint4*)(sm + FQ_L + d) = *(const uint4*)(QKVl + src);
    }
    __syncthreads();

    uint32_t qh[4][4], ql[4][4];
#pragma unroll
    for (int ks = 0; ks < 4; ks++) {
        int row = wid * 16 + (lane & 15);
        int kc = ks * 2 + (lane >> 4);
        uint32_t off = (uint32_t)(row * 64 + ((kc ^ (row & 7)) << 3)) * 2;
        ldsm4(qh[ks], smb + FQ_H * 2 + off);
        ldsm4(ql[ks], smb + FQ_L * 2 + off);
    }

    float o[8][4];
#pragma unroll
    for (int i = 0; i < 8; i++)
#pragma unroll
        for (int j = 0; j < 4; j++) o[i][j] = 0.0f;
    float m0 = -3.0e38f, m1 = -3.0e38f, l0 = 0.0f, l1 = 0.0f;

    int nkt = (len + FBC - 1) / FBC;
    for (int kt = 0; kt < nkt; kt++) {
        if (kt + 1 < nkt) { load_kv(kt + 1, (kt + 1) & 1); cp_wait<1>(); }
        else              { cp_wait<0>(); }
        __syncthreads();
        uint32_t sb = smb + (uint32_t)(FKV0 + (kt & 1) * FKV_STRIDE) * 2;

        float s[8][4];
#pragma unroll
        for (int i = 0; i < 8; i++)
#pragma unroll
            for (int j = 0; j < 4; j++) s[i][j] = 0.0f;

#pragma unroll
        for (int ks = 0; ks < 4; ks++) {
#pragma unroll
            for (int kg = 0; kg < 4; kg++) {
                int key = kg * 16 + (lane & 15);
                int kc = ks * 2 + (lane >> 4);
                uint32_t off = (uint32_t)(key * 64 + ((kc ^ (key & 7)) << 3)) * 2;
                uint32_t rh[4], rl[4];
                ldsm4(rh, sb + FK_H * 2 + off);
                ldsm4(rl, sb + FK_L * 2 + off);
                uint32_t bh0[2] = {rh[0], rh[2]}, bh1[2] = {rh[1], rh[3]};
                uint32_t bl0[2] = {rl[0], rl[2]}, bl1[2] = {rl[1], rl[3]};
                // interleaved term order: distance-2 accumulator reuse
                mma16816(s[kg * 2],     qh[ks], bh0);
                mma16816(s[kg * 2 + 1], qh[ks], bh1);
                mma16816(s[kg * 2],     qh[ks], bl0);
                mma16816(s[kg * 2 + 1], qh[ks], bl1);
                mma16816(s[kg * 2],     ql[ks], bh0);
                mma16816(s[kg * 2 + 1], ql[ks], bh1);
            }
        }

        int colbase = kt * FBC + (lane & 3) * 2;
        float mx0 = -3.0e38f, mx1 = -3.0e38f;
#pragma unroll
        for (int nf = 0; nf < 8; nf++) {
            int c = colbase + nf * 8;
            float b0 = (c     >= len) ? -1e9f : 0.0f;
            float b1 = (c + 1 >= len) ? -1e9f : 0.0f;
            s[nf][0] = s[nf][0] * 0.125f + b0;
            s[nf][1] = s[nf][1] * 0.125f + b1;
            s[nf][2] = s[nf][2] * 0.125f + b0;
            s[nf][3] = s[nf][3] * 0.125f + b1;
            mx0 = fmaxf(mx0, fmaxf(s[nf][0], s[nf][1]));
            mx1 = fmaxf(mx1, fmaxf(s[nf][2], s[nf][3]));
        }
        mx0 = fmaxf(mx0, __shfl_xor_sync(0xffffffffu, mx0, 1));
        mx0 = fmaxf(mx0, __shfl_xor_sync(0xffffffffu, mx0, 2));
        mx1 = fmaxf(mx1, __shfl_xor_sync(0xffffffffu, mx1, 1));
        mx1 = fmaxf(mx1, __shfl_xor_sync(0xffffffffu, mx1, 2));
        float mn0 = fmaxf(m0, mx0), mn1 = fmaxf(m1, mx1);
        float a0 = __expf(m0 - mn0), a1 = __expf(m1 - mn1);
        float ls0 = 0.0f, ls1 = 0.0f;
#pragma unroll
        for (int nf = 0; nf < 8; nf++) {
            s[nf][0] = __expf(s[nf][0] - mn0);
            s[nf][1] = __expf(s[nf][1] - mn0);
            s[nf][2] = __expf(s[nf][2] - mn1);
            s[nf][3] = __expf(s[nf][3] - mn1);
            ls0 += s[nf][0] + s[nf][1];
            ls1 += s[nf][2] + s[nf][3];
        }
        ls0 += __shfl_xor_sync(0xffffffffu, ls0, 1);
        ls0 += __shfl_xor_sync(0xffffffffu, ls0, 2);
        ls1 += __shfl_xor_sync(0xffffffffu, ls1, 1);
        ls1 += __shfl_xor_sync(0xffffffffu, ls1, 2);
        l0 = l0 * a0 + ls0;
        l1 = l1 * a1 + ls1;
        m0 = mn0; m1 = mn1;
#pragma unroll
        for (int nf = 0; nf < 8; nf++) {
            o[nf][0] *= a0; o[nf][1] *= a0;
            o[nf][2] *= a1; o[nf][3] *= a1;
        }

#pragma unroll
        for (int kg = 0; kg < 4; kg++) {
            uint32_t ph[4], pl[4];
            split2(s[2 * kg][0], s[2 * kg][1], ph[0], pl[0]);
            split2(s[2 * kg][2], s[2 * kg][3], ph[1], pl[1]);
            split2(s[2 * kg + 1][0], s[2 * kg + 1][1], ph[2], pl[2]);
            split2(s[2 * kg + 1][2], s[2 * kg + 1][3], ph[3], pl[3]);
#pragma unroll
            for (int np = 0; np < 4; np++) {
                int krow = kg * 16 + (lane & 15);
                int nc = np * 2 + (lane >> 4);
                uint32_t off = (uint32_t)(krow * 64 + ((nc ^ (krow & 7)) << 3)) * 2;
                uint32_t rh[4], rl[4];
                ldsm4t(rh, sb + FV_H * 2 + off);
                ldsm4t(rl, sb + FV_L * 2 + off);
                uint32_t vh0[2] = {rh[0], rh[1]}, vh1[2] = {rh[2], rh[3]};
                uint32_t vl0[2] = {rl[0], rl[1]}, vl1[2] = {rl[2], rl[3]};
                // interleaved: distance-2 accumulator reuse
                mma16816(o[np * 2],     ph, vh0);
                mma16816(o[np * 2 + 1], ph, vh1);
                mma16816(o[np * 2],     ph, vl0);
                mma16816(o[np * 2 + 1], ph, vl1);
                mma16816(o[np * 2],     pl, vh0);
                mma16816(o[np * 2 + 1], pl, vh1);
            }
        }
        __syncthreads();
    }

    float li0 = 1.0f / l0, li1 = 1.0f / l1;
    int r0 = wid * 16 + (lane >> 2);
    size_t row0 = (qrow0 + r0) * DMODEL + hoff + (lane & 3) * 2;
    size_t row1 = (qrow0 + r0 + 8) * DMODEL + hoff + (lane & 3) * 2;
#pragma unroll
    for (int nf = 0; nf < 8; nf++) {
        uint32_t hi, lo;
        split2(o[nf][0] * li0, o[nf][1] * li0, hi, lo);
        *(uint32_t*)(Oh + row0 + nf * 8) = hi;
        *(uint32_t*)(Ol + row0 + nf * 8) = lo;
        split2(o[nf][2] * li1, o[nf][3] * li1, hi, lo);
        *(uint32_t*)(Oh + row1 + nf * 8) = hi;
        *(uint32_t*)(Ol + row1 + nf * 8) = lo;
    }
}

// ---------------- orchestration -------------------------------------------
extern "C" void kernel_launch(void* const* d_in, const int* in_sizes, int n_in,
                              void* d_out, int out_size) {
    (void)in_sizes; (void)n_in; (void)out_size;
    const float* x_in    = (const float*)d_in[0];
    const int*   lengths = (const int*)d_in[1];
    const float* Wq = (const float*)d_in[2];
    const float* Wk = (const float*)d_in[3];
    const float* Wv = (const float*)d_in[4];
    const float* Wo = (const float*)d_in[5];
    const float* ln1g = (const float*)d_in[6];
    const float* ln1b = (const float*)d_in[7];
    const float* ln2g = (const float*)d_in[8];
    const float* ln2b = (const float*)d_in[9];
    const float* w1 = (const float*)d_in[10];
    const float* b1 = (const float*)d_in[11];
    const float* w2 = (const float*)d_in[12];
    const float* b2 = (const float*)d_in[13];

    float* px;
    bf16 *phh, *phl, *pqkvh, *pqkvl, *pfh, *pfl, *pwh, *pwl;
    cudaGetSymbolAddress((void**)&px, g_x);
    cudaGetSymbolAddress((void**)&phh, g_hh);
    cudaGetSymbolAddress((void**)&phl, g_hl);
    cudaGetSymbolAddress((void**)&pqkvh, g_qkvh);
    cudaGetSymbolAddress((void**)&pqkvl, g_qkvl);
    cudaGetSymbolAddress((void**)&pfh, g_fh);
    cudaGetSymbolAddress((void**)&pfl, g_fl);
    cudaGetSymbolAddress((void**)&pwh, g_wh);
    cudaGetSymbolAddress((void**)&pwl, g_wl);

    cudaFuncSetAttribute(k_fattn, cudaFuncAttributeMaxDynamicSharedMemorySize, FSMEM);
    cudaFuncSetAttribute(k_mm<false, false, false, true>,
                         cudaFuncAttributeMaxDynamicSharedMemorySize, GSMEM);
    cudaFuncSetAttribute(k_mm<false, false, true, false>,
                         cudaFuncAttributeMaxDynamicSharedMemorySize, GSMEM);
    cudaFuncSetAttribute(k_mm<true, true, false, true>,
                         cudaFuncAttributeMaxDynamicSharedMemorySize, GSMEM);
    cudaFuncSetAttribute(k_mm<true, false, true, false>,
                         cudaFuncAttributeMaxDynamicSharedMemorySize, GSMEM);

    k_wsplit<<<(WTOT / 4 + 255) / 256, 256>>>(Wq, Wk, Wv, Wo, w1, w2, pwh, pwl);
    k_pos<<<(BL * DMODEL) / 256, 256>>>(x_in, px);

    dim3 gQKV(QKVS / GBN, BL / GBM);   // (12, 64)
    dim3 gD(DMODEL / GBN, BL / GBM);   // (4, 64)
    dim3 gF(DFF / GBN, BL / GBM);      // (16, 64)
    dim3 gA(SEQL / FBR, NHEAD, BATCH);

    for (int layer = 0; layer < NLAYER; layer++) {
        const bf16* qkvh = pwh + OFF_QKV + (size_t)layer * DMODEL * QKVS;
        const bf16* qkvl = pwl + OFF_QKV + (size_t)layer * DMODEL * QKVS;
        const bf16* woh  = pwh + OFF_WO + (size_t)layer * DMODEL * DMODEL;
        const bf16* wol  = pwl + OFF_WO + (size_t)layer * DMODEL * DMODEL;
        const bf16* w1h  = pwh + OFF_W1 + (size_t)layer * DMODEL * DFF;
        const bf16* w1l  = pwl + OFF_W1 + (size_t)layer * DMODEL * DFF;
        const bf16* w2h  = pwh + OFF_W2 + (size_t)layer * DFF * DMODEL;
        const bf16* w2l  = pwl + OFF_W2 + (size_t)layer * DFF * DMODEL;

        k_ln<<<BL, 128>>>(px, ln1g + (size_t)layer * DMODEL, ln1b + (size_t)layer * DMODEL,
                          phh, phl);
        k_mm<false, false, false, true><<<gQKV, 256, GSMEM>>>(
            phh, phl, qkvh, qkvl, nullptr, nullptr, nullptr, pqkvh, pqkvl,
            BL, QKVS, DMODEL);
        k_fattn<<<gA, 256, FSMEM>>>(pqkvh, pqkvl, lengths, phh, phl);
        k_mm<false, false, true, false><<<gD, 256, GSMEM>>>(
            phh, phl, woh, wol, nullptr, px, px, nullptr, nullptr, BL, DMODEL, DMODEL);

        k_ln<<<BL, 128>>>(px, ln2g + (size_t)layer * DMODEL, ln2b + (size_t)layer * DMODEL,
                          phh, phl);
        k_mm<true, true, false, true><<<gF, 256, GSMEM>>>(
            phh, phl, w1h, w1l, b1 + (size_t)layer * DFF, nullptr,
            nullptr, pfh, pfl, BL, DFF, DMODEL);
        float* dst = (layer == NLAYER - 1) ? (float*)d_out : px;
        k_mm<true, false, true, false><<<gD, 256, GSMEM>>>(
            pfh, pfl, w2h, w2l, b2 + (size_t)layer * DMODEL, px,
            dst, nullptr, nullptr, BL, DMODEL, DFF);
    }
}

// round 9
// speedup vs baseline: 1.1493x; 1.1493x over previous
#include <cuda_runtime.h>
#include <cuda_fp16.h>
#include <math.h>
#include <stdint.h>

#define BATCH 8
#define SEQL 1024
#define DMODEL 512
#define NHEAD 8
#define DHEAD 64
#define DFF 2048
#define NLAYER 6
#define BL (BATCH * SEQL)   // 8192
#define QKVS 1536           // fused QKV row stride

typedef __half f16;

// ---------------- scratch (device globals: no allocs allowed) -------------
__device__ __align__(128) float g_x[BL * DMODEL];
__device__ __align__(128) f16   g_hh[BL * DMODEL];
__device__ __align__(128) f16   g_hl[BL * DMODEL];
__device__ __align__(128) f16   g_qkvh[BL * QKVS];
__device__ __align__(128) f16   g_qkvl[BL * QKVS];
__device__ __align__(128) f16   g_fh[BL * DFF];
__device__ __align__(128) f16   g_fl[BL * DFF];

// weight regions (all [K][N] row-major, fp16 hi/lo split)
#define SZ_QKV (NLAYER * DMODEL * QKVS)
#define SZ_WO  (NLAYER * DMODEL * DMODEL)
#define SZ_W1  (NLAYER * DMODEL * DFF)
#define SZ_W2  (NLAYER * DFF * DMODEL)
#define OFF_QKV 0
#define OFF_WO  (OFF_QKV + SZ_QKV)
#define OFF_W1  (OFF_WO + SZ_WO)
#define OFF_W2  (OFF_W1 + SZ_W1)
#define WTOT    (OFF_W2 + SZ_W2)
__device__ __align__(128) f16   g_wh[WTOT];
__device__ __align__(128) f16   g_wl[WTOT];

// ---------------- helpers --------------------------------------------------
__device__ __forceinline__ void cp16(uint32_t s, const void* g) {
    asm volatile("cp.async.cg.shared.global [%0], [%1], 16;\n" :: "r"(s), "l"(g));
}
__device__ __forceinline__ void cp_commit() {
    asm volatile("cp.async.commit_group;\n" ::: "memory");
}
template <int N_>
__device__ __forceinline__ void cp_wait() {
    asm volatile("cp.async.wait_group %0;\n" :: "n"(N_) : "memory");
}
__device__ __forceinline__ void ldsm4(uint32_t* r, uint32_t addr) {
    asm volatile("ldmatrix.sync.aligned.m8n8.x4.shared.b16 {%0,%1,%2,%3}, [%4];"
                 : "=r"(r[0]), "=r"(r[1]), "=r"(r[2]), "=r"(r[3]) : "r"(addr));
}
__device__ __forceinline__ void ldsm4t(uint32_t* r, uint32_t addr) {
    asm volatile("ldmatrix.sync.aligned.m8n8.x4.trans.shared.b16 {%0,%1,%2,%3}, [%4];"
                 : "=r"(r[0]), "=r"(r[1]), "=r"(r[2]), "=r"(r[3]) : "r"(addr));
}
__device__ __forceinline__ void mma16816(float* c, const uint32_t* a, const uint32_t* b) {
    asm volatile(
        "mma.sync.aligned.m16n8k16.row.col.f32.f16.f16.f32 "
        "{%0,%1,%2,%3}, {%4,%5,%6,%7}, {%8,%9}, {%0,%1,%2,%3};"
        : "+f"(c[0]), "+f"(c[1]), "+f"(c[2]), "+f"(c[3])
        : "r"(a[0]), "r"(a[1]), "r"(a[2]), "r"(a[3]), "r"(b[0]), "r"(b[1]));
}
__device__ __forceinline__ uint32_t packh(f16 a, f16 b) {
    return ((uint32_t)__half_as_ushort(b) << 16) | __half_as_ushort(a);
}
__device__ __forceinline__ void split2(float a, float b, uint32_t& hi, uint32_t& lo) {
    f16 ha = __float2half_rn(a), hb = __float2half_rn(b);
    f16 la = __float2half_rn(a - __half2float(ha));
    f16 lb = __float2half_rn(b - __half2float(hb));
    hi = packh(ha, hb);
    lo = packh(la, lb);
}

// ---------------- positional embedding + add ------------------------------
__global__ void k_pos(const float* __restrict__ xin, float* __restrict__ xout) {
    int idx = blockIdx.x * 256 + threadIdx.x;
    if (idx >= BL * DMODEL) return;
    int d = idx % DMODEL;
    int l = (idx / DMODEL) % SEQL;
    int half = DMODEL / 2;
    int i = (d < half) ? d : d - half;
    float inv = powf(10000.0f, -2.0f * (float)i / (float)DMODEL);
    float ang = (float)l * inv;
    float pe = (d < half) ? sinf(ang) : cosf(ang);
    xout[idx] = xin[idx] + pe;
}

// ---------------- ONE combined weight split kernel -------------------------
__global__ void __launch_bounds__(256) k_wsplit(
    const float* __restrict__ Wq, const float* __restrict__ Wk,
    const float* __restrict__ Wv, const float* __restrict__ Wo,
    const float* __restrict__ w1, const float* __restrict__ w2,
    f16* __restrict__ dh, f16* __restrict__ dl) {
    uint32_t idx = (blockIdx.x * 256 + threadIdx.x) * 4;
    if (idx >= WTOT) return;
    const float* src;
    if (idx < OFF_WO) {
        uint32_t rel = idx;
        uint32_t l = rel / (DMODEL * QKVS);
        uint32_t r2 = rel - l * (DMODEL * QKVS);
        uint32_t k = r2 / QKVS;
        uint32_t j = r2 - k * QKVS;
        uint32_t sel = j >> 9;
        uint32_t jj = j & 511;
        const float* W = (sel == 0) ? Wq : (sel == 1) ? Wk : Wv;
        src = W + (size_t)l * DMODEL * DMODEL + (size_t)k * DMODEL + jj;
    } else if (idx < OFF_W1) {
        src = Wo + (idx - OFF_WO);
    } else if (idx < OFF_W2) {
        src = w1 + (idx - OFF_W1);
    } else {
        src = w2 + (idx - OFF_W2);
    }
    float4 v = *(const float4*)src;
    uint32_t h0, l0, h1, l1;
    split2(v.x, v.y, h0, l0);
    split2(v.z, v.w, h1, l1);
    uint32_t* hp = (uint32_t*)(dh + idx);
    uint32_t* lp = (uint32_t*)(dl + idx);
    hp[0] = h0; hp[1] = h1;
    lp[0] = l0; lp[1] = l1;
}

// ---------------- layernorm -> split fp16 output --------------------------
__global__ void __launch_bounds__(128) k_ln(const float* __restrict__ x,
                                            const float* __restrict__ g,
                                            const float* __restrict__ b,
                                            f16* __restrict__ ohi,
                                            f16* __restrict__ olo) {
    int row = blockIdx.x;
    int tid = threadIdx.x;
    const float4* xr = (const float4*)(x + (size_t)row * DMODEL);
    float4 v = xr[tid];
    __shared__ float sh[4];

    float s = v.x + v.y + v.z + v.w;
    for (int o = 16; o; o >>= 1) s += __shfl_xor_sync(0xffffffffu, s, o);
    if ((tid & 31) == 0) sh[tid >> 5] = s;
    __syncthreads();
    float mean = (sh[0] + sh[1] + sh[2] + sh[3]) * (1.0f / DMODEL);
    __syncthreads();

    float dx0 = v.x - mean, dx1 = v.y - mean, dx2 = v.z - mean, dx3 = v.w - mean;
    float s2 = dx0 * dx0 + dx1 * dx1 + dx2 * dx2 + dx3 * dx3;
    for (int o = 16; o; o >>= 1) s2 += __shfl_xor_sync(0xffffffffu, s2, o);
    if ((tid & 31) == 0) sh[tid >> 5] = s2;
    __syncthreads();
    float var = (sh[0] + sh[1] + sh[2] + sh[3]) * (1.0f / DMODEL);
    float r = rsqrtf(var + 1e-3f);

    float4 gg = ((const float4*)g)[tid];
    float4 bb = ((const float4*)b)[tid];
    float o0 = dx0 * r * gg.x + bb.x;
    float o1 = dx1 * r * gg.y + bb.y;
    float o2 = dx2 * r * gg.z + bb.z;
    float o3 = dx3 * r * gg.w + bb.w;

    uint32_t h0, l0, h1, l1;
    split2(o0, o1, h0, l0);
    split2(o2, o3, h1, l1);
    size_t off = (size_t)row * DMODEL + tid * 4;
    uint32_t* hp = (uint32_t*)(ohi + off);
    uint32_t* lp = (uint32_t*)(olo + off);
    hp[0] = h0; hp[1] = h1;
    lp[0] = l0; lp[1] = l1;
}

// ---------------- fp16 split HMMA GEMM: 128x128, GBK=32, 3-stage -----------
// TERMS==3: C = Ah*Bh + Ah*Bl + Al*Bh   (error ~2^-22)
// TERMS==2: C = Ah*B  + Al*B   (B single fp16; error ~2^-12.6, FFN only)
#define GBM 128
#define GBN 128
#define GBK 32
#define NSTAGE 3
#define STAGE_ELEMS (2 * GBM * GBK + 2 * GBK * GBN)   // 16384 f16 = 32 KB
#define STAGE_BYTES (STAGE_ELEMS * 2)
#define SOFF_AH 0
#define SOFF_AL (GBM * GBK)
#define SOFF_BH (2 * GBM * GBK)
#define SOFF_BL (2 * GBM * GBK + GBK * GBN)
#define GSMEM (NSTAGE * STAGE_BYTES)                  // 98304 bytes

template <int TERMS, bool BIAS, bool RELU, bool RES, bool SPLIT>
__global__ void __launch_bounds__(256, 2) k_mm(
    const f16* __restrict__ Ah, const f16* __restrict__ Al,
    const f16* __restrict__ Bh, const f16* __restrict__ Bl,
    const float* __restrict__ bias, const float* __restrict__ res,
    float* __restrict__ Cf, f16* __restrict__ Ch, f16* __restrict__ Cl,
    int M, int N, int K) {
    extern __shared__ f16 sm[];
    int tid = threadIdx.x;
    int lane = tid & 31, wid = tid >> 5;
    int wm = wid >> 2;            // 0..1  (64 rows)
    int wn = wid & 3;             // 0..3  (32 cols)
    int m0 = blockIdx.y * GBM, n0 = blockIdx.x * GBN;
    uint32_t smbase = (uint32_t)__cvta_generic_to_shared(sm);

    float acc[4][4][4];
#pragma unroll
    for (int i = 0; i < 4; i++)
#pragma unroll
        for (int j = 0; j < 4; j++)
#pragma unroll
            for (int q = 0; q < 4; q++) acc[i][j][q] = 0.0f;

    int nk = K / GBK;

    auto load_stage = [&](int kt) {
        int buf = kt % NSTAGE;
        uint32_t sb = smbase + (uint32_t)buf * STAGE_BYTES;
#pragma unroll
        for (int p = 0; p < 2; p++) {       // A: 128 rows x 4 16B-chunks
            int f = p * 256 + tid;
            int r = f >> 2, c = f & 3;
            uint32_t dst = (uint32_t)(r * GBK + ((c ^ ((r >> 1) & 3)) << 3));
            size_t src = (size_t)(m0 + r) * K + kt * GBK + (c << 3);
            cp16(sb + (SOFF_AH + dst) * 2, Ah + src);
            cp16(sb + (SOFF_AL + dst) * 2, Al + src);
        }
#pragma unroll
        for (int p = 0; p < 2; p++) {       // B: 32 k-rows x 16 16B-chunks
            int f = p * 256 + tid;
            int k = f >> 4, c = f & 15;
            int cs = (c & 8) | ((c ^ (k & 7)) & 7);
            uint32_t dst = (uint32_t)(k * GBN + (cs << 3));
            size_t src = (size_t)(kt * GBK + k) * N + n0 + (c << 3);
            cp16(sb + (SOFF_BH + dst) * 2, Bh + src);
            if (TERMS == 3) cp16(sb + (SOFF_BL + dst) * 2, Bl + src);
        }
        cp_commit();
    };

    load_stage(0);
    if (nk > 1) load_stage(1);

    for (int kt = 0; kt < nk; kt++) {
        if (kt == nk - 1) cp_wait<0>();
        else              cp_wait<1>();
        __syncthreads();        // rendezvous: compute(kt-1) done, stage kt visible
        if (kt + 2 < nk) load_stage(kt + 2);
        uint32_t sb = smbase + (uint32_t)(kt % NSTAGE) * STAGE_BYTES;

#pragma unroll
        for (int ks = 0; ks < GBK / 16; ks++) {
            uint32_t ah[4][4], al[4][4];
#pragma unroll
            for (int mt = 0; mt < 4; mt++) {
                int row = wm * 64 + mt * 16 + (lane & 15);
                int kc = ks * 2 + (lane >> 4);
                uint32_t off = (uint32_t)(row * GBK + ((kc ^ ((row >> 1) & 3)) << 3)) * 2;
                ldsm4(ah[mt], sb + SOFF_AH * 2 + off);
                ldsm4(al[mt], sb + SOFF_AL * 2 + off);
            }
#pragma unroll
            for (int np = 0; np < 2; np++) {
                uint32_t bh[2][2], bl[2][2];
                {
                    int krow = ks * 16 + (lane & 15);
                    int nc = wn * 4 + np * 2 + (lane >> 4);
                    int ncs = (nc & 8) | ((nc ^ (krow & 7)) & 7);
                    uint32_t off = (uint32_t)(krow * GBN + (ncs << 3)) * 2;
                    uint32_t r[4];
                    ldsm4t(r, sb + SOFF_BH * 2 + off);
                    bh[0][0] = r[0]; bh[0][1] = r[1];
                    bh[1][0] = r[2]; bh[1][1] = r[3];
                    if (TERMS == 3) {
                        ldsm4t(r, sb + SOFF_BL * 2 + off);
                        bl[0][0] = r[0]; bl[0][1] = r[1];
                        bl[1][0] = r[2]; bl[1][1] = r[3];
                    }
                }
                // pass 1: Ah * Bh
#pragma unroll
                for (int mt = 0; mt < 4; mt++)
#pragma unroll
                    for (int j = 0; j < 2; j++)
                        mma16816(acc[mt][np * 2 + j], ah[mt], bh[j]);
                // pass 2: Al * Bh
#pragma unroll
                for (int mt = 0; mt < 4; mt++)
#pragma unroll
                    for (int j = 0; j < 2; j++)
                        mma16816(acc[mt][np * 2 + j], al[mt], bh[j]);
                if (TERMS == 3) {
                    // pass 3: Ah * Bl
#pragma unroll
                    for (int mt = 0; mt < 4; mt++)
#pragma unroll
                        for (int j = 0; j < 2; j++)
                            mma16816(acc[mt][np * 2 + j], ah[mt], bl[j]);
                }
            }
        }
    }

#pragma unroll
    for (int mt = 0; mt < 4; mt++)
#pragma unroll
        for (int nt = 0; nt < 4; nt++) {
            int rbase = m0 + wm * 64 + mt * 16 + (lane >> 2);
            int cbase = n0 + wn * 32 + nt * 8 + (lane & 3) * 2;
#pragma unroll
            for (int half = 0; half < 2; half++) {
                int r = rbase + half * 8;
                float c0 = acc[mt][nt][half * 2 + 0];
                float c1 = acc[mt][nt][half * 2 + 1];
                size_t off = (size_t)r * N + cbase;
                if (BIAS) { c0 += bias[cbase]; c1 += bias[cbase + 1]; }
                if (RES)  { float2 rv = *(const float2*)(res + off); c0 += rv.x; c1 += rv.y; }
                if (RELU) { c0 = fmaxf(c0, 0.f); c1 = fmaxf(c1, 0.f); }
                if (SPLIT) {
                    uint32_t hi, lo;
                    split2(c0, c1, hi, lo);
                    *(uint32_t*)(Ch + off) = hi;
                    *(uint32_t*)(Cl + off) = lo;
                } else {
                    *(float2*)(Cf + off) = make_float2(c0, c1);
                }
            }
        }
}

// ---------------- tensor-core flash attention (fused QKV buffer) -----------
// S = Q K^T 3-term fp16 (protect logits); P V 2-term (V hi only).
#define FBR 128
#define FBC 64
#define FQ_H 0
#define FQ_L (FBR * 64)
#define FKV0 (2 * FBR * 64)
#define FKV_STRIDE (3 * FBC * 64)
#define FK_H 0
#define FK_L (FBC * 64)
#define FV_H (2 * FBC * 64)
#define FSMEM ((2 * FBR * 64 + 2 * FKV_STRIDE) * 2)   // 81920 bytes

__global__ void __launch_bounds__(256, 1) k_fattn(
    const f16* __restrict__ QKVh, const f16* __restrict__ QKVl,
    const int* __restrict__ lengths,
    f16* __restrict__ Oh, f16* __restrict__ Ol) {
    extern __shared__ f16 sm[];
    uint32_t smb = (uint32_t)__cvta_generic_to_shared(sm);
    int b = blockIdx.z, h = blockIdx.y, qt = blockIdx.x;
    int len = lengths[b];
    int tid = threadIdx.x, lane = tid & 31, wid = tid >> 5;
    size_t qrow0 = (size_t)(b * SEQL + qt * FBR);
    size_t hoff = (size_t)h * DHEAD;

    auto load_kv = [&](int kt, int stg) {
        uint32_t sb = smb + (uint32_t)(FKV0 + stg * FKV_STRIDE) * 2;
        int kb = kt * FBC;
#pragma unroll
        for (int p = 0; p < 2; p++) {
            int f = p * 256 + tid;
            int r = f >> 3, c = f & 7;
            uint32_t d = (uint32_t)((r * 64 + ((c ^ (r & 7)) << 3)) * 2);
            size_t src = (size_t)(b * SEQL + kb + r) * QKVS + hoff + (c << 3);
            cp16(sb + FK_H * 2 + d, QKVh + src + 512);
            cp16(sb + FK_L * 2 + d, QKVl + src + 512);
            cp16(sb + FV_H * 2 + d, QKVh + src + 1024);
        }
        cp_commit();
    };

    load_kv(0, 0);

#pragma unroll
    for (int p = 0; p < 4; p++) {
        int f = p * 256 + tid;
        int r = f >> 3, c = f & 7;
        uint32_t d = (uint32_t)(r * 64 + ((c ^ (r & 7)) << 3));
        size_t src = (qrow0 + r) * QKVS + hoff + (c << 3);
        *(uint4*)(sm + FQ_H + d) = *(const uint4*)(QKVh + src);
        *(uint4*)(sm + FQ_L + d) = *(const uint4*)(QKVl + src);
    }
    __syncthreads();

    uint32_t qh[4][4], ql[4][4];
#pragma unroll
    for (int ks = 0; ks < 4; ks++) {
        int row = wid * 16 + (lane & 15);
        int kc = ks * 2 + (lane >> 4);
        uint32_t off = (uint32_t)(row * 64 + ((kc ^ (row & 7)) << 3)) * 2;
        ldsm4(qh[ks], smb + FQ_H * 2 + off);
        ldsm4(ql[ks], smb + FQ_L * 2 + off);
    }

    float o[8][4];
#pragma unroll
    for (int i = 0; i < 8; i++)
#pragma unroll
        for (int j = 0; j < 4; j++) o[i][j] = 0.0f;
    float m0 = -3.0e38f, m1 = -3.0e38f, l0 = 0.0f, l1 = 0.0f;

    int nkt = (len + FBC - 1) / FBC;
    for (int kt = 0; kt < nkt; kt++) {
        if (kt + 1 < nkt) { load_kv(kt + 1, (kt + 1) & 1); cp_wait<1>(); }
        else              { cp_wait<0>(); }
        __syncthreads();
        uint32_t sb = smb + (uint32_t)(FKV0 + (kt & 1) * FKV_STRIDE) * 2;

        float s[8][4];
#pragma unroll
        for (int i = 0; i < 8; i++)
#pragma unroll
            for (int j = 0; j < 4; j++) s[i][j] = 0.0f;

#pragma unroll
        for (int ks = 0; ks < 4; ks++) {
#pragma unroll
            for (int kg = 0; kg < 4; kg++) {
                int key = kg * 16 + (lane & 15);
                int kc = ks * 2 + (lane >> 4);
                uint32_t off = (uint32_t)(key * 64 + ((kc ^ (key & 7)) << 3)) * 2;
                uint32_t rh[4], rl[4];
                ldsm4(rh, sb + FK_H * 2 + off);
                ldsm4(rl, sb + FK_L * 2 + off);
                uint32_t bh0[2] = {rh[0], rh[2]}, bh1[2] = {rh[1], rh[3]};
                uint32_t bl0[2] = {rl[0], rl[2]}, bl1[2] = {rl[1], rl[3]};
                mma16816(s[kg * 2],     qh[ks], bh0);
                mma16816(s[kg * 2 + 1], qh[ks], bh1);
                mma16816(s[kg * 2],     qh[ks], bl0);
                mma16816(s[kg * 2 + 1], qh[ks], bl1);
                mma16816(s[kg * 2],     ql[ks], bh0);
                mma16816(s[kg * 2 + 1], ql[ks], bh1);
            }
        }

        int colbase = kt * FBC + (lane & 3) * 2;
        float mx0 = -3.0e38f, mx1 = -3.0e38f;
#pragma unroll
        for (int nf = 0; nf < 8; nf++) {
            int c = colbase + nf * 8;
            float b0 = (c     >= len) ? -1e9f : 0.0f;
            float b1 = (c + 1 >= len) ? -1e9f : 0.0f;
            s[nf][0] = s[nf][0] * 0.125f + b0;
            s[nf][1] = s[nf][1] * 0.125f + b1;
            s[nf][2] = s[nf][2] * 0.125f + b0;
            s[nf][3] = s[nf][3] * 0.125f + b1;
            mx0 = fmaxf(mx0, fmaxf(s[nf][0], s[nf][1]));
            mx1 = fmaxf(mx1, fmaxf(s[nf][2], s[nf][3]));
        }
        mx0 = fmaxf(mx0, __shfl_xor_sync(0xffffffffu, mx0, 1));
        mx0 = fmaxf(mx0, __shfl_xor_sync(0xffffffffu, mx0, 2));
        mx1 = fmaxf(mx1, __shfl_xor_sync(0xffffffffu, mx1, 1));
        mx1 = fmaxf(mx1, __shfl_xor_sync(0xffffffffu, mx1, 2));
        float mn0 = fmaxf(m0, mx0), mn1 = fmaxf(m1, mx1);
        float a0 = __expf(m0 - mn0), a1 = __expf(m1 - mn1);
        float ls0 = 0.0f, ls1 = 0.0f;
#pragma unroll
        for (int nf = 0; nf < 8; nf++) {
            s[nf][0] = __expf(s[nf][0] - mn0);
            s[nf][1] = __expf(s[nf][1] - mn0);
            s[nf][2] = __expf(s[nf][2] - mn1);
            s[nf][3] = __expf(s[nf][3] - mn1);
            ls0 += s[nf][0] + s[nf][1];
            ls1 += s[nf][2] + s[nf][3];
        }
        ls0 += __shfl_xor_sync(0xffffffffu, ls0, 1);
        ls0 += __shfl_xor_sync(0xffffffffu, ls0, 2);
        ls1 += __shfl_xor_sync(0xffffffffu, ls1, 1);
        ls1 += __shfl_xor_sync(0xffffffffu, ls1, 2);
        l0 = l0 * a0 + ls0;
        l1 = l1 * a1 + ls1;
        m0 = mn0; m1 = mn1;
#pragma unroll
        for (int nf = 0; nf < 8; nf++) {
            o[nf][0] *= a0; o[nf][1] *= a0;
            o[nf][2] *= a1; o[nf][3] *= a1;
        }

        // P V : 2-term (Ph + Pl) x Vh
#pragma unroll
        for (int kg = 0; kg < 4; kg++) {
            uint32_t ph[4], pl[4];
            split2(s[2 * kg][0], s[2 * kg][1], ph[0], pl[0]);
            split2(s[2 * kg][2], s[2 * kg][3], ph[1], pl[1]);
            split2(s[2 * kg + 1][0], s[2 * kg + 1][1], ph[2], pl[2]);
            split2(s[2 * kg + 1][2], s[2 * kg + 1][3], ph[3], pl[3]);
#pragma unroll
            for (int np = 0; np < 4; np++) {
                int krow = kg * 16 + (lane & 15);
                int nc = np * 2 + (lane >> 4);
                uint32_t off = (uint32_t)(krow * 64 + ((nc ^ (krow & 7)) << 3)) * 2;
                uint32_t rh[4];
                ldsm4t(rh, sb + FV_H * 2 + off);
                uint32_t vh0[2] = {rh[0], rh[1]}, vh1[2] = {rh[2], rh[3]};
                mma16816(o[np * 2],     ph, vh0);
                mma16816(o[np * 2 + 1], ph, vh1);
                mma16816(o[np * 2],     pl, vh0);
                mma16816(o[np * 2 + 1], pl, vh1);
            }
        }
        __syncthreads();
    }

    float li0 = 1.0f / l0, li1 = 1.0f / l1;
    int r0 = wid * 16 + (lane >> 2);
    size_t row0 = (qrow0 + r0) * DMODEL + hoff + (lane & 3) * 2;
    size_t row1 = (qrow0 + r0 + 8) * DMODEL + hoff + (lane & 3) * 2;
#pragma unroll
    for (int nf = 0; nf < 8; nf++) {
        uint32_t hi, lo;
        split2(o[nf][0] * li0, o[nf][1] * li0, hi, lo);
        *(uint32_t*)(Oh + row0 + nf * 8) = hi;
        *(uint32_t*)(Ol + row0 + nf * 8) = lo;
        split2(o[nf][2] * li1, o[nf][3] * li1, hi, lo);
        *(uint32_t*)(Oh + row1 + nf * 8) = hi;
        *(uint32_t*)(Ol + row1 + nf * 8) = lo;
    }
}

// ---------------- orchestration -------------------------------------------
extern "C" void kernel_launch(void* const* d_in, const int* in_sizes, int n_in,
                              void* d_out, int out_size) {
    (void)in_sizes; (void)n_in; (void)out_size;
    const float* x_in    = (const float*)d_in[0];
    const int*   lengths = (const int*)d_in[1];
    const float* Wq = (const float*)d_in[2];
    const float* Wk = (const float*)d_in[3];
    const float* Wv = (const float*)d_in[4];
    const float* Wo = (const float*)d_in[5];
    const float* ln1g = (const float*)d_in[6];
    const float* ln1b = (const float*)d_in[7];
    const float* ln2g = (const float*)d_in[8];
    const float* ln2b = (const float*)d_in[9];
    const float* w1 = (const float*)d_in[10];
    const float* b1 = (const float*)d_in[11];
    const float* w2 = (const float*)d_in[12];
    const float* b2 = (const float*)d_in[13];

    float* px;
    f16 *phh, *phl, *pqkvh, *pqkvl, *pfh, *pfl, *pwh, *pwl;
    cudaGetSymbolAddress((void**)&px, g_x);
    cudaGetSymbolAddress((void**)&phh, g_hh);
    cudaGetSymbolAddress((void**)&phl, g_hl);
    cudaGetSymbolAddress((void**)&pqkvh, g_qkvh);
    cudaGetSymbolAddress((void**)&pqkvl, g_qkvl);
    cudaGetSymbolAddress((void**)&pfh, g_fh);
    cudaGetSymbolAddress((void**)&pfl, g_fl);
    cudaGetSymbolAddress((void**)&pwh, g_wh);
    cudaGetSymbolAddress((void**)&pwl, g_wl);

    cudaFuncSetAttribute(k_fattn, cudaFuncAttributeMaxDynamicSharedMemorySize, FSMEM);
    cudaFuncSetAttribute(k_mm<3, false, false, false, true>,
                         cudaFuncAttributeMaxDynamicSharedMemorySize, GSMEM);
    cudaFuncSetAttribute(k_mm<3, false, false, true, false>,
                         cudaFuncAttributeMaxDynamicSharedMemorySize, GSMEM);
    cudaFuncSetAttribute(k_mm<2, true, true, false, true>,
                         cudaFuncAttributeMaxDynamicSharedMemorySize, GSMEM);
    cudaFuncSetAttribute(k_mm<2, true, false, true, false>,
                         cudaFuncAttributeMaxDynamicSharedMemorySize, GSMEM);

    k_wsplit<<<(WTOT / 4 + 255) / 256, 256>>>(Wq, Wk, Wv, Wo, w1, w2, pwh, pwl);
    k_pos<<<(BL * DMODEL) / 256, 256>>>(x_in, px);

    dim3 gQKV(QKVS / GBN, BL / GBM);   // (12, 64)
    dim3 gD(DMODEL / GBN, BL / GBM);   // (4, 64)
    dim3 gF(DFF / GBN, BL / GBM);      // (16, 64)
    dim3 gA(SEQL / FBR, NHEAD, BATCH);

    for (int layer = 0; layer < NLAYER; layer++) {
        const f16* qkvh = pwh + OFF_QKV + (size_t)layer * DMODEL * QKVS;
        const f16* qkvl = pwl + OFF_QKV + (size_t)layer * DMODEL * QKVS;
        const f16* woh  = pwh + OFF_WO + (size_t)layer * DMODEL * DMODEL;
        const f16* wol  = pwl + OFF_WO + (size_t)layer * DMODEL * DMODEL;
        const f16* w1h  = pwh + OFF_W1 + (size_t)layer * DMODEL * DFF;
        const f16* w2h  = pwh + OFF_W2 + (size_t)layer * DFF * DMODEL;

        k_ln<<<BL, 128>>>(px, ln1g + (size_t)layer * DMODEL, ln1b + (size_t)layer * DMODEL,
                          phh, phl);
        k_mm<3, false, false, false, true><<<gQKV, 256, GSMEM>>>(
            phh, phl, qkvh, qkvl, nullptr, nullptr, nullptr, pqkvh, pqkvl,
            BL, QKVS, DMODEL);
        k_fattn<<<gA, 256, FSMEM>>>(pqkvh, pqkvl, lengths, phh, phl);
        k_mm<3, false, false, true, false><<<gD, 256, GSMEM>>>(
            phh, phl, woh, wol, nullptr, px, px, nullptr, nullptr, BL, DMODEL, DMODEL);

        k_ln<<<BL, 128>>>(px, ln2g + (size_t)layer * DMODEL, ln2b + (size_t)layer * DMODEL,
                          phh, phl);
        k_mm<2, true, true, false, true><<<gF, 256, GSMEM>>>(
            phh, phl, w1h, nullptr, b1 + (size_t)layer * DFF, nullptr,
            nullptr, pfh, pfl, BL, DFF, DMODEL);
        float* dst = (layer == NLAYER - 1) ? (float*)d_out : px;
        k_mm<2, true, false, true, false><<<gD, 256, GSMEM>>>(
            pfh, pfl, w2h, nullptr, b2 + (size_t)layer * DMODEL, px,
            dst, nullptr, nullptr, BL, DMODEL, DFF);
    }
}

// round 10
// speedup vs baseline: 1.2438x; 1.0822x over previous
#include <cuda_runtime.h>
#include <cuda_fp16.h>
#include <math.h>
#include <stdint.h>

#define BATCH 8
#define SEQL 1024
#define DMODEL 512
#define NHEAD 8
#define DHEAD 64
#define DFF 2048
#define NLAYER 6
#define BL (BATCH * SEQL)   // 8192
#define QKVS 1536           // fused QKV row stride

typedef __half f16;

// ---------------- scratch (device globals: no allocs allowed) -------------
__device__ __align__(128) float g_x[BL * DMODEL];
__device__ __align__(128) f16   g_hh[BL * DMODEL];
__device__ __align__(128) f16   g_hl[BL * DMODEL];
__device__ __align__(128) f16   g_qkvh[BL * QKVS];
__device__ __align__(128) f16   g_qkvl[BL * QKVS];
__device__ __align__(128) f16   g_fh[BL * DFF];
__device__ __align__(128) f16   g_fl[BL * DFF];

// weight regions (all [K][N] row-major, fp16 HI only — 2-term everywhere)
#define SZ_QKV (NLAYER * DMODEL * QKVS)
#define SZ_WO  (NLAYER * DMODEL * DMODEL)
#define SZ_W1  (NLAYER * DMODEL * DFF)
#define SZ_W2  (NLAYER * DFF * DMODEL)
#define OFF_QKV 0
#define OFF_WO  (OFF_QKV + SZ_QKV)
#define OFF_W1  (OFF_WO + SZ_WO)
#define OFF_W2  (OFF_W1 + SZ_W1)
#define WTOT    (OFF_W2 + SZ_W2)
__device__ __align__(128) f16   g_wh[WTOT];

// ---------------- helpers --------------------------------------------------
__device__ __forceinline__ void cp16(uint32_t s, const void* g) {
    asm volatile("cp.async.cg.shared.global [%0], [%1], 16;\n" :: "r"(s), "l"(g));
}
__device__ __forceinline__ void cp_commit() {
    asm volatile("cp.async.commit_group;\n" ::: "memory");
}
template <int N_>
__device__ __forceinline__ void cp_wait() {
    asm volatile("cp.async.wait_group %0;\n" :: "n"(N_) : "memory");
}
__device__ __forceinline__ void ldsm4(uint32_t* r, uint32_t addr) {
    asm volatile("ldmatrix.sync.aligned.m8n8.x4.shared.b16 {%0,%1,%2,%3}, [%4];"
                 : "=r"(r[0]), "=r"(r[1]), "=r"(r[2]), "=r"(r[3]) : "r"(addr));
}
__device__ __forceinline__ void ldsm4t(uint32_t* r, uint32_t addr) {
    asm volatile("ldmatrix.sync.aligned.m8n8.x4.trans.shared.b16 {%0,%1,%2,%3}, [%4];"
                 : "=r"(r[0]), "=r"(r[1]), "=r"(r[2]), "=r"(r[3]) : "r"(addr));
}
__device__ __forceinline__ void mma16816(float* c, const uint32_t* a, const uint32_t* b) {
    asm volatile(
        "mma.sync.aligned.m16n8k16.row.col.f32.f16.f16.f32 "
        "{%0,%1,%2,%3}, {%4,%5,%6,%7}, {%8,%9}, {%0,%1,%2,%3};"
        : "+f"(c[0]), "+f"(c[1]), "+f"(c[2]), "+f"(c[3])
        : "r"(a[0]), "r"(a[1]), "r"(a[2]), "r"(a[3]), "r"(b[0]), "r"(b[1]));
}
__device__ __forceinline__ uint32_t packh(f16 a, f16 b) {
    return ((uint32_t)__half_as_ushort(b) << 16) | __half_as_ushort(a);
}
__device__ __forceinline__ void split2(float a, float b, uint32_t& hi, uint32_t& lo) {
    f16 ha = __float2half_rn(a), hb = __float2half_rn(b);
    f16 la = __float2half_rn(a - __half2float(ha));
    f16 lb = __float2half_rn(b - __half2float(hb));
    hi = packh(ha, hb);
    lo = packh(la, lb);
}

// ---------------- positional embedding + add ------------------------------
__global__ void k_pos(const float* __restrict__ xin, float* __restrict__ xout) {
    int idx = blockIdx.x * 256 + threadIdx.x;
    if (idx >= BL * DMODEL) return;
    int d = idx % DMODEL;
    int l = (idx / DMODEL) % SEQL;
    int half = DMODEL / 2;
    int i = (d < half) ? d : d - half;
    float inv = powf(10000.0f, -2.0f * (float)i / (float)DMODEL);
    float ang = (float)l * inv;
    float pe = (d < half) ? sinf(ang) : cosf(ang);
    xout[idx] = xin[idx] + pe;
}

// ---------------- combined weight convert (hi only) ------------------------
__global__ void __launch_bounds__(256) k_wsplit(
    const float* __restrict__ Wq, const float* __restrict__ Wk,
    const float* __restrict__ Wv, const float* __restrict__ Wo,
    const float* __restrict__ w1, const float* __restrict__ w2,
    f16* __restrict__ dh) {
    uint32_t idx = (blockIdx.x * 256 + threadIdx.x) * 4;
    if (idx >= WTOT) return;
    const float* src;
    if (idx < OFF_WO) {
        uint32_t rel = idx;
        uint32_t l = rel / (DMODEL * QKVS);
        uint32_t r2 = rel - l * (DMODEL * QKVS);
        uint32_t k = r2 / QKVS;
        uint32_t j = r2 - k * QKVS;
        uint32_t sel = j >> 9;
        uint32_t jj = j & 511;
        const float* W = (sel == 0) ? Wq : (sel == 1) ? Wk : Wv;
        src = W + (size_t)l * DMODEL * DMODEL + (size_t)k * DMODEL + jj;
    } else if (idx < OFF_W1) {
        src = Wo + (idx - OFF_WO);
    } else if (idx < OFF_W2) {
        src = w1 + (idx - OFF_W1);
    } else {
        src = w2 + (idx - OFF_W2);
    }
    float4 v = *(const float4*)src;
    uint32_t h0 = packh(__float2half_rn(v.x), __float2half_rn(v.y));
    uint32_t h1 = packh(__float2half_rn(v.z), __float2half_rn(v.w));
    uint32_t* hp = (uint32_t*)(dh + idx);
    hp[0] = h0; hp[1] = h1;
}

// ---------------- layernorm -> split fp16 output --------------------------
__global__ void __launch_bounds__(128) k_ln(const float* __restrict__ x,
                                            const float* __restrict__ g,
                                            const float* __restrict__ b,
                                            f16* __restrict__ ohi,
                                            f16* __restrict__ olo) {
    int row = blockIdx.x;
    int tid = threadIdx.x;
    const float4* xr = (const float4*)(x + (size_t)row * DMODEL);
    float4 v = xr[tid];
    __shared__ float sh[4];

    float s = v.x + v.y + v.z + v.w;
    for (int o = 16; o; o >>= 1) s += __shfl_xor_sync(0xffffffffu, s, o);
    if ((tid & 31) == 0) sh[tid >> 5] = s;
    __syncthreads();
    float mean = (sh[0] + sh[1] + sh[2] + sh[3]) * (1.0f / DMODEL);
    __syncthreads();

    float dx0 = v.x - mean, dx1 = v.y - mean, dx2 = v.z - mean, dx3 = v.w - mean;
    float s2 = dx0 * dx0 + dx1 * dx1 + dx2 * dx2 + dx3 * dx3;
    for (int o = 16; o; o >>= 1) s2 += __shfl_xor_sync(0xffffffffu, s2, o);
    if ((tid & 31) == 0) sh[tid >> 5] = s2;
    __syncthreads();
    float var = (sh[0] + sh[1] + sh[2] + sh[3]) * (1.0f / DMODEL);
    float r = rsqrtf(var + 1e-3f);

    float4 gg = ((const float4*)g)[tid];
    float4 bb = ((const float4*)b)[tid];
    float o0 = dx0 * r * gg.x + bb.x;
    float o1 = dx1 * r * gg.y + bb.y;
    float o2 = dx2 * r * gg.z + bb.z;
    float o3 = dx3 * r * gg.w + bb.w;

    uint32_t h0, l0, h1, l1;
    split2(o0, o1, h0, l0);
    split2(o2, o3, h1, l1);
    size_t off = (size_t)row * DMODEL + tid * 4;
    uint32_t* hp = (uint32_t*)(ohi + off);
    uint32_t* lp = (uint32_t*)(olo + off);
    hp[0] = h0; hp[1] = h1;
    lp[0] = l0; lp[1] = l1;
}

// ---------------- 2-term fp16 HMMA GEMM: 128x128, GBK=32, 3-stage ----------
// C = (Ah + Al) * B   (A split fp16, B single fp16)
#define GBM 128
#define GBN 128
#define GBK 32
#define NSTAGE 3
#define STAGE_ELEMS (2 * GBM * GBK + GBK * GBN)       // 12288 f16 = 24 KB
#define STAGE_BYTES (STAGE_ELEMS * 2)
#define SOFF_AH 0
#define SOFF_AL (GBM * GBK)
#define SOFF_B  (2 * GBM * GBK)
#define GSMEM (NSTAGE * STAGE_BYTES)                  // 73728 bytes

template <bool BIAS, bool RELU, bool RES, bool SPLIT>
__global__ void __launch_bounds__(256, 2) k_mm(
    const f16* __restrict__ Ah, const f16* __restrict__ Al,
    const f16* __restrict__ B,
    const float* __restrict__ bias, const float* __restrict__ res,
    float* __restrict__ Cf, f16* __restrict__ Ch, f16* __restrict__ Cl,
    int M, int N, int K) {
    extern __shared__ f16 sm[];
    int tid = threadIdx.x;
    int lane = tid & 31, wid = tid >> 5;
    int wm = wid >> 2;            // 0..1  (64 rows)
    int wn = wid & 3;             // 0..3  (32 cols)
    int m0 = blockIdx.y * GBM, n0 = blockIdx.x * GBN;
    uint32_t smbase = (uint32_t)__cvta_generic_to_shared(sm);

    float acc[4][4][4];
#pragma unroll
    for (int i = 0; i < 4; i++)
#pragma unroll
        for (int j = 0; j < 4; j++)
#pragma unroll
            for (int q = 0; q < 4; q++) acc[i][j][q] = 0.0f;

    int nk = K / GBK;

    auto load_stage = [&](int kt) {
        int buf = kt % NSTAGE;
        uint32_t sb = smbase + (uint32_t)buf * STAGE_BYTES;
#pragma unroll
        for (int p = 0; p < 2; p++) {       // A: 128 rows x 4 16B-chunks
            int f = p * 256 + tid;
            int r = f >> 2, c = f & 3;
            uint32_t dst = (uint32_t)(r * GBK + ((c ^ ((r >> 1) & 3)) << 3));
            size_t src = (size_t)(m0 + r) * K + kt * GBK + (c << 3);
            cp16(sb + (SOFF_AH + dst) * 2, Ah + src);
            cp16(sb + (SOFF_AL + dst) * 2, Al + src);
        }
#pragma unroll
        for (int p = 0; p < 2; p++) {       // B: 32 k-rows x 16 16B-chunks
            int f = p * 256 + tid;
            int k = f >> 4, c = f & 15;
            int cs = (c & 8) | ((c ^ (k & 7)) & 7);
            uint32_t dst = (uint32_t)(k * GBN + (cs << 3));
            size_t src = (size_t)(kt * GBK + k) * N + n0 + (c << 3);
            cp16(sb + (SOFF_B + dst) * 2, B + src);
        }
        cp_commit();
    };

    load_stage(0);
    if (nk > 1) load_stage(1);

    for (int kt = 0; kt < nk; kt++) {
        if (kt == nk - 1) cp_wait<0>();
        else              cp_wait<1>();
        __syncthreads();        // rendezvous: compute(kt-1) done, stage kt visible
        if (kt + 2 < nk) load_stage(kt + 2);
        uint32_t sb = smbase + (uint32_t)(kt % NSTAGE) * STAGE_BYTES;

#pragma unroll
        for (int ks = 0; ks < GBK / 16; ks++) {
            uint32_t ah[4][4], al[4][4];
#pragma unroll
            for (int mt = 0; mt < 4; mt++) {
                int row = wm * 64 + mt * 16 + (lane & 15);
                int kc = ks * 2 + (lane >> 4);
                uint32_t off = (uint32_t)(row * GBK + ((kc ^ ((row >> 1) & 3)) << 3)) * 2;
                ldsm4(ah[mt], sb + SOFF_AH * 2 + off);
                ldsm4(al[mt], sb + SOFF_AL * 2 + off);
            }
#pragma unroll
            for (int np = 0; np < 2; np++) {
                uint32_t bb[2][2];
                {
                    int krow = ks * 16 + (lane & 15);
                    int nc = wn * 4 + np * 2 + (lane >> 4);
                    int ncs = (nc & 8) | ((nc ^ (krow & 7)) & 7);
                    uint32_t off = (uint32_t)(krow * GBN + (ncs << 3)) * 2;
                    uint32_t r[4];
                    ldsm4t(r, sb + SOFF_B * 2 + off);
                    bb[0][0] = r[0]; bb[0][1] = r[1];
                    bb[1][0] = r[2]; bb[1][1] = r[3];
                }
                // pass 1: Ah * B
#pragma unroll
                for (int mt = 0; mt < 4; mt++)
#pragma unroll
                    for (int j = 0; j < 2; j++)
                        mma16816(acc[mt][np * 2 + j], ah[mt], bb[j]);
                // pass 2: Al * B
#pragma unroll
                for (int mt = 0; mt < 4; mt++)
#pragma unroll
                    for (int j = 0; j < 2; j++)
                        mma16816(acc[mt][np * 2 + j], al[mt], bb[j]);
            }
        }
    }

#pragma unroll
    for (int mt = 0; mt < 4; mt++)
#pragma unroll
        for (int nt = 0; nt < 4; nt++) {
            int rbase = m0 + wm * 64 + mt * 16 + (lane >> 2);
            int cbase = n0 + wn * 32 + nt * 8 + (lane & 3) * 2;
#pragma unroll
            for (int half = 0; half < 2; half++) {
                int r = rbase + half * 8;
                float c0 = acc[mt][nt][half * 2 + 0];
                float c1 = acc[mt][nt][half * 2 + 1];
                size_t off = (size_t)r * N + cbase;
                if (BIAS) { c0 += bias[cbase]; c1 += bias[cbase + 1]; }
                if (RES)  { float2 rv = *(const float2*)(res + off); c0 += rv.x; c1 += rv.y; }
                if (RELU) { c0 = fmaxf(c0, 0.f); c1 = fmaxf(c1, 0.f); }
                if (SPLIT) {
                    uint32_t hi, lo;
                    split2(c0, c1, hi, lo);
                    *(uint32_t*)(Ch + off) = hi;
                    *(uint32_t*)(Cl + off) = lo;
                } else {
                    *(float2*)(Cf + off) = make_float2(c0, c1);
                }
            }
        }
}

// ---------------- tensor-core flash attention (fused QKV buffer) -----------
// S = Q K^T 3-term fp16 (protect logits); P V 2-term (V hi only).
#define FBR 128
#define FBC 64
#define FQ_H 0
#define FQ_L (FBR * 64)
#define FKV0 (2 * FBR * 64)
#define FKV_STRIDE (3 * FBC * 64)
#define FK_H 0
#define FK_L (FBC * 64)
#define FV_H (2 * FBC * 64)
#define FSMEM ((2 * FBR * 64 + 2 * FKV_STRIDE) * 2)   // 81920 bytes

__global__ void __launch_bounds__(256, 1) k_fattn(
    const f16* __restrict__ QKVh, const f16* __restrict__ QKVl,
    const int* __restrict__ lengths,
    f16* __restrict__ Oh, f16* __restrict__ Ol) {
    extern __shared__ f16 sm[];
    uint32_t smb = (uint32_t)__cvta_generic_to_shared(sm);
    int b = blockIdx.z, h = blockIdx.y, qt = blockIdx.x;
    int len = lengths[b];
    int tid = threadIdx.x, lane = tid & 31, wid = tid >> 5;
    size_t qrow0 = (size_t)(b * SEQL + qt * FBR);
    size_t hoff = (size_t)h * DHEAD;

    auto load_kv = [&](int kt, int stg) {
        uint32_t sb = smb + (uint32_t)(FKV0 + stg * FKV_STRIDE) * 2;
        int kb = kt * FBC;
#pragma unroll
        for (int p = 0; p < 2; p++) {
            int f = p * 256 + tid;
            int r = f >> 3, c = f & 7;
            uint32_t d = (uint32_t)((r * 64 + ((c ^ (r & 7)) << 3)) * 2);
            size_t src = (size_t)(b * SEQL + kb + r) * QKVS + hoff + (c << 3);
            cp16(sb + FK_H * 2 + d, QKVh + src + 512);
            cp16(sb + FK_L * 2 + d, QKVl + src + 512);
            cp16(sb + FV_H * 2 + d, QKVh + src + 1024);
        }
        cp_commit();
    };

    load_kv(0, 0);

#pragma unroll
    for (int p = 0; p < 4; p++) {
        int f = p * 256 + tid;
        int r = f >> 3, c = f & 7;
        uint32_t d = (uint32_t)(r * 64 + ((c ^ (r & 7)) << 3));
        size_t src = (qrow0 + r) * QKVS + hoff + (c << 3);
        *(uint4*)(sm + FQ_H + d) = *(const uint4*)(QKVh + src);
        *(uint4*)(sm + FQ_L + d) = *(const uint4*)(QKVl + src);
    }
    __syncthreads();

    uint32_t qh[4][4], ql[4][4];
#pragma unroll
    for (int ks = 0; ks < 4; ks++) {
        int row = wid * 16 + (lane & 15);
        int kc = ks * 2 + (lane >> 4);
        uint32_t off = (uint32_t)(row * 64 + ((kc ^ (row & 7)) << 3)) * 2;
        ldsm4(qh[ks], smb + FQ_H * 2 + off);
        ldsm4(ql[ks], smb + FQ_L * 2 + off);
    }

    float o[8][4];
#pragma unroll
    for (int i = 0; i < 8; i++)
#pragma unroll
        for (int j = 0; j < 4; j++) o[i][j] = 0.0f;
    float m0 = -3.0e38f, m1 = -3.0e38f, l0 = 0.0f, l1 = 0.0f;

    int nkt = (len + FBC - 1) / FBC;
    for (int kt = 0; kt < nkt; kt++) {
        if (kt + 1 < nkt) { load_kv(kt + 1, (kt + 1) & 1); cp_wait<1>(); }
        else              { cp_wait<0>(); }
        __syncthreads();
        uint32_t sb = smb + (uint32_t)(FKV0 + (kt & 1) * FKV_STRIDE) * 2;

        float s[8][4];
#pragma unroll
        for (int i = 0; i < 8; i++)
#pragma unroll
            for (int j = 0; j < 4; j++) s[i][j] = 0.0f;

#pragma unroll
        for (int ks = 0; ks < 4; ks++) {
#pragma unroll
            for (int kg = 0; kg < 4; kg++) {
                int key = kg * 16 + (lane & 15);
                int kc = ks * 2 + (lane >> 4);
                uint32_t off = (uint32_t)(key * 64 + ((kc ^ (key & 7)) << 3)) * 2;
                uint32_t rh[4], rl[4];
                ldsm4(rh, sb + FK_H * 2 + off);
                ldsm4(rl, sb + FK_L * 2 + off);
                uint32_t bh0[2] = {rh[0], rh[2]}, bh1[2] = {rh[1], rh[3]};
                uint32_t bl0[2] = {rl[0], rl[2]}, bl1[2] = {rl[1], rl[3]};
                mma16816(s[kg * 2],     qh[ks], bh0);
                mma16816(s[kg * 2 + 1], qh[ks], bh1);
                mma16816(s[kg * 2],     qh[ks], bl0);
                mma16816(s[kg * 2 + 1], qh[ks], bl1);
                mma16816(s[kg * 2],     ql[ks], bh0);
                mma16816(s[kg * 2 + 1], ql[ks], bh1);
            }
        }

        int colbase = kt * FBC + (lane & 3) * 2;
        float mx0 = -3.0e38f, mx1 = -3.0e38f;
#pragma unroll
        for (int nf = 0; nf < 8; nf++) {
            int c = colbase + nf * 8;
            float b0 = (c     >= len) ? -1e9f : 0.0f;
            float b1 = (c + 1 >= len) ? -1e9f : 0.0f;
            s[nf][0] = s[nf][0] * 0.125f + b0;
            s[nf][1] = s[nf][1] * 0.125f + b1;
            s[nf][2] = s[nf][2] * 0.125f + b0;
            s[nf][3] = s[nf][3] * 0.125f + b1;
            mx0 = fmaxf(mx0, fmaxf(s[nf][0], s[nf][1]));
            mx1 = fmaxf(mx1, fmaxf(s[nf][2], s[nf][3]));
        }
        mx0 = fmaxf(mx0, __shfl_xor_sync(0xffffffffu, mx0, 1));
        mx0 = fmaxf(mx0, __shfl_xor_sync(0xffffffffu, mx0, 2));
        mx1 = fmaxf(mx1, __shfl_xor_sync(0xffffffffu, mx1, 1));
        mx1 = fmaxf(mx1, __shfl_xor_sync(0xffffffffu, mx1, 2));
        float mn0 = fmaxf(m0, mx0), mn1 = fmaxf(m1, mx1);
        float a0 = __expf(m0 - mn0), a1 = __expf(m1 - mn1);
        float ls0 = 0.0f, ls1 = 0.0f;
#pragma unroll
        for (int nf = 0; nf < 8; nf++) {
            s[nf][0] = __expf(s[nf][0] - mn0);
            s[nf][1] = __expf(s[nf][1] - mn0);
            s[nf][2] = __expf(s[nf][2] - mn1);
            s[nf][3] = __expf(s[nf][3] - mn1);
            ls0 += s[nf][0] + s[nf][1];
            ls1 += s[nf][2] + s[nf][3];
        }
        ls0 += __shfl_xor_sync(0xffffffffu, ls0, 1);
        ls0 += __shfl_xor_sync(0xffffffffu, ls0, 2);
        ls1 += __shfl_xor_sync(0xffffffffu, ls1, 1);
        ls1 += __shfl_xor_sync(0xffffffffu, ls1, 2);
        l0 = l0 * a0 + ls0;
        l1 = l1 * a1 + ls1;
        m0 = mn0; m1 = mn1;
#pragma unroll
        for (int nf = 0; nf < 8; nf++) {
            o[nf][0] *= a0; o[nf][1] *= a0;
            o[nf][2] *= a1; o[nf][3] *= a1;
        }

        // P V : 2-term (Ph + Pl) x Vh
#pragma unroll
        for (int kg = 0; kg < 4; kg++) {
            uint32_t ph[4], pl[4];
            split2(s[2 * kg][0], s[2 * kg][1], ph[0], pl[0]);
            split2(s[2 * kg][2], s[2 * kg][3], ph[1], pl[1]);
            split2(s[2 * kg + 1][0], s[2 * kg + 1][1], ph[2], pl[2]);
            split2(s[2 * kg + 1][2], s[2 * kg + 1][3], ph[3], pl[3]);
#pragma unroll
            for (int np = 0; np < 4; np++) {
                int krow = kg * 16 + (lane & 15);
                int nc = np * 2 + (lane >> 4);
                uint32_t off = (uint32_t)(krow * 64 + ((nc ^ (krow & 7)) << 3)) * 2;
                uint32_t rh[4];
                ldsm4t(rh, sb + FV_H * 2 + off);
                uint32_t vh0[2] = {rh[0], rh[1]}, vh1[2] = {rh[2], rh[3]};
                mma16816(o[np * 2],     ph, vh0);
                mma16816(o[np * 2 + 1], ph, vh1);
                mma16816(o[np * 2],     pl, vh0);
                mma16816(o[np * 2 + 1], pl, vh1);
            }
        }
        __syncthreads();
    }

    float li0 = 1.0f / l0, li1 = 1.0f / l1;
    int r0 = wid * 16 + (lane >> 2);
    size_t row0 = (qrow0 + r0) * DMODEL + hoff + (lane & 3) * 2;
    size_t row1 = (qrow0 + r0 + 8) * DMODEL + hoff + (lane & 3) * 2;
#pragma unroll
    for (int nf = 0; nf < 8; nf++) {
        uint32_t hi, lo;
        split2(o[nf][0] * li0, o[nf][1] * li0, hi, lo);
        *(uint32_t*)(Oh + row0 + nf * 8) = hi;
        *(uint32_t*)(Ol + row0 + nf * 8) = lo;
        split2(o[nf][2] * li1, o[nf][3] * li1, hi, lo);
        *(uint32_t*)(Oh + row1 + nf * 8) = hi;
        *(uint32_t*)(Ol + row1 + nf * 8) = lo;
    }
}

// ---------------- orchestration -------------------------------------------
extern "C" void kernel_launch(void* const* d_in, const int* in_sizes, int n_in,
                              void* d_out, int out_size) {
    (void)in_sizes; (void)n_in; (void)out_size;
    const float* x_in    = (const float*)d_in[0];
    const int*   lengths = (const int*)d_in[1];
    const float* Wq = (const float*)d_in[2];
    const float* Wk = (const float*)d_in[3];
    const float* Wv = (const float*)d_in[4];
    const float* Wo = (const float*)d_in[5];
    const float* ln1g = (const float*)d_in[6];
    const float* ln1b = (const float*)d_in[7];
    const float* ln2g = (const float*)d_in[8];
    const float* ln2b = (const float*)d_in[9];
    const float* w1 = (const float*)d_in[10];
    const float* b1 = (const float*)d_in[11];
    const float* w2 = (const float*)d_in[12];
    const float* b2 = (const float*)d_in[13];

    float* px;
    f16 *phh, *phl, *pqkvh, *pqkvl, *pfh, *pfl, *pwh;
    cudaGetSymbolAddress((void**)&px, g_x);
    cudaGetSymbolAddress((void**)&phh, g_hh);
    cudaGetSymbolAddress((void**)&phl, g_hl);
    cudaGetSymbolAddress((void**)&pqkvh, g_qkvh);
    cudaGetSymbolAddress((void**)&pqkvl, g_qkvl);
    cudaGetSymbolAddress((void**)&pfh, g_fh);
    cudaGetSymbolAddress((void**)&pfl, g_fl);
    cudaGetSymbolAddress((void**)&pwh, g_wh);

    cudaFuncSetAttribute(k_fattn, cudaFuncAttributeMaxDynamicSharedMemorySize, FSMEM);
    cudaFuncSetAttribute(k_mm<false, false, false, true>,
                         cudaFuncAttributeMaxDynamicSharedMemorySize, GSMEM);
    cudaFuncSetAttribute(k_mm<false, false, true, false>,
                         cudaFuncAttributeMaxDynamicSharedMemorySize, GSMEM);
    cudaFuncSetAttribute(k_mm<true, true, false, true>,
                         cudaFuncAttributeMaxDynamicSharedMemorySize, GSMEM);
    cudaFuncSetAttribute(k_mm<true, false, true, false>,
                         cudaFuncAttributeMaxDynamicSharedMemorySize, GSMEM);

    k_wsplit<<<(WTOT / 4 + 255) / 256, 256>>>(Wq, Wk, Wv, Wo, w1, w2, pwh);
    k_pos<<<(BL * DMODEL) / 256, 256>>>(x_in, px);

    dim3 gQKV(QKVS / GBN, BL / GBM);   // (12, 64)
    dim3 gD(DMODEL / GBN, BL / GBM);   // (4, 64)
    dim3 gF(DFF / GBN, BL / GBM);      // (16, 64)
    dim3 gA(SEQL / FBR, NHEAD, BATCH);

    for (int layer = 0; layer < NLAYER; layer++) {
        const f16* qkvw = pwh + OFF_QKV + (size_t)layer * DMODEL * QKVS;
        const f16* wow  = pwh + OFF_WO + (size_t)layer * DMODEL * DMODEL;
        const f16* w1w  = pwh + OFF_W1 + (size_t)layer * DMODEL * DFF;
        const f16* w2w  = pwh + OFF_W2 + (size_t)layer * DFF * DMODEL;

        k_ln<<<BL, 128>>>(px, ln1g + (size_t)layer * DMODEL, ln1b + (size_t)layer * DMODEL,
                          phh, phl);
        k_mm<false, false, false, true><<<gQKV, 256, GSMEM>>>(
            phh, phl, qkvw, nullptr, nullptr, nullptr, pqkvh, pqkvl,
            BL, QKVS, DMODEL);
        k_fattn<<<gA, 256, FSMEM>>>(pqkvh, pqkvl, lengths, phh, phl);
        k_mm<false, false, true, false><<<gD, 256, GSMEM>>>(
            phh, phl, wow, nullptr, px, px, nullptr, nullptr, BL, DMODEL, DMODEL);

        k_ln<<<BL, 128>>>(px, ln2g + (size_t)layer * DMODEL, ln2b + (size_t)layer * DMODEL,
                          phh, phl);
        k_mm<true, true, false, true><<<gF, 256, GSMEM>>>(
            phh, phl, w1w, b1 + (size_t)layer * DFF, nullptr,
            nullptr, pfh, pfl, BL, DFF, DMODEL);
        float* dst = (layer == NLAYER - 1) ? (float*)d_out : px;
        k_mm<true, false, true, false><<<gD, 256, GSMEM>>>(
            pfh, pfl, w2w, b2 + (size_t)layer * DMODEL, px,
            dst, nullptr, nullptr, BL, DMODEL, DFF);
    }
}

// round 11
// speedup vs baseline: 1.2835x; 1.0319x over previous
#include <cuda_runtime.h>
#include <cuda_fp16.h>
#include <math.h>
#include <stdint.h>

#define BATCH 8
#define SEQL 1024
#define DMODEL 512
#define NHEAD 8
#define DHEAD 64
#define DFF 2048
#define NLAYER 6
#define BL (BATCH * SEQL)   // 8192
#define QKVS 1536           // fused QKV row stride

typedef __half f16;

// ---------------- scratch (device globals: no allocs allowed) -------------
__device__ __align__(128) float g_x[BL * DMODEL];
__device__ __align__(128) f16   g_hh[BL * DMODEL];
__device__ __align__(128) f16   g_hl[BL * DMODEL];
__device__ __align__(128) f16   g_qkvh[BL * QKVS];
__device__ __align__(128) f16   g_qkvl[BL * QKVS];
__device__ __align__(128) f16   g_fh[BL * DFF];
__device__ __align__(128) f16   g_fl[BL * DFF];

// weight regions (all [K][N] row-major, fp16 HI only — 2-term everywhere)
#define SZ_QKV (NLAYER * DMODEL * QKVS)
#define SZ_WO  (NLAYER * DMODEL * DMODEL)
#define SZ_W1  (NLAYER * DMODEL * DFF)
#define SZ_W2  (NLAYER * DFF * DMODEL)
#define OFF_QKV 0
#define OFF_WO  (OFF_QKV + SZ_QKV)
#define OFF_W1  (OFF_WO + SZ_WO)
#define OFF_W2  (OFF_W1 + SZ_W1)
#define WTOT    (OFF_W2 + SZ_W2)
__device__ __align__(128) f16   g_wh[WTOT];

// ---------------- helpers --------------------------------------------------
__device__ __forceinline__ void cp16(uint32_t s, const void* g) {
    asm volatile("cp.async.cg.shared.global [%0], [%1], 16;\n" :: "r"(s), "l"(g));
}
__device__ __forceinline__ void cp_commit() {
    asm volatile("cp.async.commit_group;\n" ::: "memory");
}
template <int N_>
__device__ __forceinline__ void cp_wait() {
    asm volatile("cp.async.wait_group %0;\n" :: "n"(N_) : "memory");
}
__device__ __forceinline__ void ldsm4(uint32_t* r, uint32_t addr) {
    asm volatile("ldmatrix.sync.aligned.m8n8.x4.shared.b16 {%0,%1,%2,%3}, [%4];"
                 : "=r"(r[0]), "=r"(r[1]), "=r"(r[2]), "=r"(r[3]) : "r"(addr));
}
__device__ __forceinline__ void ldsm4t(uint32_t* r, uint32_t addr) {
    asm volatile("ldmatrix.sync.aligned.m8n8.x4.trans.shared.b16 {%0,%1,%2,%3}, [%4];"
                 : "=r"(r[0]), "=r"(r[1]), "=r"(r[2]), "=r"(r[3]) : "r"(addr));
}
__device__ __forceinline__ void mma16816(float* c, const uint32_t* a, const uint32_t* b) {
    asm volatile(
        "mma.sync.aligned.m16n8k16.row.col.f32.f16.f16.f32 "
        "{%0,%1,%2,%3}, {%4,%5,%6,%7}, {%8,%9}, {%0,%1,%2,%3};"
        : "+f"(c[0]), "+f"(c[1]), "+f"(c[2]), "+f"(c[3])
        : "r"(a[0]), "r"(a[1]), "r"(a[2]), "r"(a[3]), "r"(b[0]), "r"(b[1]));
}
__device__ __forceinline__ uint32_t packh(f16 a, f16 b) {
    return ((uint32_t)__half_as_ushort(b) << 16) | __half_as_ushort(a);
}
__device__ __forceinline__ void split2(float a, float b, uint32_t& hi, uint32_t& lo) {
    f16 ha = __float2half_rn(a), hb = __float2half_rn(b);
    f16 la = __float2half_rn(a - __half2float(ha));
    f16 lb = __float2half_rn(b - __half2float(hb));
    hi = packh(ha, hb);
    lo = packh(la, lb);
}

// ---------------- positional embedding + add ------------------------------
__global__ void k_pos(const float* __restrict__ xin, float* __restrict__ xout) {
    int idx = blockIdx.x * 256 + threadIdx.x;
    if (idx >= BL * DMODEL) return;
    int d = idx % DMODEL;
    int l = (idx / DMODEL) % SEQL;
    int half = DMODEL / 2;
    int i = (d < half) ? d : d - half;
    float inv = powf(10000.0f, -2.0f * (float)i / (float)DMODEL);
    float ang = (float)l * inv;
    float pe = (d < half) ? sinf(ang) : cosf(ang);
    xout[idx] = xin[idx] + pe;
}

// ---------------- combined weight convert (hi only) ------------------------
__global__ void __launch_bounds__(256) k_wsplit(
    const float* __restrict__ Wq, const float* __restrict__ Wk,
    const float* __restrict__ Wv, const float* __restrict__ Wo,
    const float* __restrict__ w1, const float* __restrict__ w2,
    f16* __restrict__ dh) {
    uint32_t idx = (blockIdx.x * 256 + threadIdx.x) * 4;
    if (idx >= WTOT) return;
    const float* src;
    if (idx < OFF_WO) {
        uint32_t rel = idx;
        uint32_t l = rel / (DMODEL * QKVS);
        uint32_t r2 = rel - l * (DMODEL * QKVS);
        uint32_t k = r2 / QKVS;
        uint32_t j = r2 - k * QKVS;
        uint32_t sel = j >> 9;
        uint32_t jj = j & 511;
        const float* W = (sel == 0) ? Wq : (sel == 1) ? Wk : Wv;
        src = W + (size_t)l * DMODEL * DMODEL + (size_t)k * DMODEL + jj;
    } else if (idx < OFF_W1) {
        src = Wo + (idx - OFF_WO);
    } else if (idx < OFF_W2) {
        src = w1 + (idx - OFF_W1);
    } else {
        src = w2 + (idx - OFF_W2);
    }
    float4 v = *(const float4*)src;
    uint32_t h0 = packh(__float2half_rn(v.x), __float2half_rn(v.y));
    uint32_t h1 = packh(__float2half_rn(v.z), __float2half_rn(v.w));
    uint32_t* hp = (uint32_t*)(dh + idx);
    hp[0] = h0; hp[1] = h1;
}

// ---------------- layernorm -> split fp16 output --------------------------
__global__ void __launch_bounds__(128) k_ln(const float* __restrict__ x,
                                            const float* __restrict__ g,
                                            const float* __restrict__ b,
                                            f16* __restrict__ ohi,
                                            f16* __restrict__ olo) {
    int row = blockIdx.x;
    int tid = threadIdx.x;
    const float4* xr = (const float4*)(x + (size_t)row * DMODEL);
    float4 v = xr[tid];
    __shared__ float sh[4];

    float s = v.x + v.y + v.z + v.w;
    for (int o = 16; o; o >>= 1) s += __shfl_xor_sync(0xffffffffu, s, o);
    if ((tid & 31) == 0) sh[tid >> 5] = s;
    __syncthreads();
    float mean = (sh[0] + sh[1] + sh[2] + sh[3]) * (1.0f / DMODEL);
    __syncthreads();

    float dx0 = v.x - mean, dx1 = v.y - mean, dx2 = v.z - mean, dx3 = v.w - mean;
    float s2 = dx0 * dx0 + dx1 * dx1 + dx2 * dx2 + dx3 * dx3;
    for (int o = 16; o; o >>= 1) s2 += __shfl_xor_sync(0xffffffffu, s2, o);
    if ((tid & 31) == 0) sh[tid >> 5] = s2;
    __syncthreads();
    float var = (sh[0] + sh[1] + sh[2] + sh[3]) * (1.0f / DMODEL);
    float r = rsqrtf(var + 1e-3f);

    float4 gg = ((const float4*)g)[tid];
    float4 bb = ((const float4*)b)[tid];
    float o0 = dx0 * r * gg.x + bb.x;
    float o1 = dx1 * r * gg.y + bb.y;
    float o2 = dx2 * r * gg.z + bb.z;
    float o3 = dx3 * r * gg.w + bb.w;

    uint32_t h0, l0, h1, l1;
    split2(o0, o1, h0, l0);
    split2(o2, o3, h1, l1);
    size_t off = (size_t)row * DMODEL + tid * 4;
    uint32_t* hp = (uint32_t*)(ohi + off);
    uint32_t* lp = (uint32_t*)(olo + off);
    hp[0] = h0; hp[1] = h1;
    lp[0] = l0; lp[1] = l1;
}

// ---------------- 2-term fp16 HMMA GEMM: 128x128, GBK=32, 3-stage ----------
// C = (Ah + Al) * B   (A split fp16, B single fp16)
#define GBM 128
#define GBN 128
#define GBK 32
#define NSTAGE 3
#define STAGE_ELEMS (2 * GBM * GBK + GBK * GBN)       // 12288 f16 = 24 KB
#define STAGE_BYTES (STAGE_ELEMS * 2)
#define SOFF_AH 0
#define SOFF_AL (GBM * GBK)
#define SOFF_B  (2 * GBM * GBK)
#define GSMEM (NSTAGE * STAGE_BYTES)                  // 73728 bytes

template <bool BIAS, bool RELU, bool RES, bool SPLIT>
__global__ void __launch_bounds__(256, 2) k_mm(
    const f16* __restrict__ Ah, const f16* __restrict__ Al,
    const f16* __restrict__ B,
    const float* __restrict__ bias, const float* __restrict__ res,
    float* __restrict__ Cf, f16* __restrict__ Ch, f16* __restrict__ Cl,
    int M, int N, int K) {
    extern __shared__ f16 sm[];
    int tid = threadIdx.x;
    int lane = tid & 31, wid = tid >> 5;
    int wm = wid >> 2;            // 0..1  (64 rows)
    int wn = wid & 3;             // 0..3  (32 cols)
    int m0 = blockIdx.y * GBM, n0 = blockIdx.x * GBN;
    uint32_t smbase = (uint32_t)__cvta_generic_to_shared(sm);

    float acc[4][4][4];
#pragma unroll
    for (int i = 0; i < 4; i++)
#pragma unroll
        for (int j = 0; j < 4; j++)
#pragma unroll
            for (int q = 0; q < 4; q++) acc[i][j][q] = 0.0f;

    int nk = K / GBK;

    auto load_stage = [&](int kt) {
        int buf = kt % NSTAGE;
        uint32_t sb = smbase + (uint32_t)buf * STAGE_BYTES;
#pragma unroll
        for (int p = 0; p < 2; p++) {       // A: 128 rows x 4 16B-chunks
            int f = p * 256 + tid;
            int r = f >> 2, c = f & 3;
            uint32_t dst = (uint32_t)(r * GBK + ((c ^ ((r >> 1) & 3)) << 3));
            size_t src = (size_t)(m0 + r) * K + kt * GBK + (c << 3);
            cp16(sb + (SOFF_AH + dst) * 2, Ah + src);
            cp16(sb + (SOFF_AL + dst) * 2, Al + src);
        }
#pragma unroll
        for (int p = 0; p < 2; p++) {       // B: 32 k-rows x 16 16B-chunks
            int f = p * 256 + tid;
            int k = f >> 4, c = f & 15;
            int cs = (c & 8) | ((c ^ (k & 7)) & 7);
            uint32_t dst = (uint32_t)(k * GBN + (cs << 3));
            size_t src = (size_t)(kt * GBK + k) * N + n0 + (c << 3);
            cp16(sb + (SOFF_B + dst) * 2, B + src);
        }
        cp_commit();
    };

    load_stage(0);
    if (nk > 1) load_stage(1);

    for (int kt = 0; kt < nk; kt++) {
        if (kt == nk - 1) cp_wait<0>();
        else              cp_wait<1>();
        __syncthreads();        // rendezvous: compute(kt-1) done, stage kt visible
        if (kt + 2 < nk) load_stage(kt + 2);
        uint32_t sb = smbase + (uint32_t)(kt % NSTAGE) * STAGE_BYTES;

#pragma unroll
        for (int ks = 0; ks < GBK / 16; ks++) {
            uint32_t ah[4][4], al[4][4];
#pragma unroll
            for (int mt = 0; mt < 4; mt++) {
                int row = wm * 64 + mt * 16 + (lane & 15);
                int kc = ks * 2 + (lane >> 4);
                uint32_t off = (uint32_t)(row * GBK + ((kc ^ ((row >> 1) & 3)) << 3)) * 2;
                ldsm4(ah[mt], sb + SOFF_AH * 2 + off);
                ldsm4(al[mt], sb + SOFF_AL * 2 + off);
            }
#pragma unroll
            for (int np = 0; np < 2; np++) {
                uint32_t bb[2][2];
                {
                    int krow = ks * 16 + (lane & 15);
                    int nc = wn * 4 + np * 2 + (lane >> 4);
                    int ncs = (nc & 8) | ((nc ^ (krow & 7)) & 7);
                    uint32_t off = (uint32_t)(krow * GBN + (ncs << 3)) * 2;
                    uint32_t r[4];
                    ldsm4t(r, sb + SOFF_B * 2 + off);
                    bb[0][0] = r[0]; bb[0][1] = r[1];
                    bb[1][0] = r[2]; bb[1][1] = r[3];
                }
                // pass 1: Ah * B
#pragma unroll
                for (int mt = 0; mt < 4; mt++)
#pragma unroll
                    for (int j = 0; j < 2; j++)
                        mma16816(acc[mt][np * 2 + j], ah[mt], bb[j]);
                // pass 2: Al * B
#pragma unroll
                for (int mt = 0; mt < 4; mt++)
#pragma unroll
                    for (int j = 0; j < 2; j++)
                        mma16816(acc[mt][np * 2 + j], al[mt], bb[j]);
            }
        }
    }

#pragma unroll
    for (int mt = 0; mt < 4; mt++)
#pragma unroll
        for (int nt = 0; nt < 4; nt++) {
            int rbase = m0 + wm * 64 + mt * 16 + (lane >> 2);
            int cbase = n0 + wn * 32 + nt * 8 + (lane & 3) * 2;
#pragma unroll
            for (int half = 0; half < 2; half++) {
                int r = rbase + half * 8;
                float c0 = acc[mt][nt][half * 2 + 0];
                float c1 = acc[mt][nt][half * 2 + 1];
                size_t off = (size_t)r * N + cbase;
                if (BIAS) { c0 += bias[cbase]; c1 += bias[cbase + 1]; }
                if (RES)  { float2 rv = *(const float2*)(res + off); c0 += rv.x; c1 += rv.y; }
                if (RELU) { c0 = fmaxf(c0, 0.f); c1 = fmaxf(c1, 0.f); }
                if (SPLIT) {
                    uint32_t hi, lo;
                    split2(c0, c1, hi, lo);
                    *(uint32_t*)(Ch + off) = hi;
                    *(uint32_t*)(Cl + off) = lo;
                } else {
                    *(float2*)(Cf + off) = make_float2(c0, c1);
                }
            }
        }
}

// ---------------- tensor-core flash attention (fused QKV buffer) -----------
// S = (Qh+Ql) Kh^T  (2-term, K hi only);  P V 2-term (V hi only).
#define FBR 128
#define FBC 64
#define FQ_H 0
#define FQ_L (FBR * 64)
#define FKV0 (2 * FBR * 64)
#define FKV_STRIDE (2 * FBC * 64)
#define FK_H 0
#define FV_H (FBC * 64)
#define FSMEM ((2 * FBR * 64 + 2 * FKV_STRIDE) * 2)   // 65536 bytes

__global__ void __launch_bounds__(256, 2) k_fattn(
    const f16* __restrict__ QKVh, const f16* __restrict__ QKVl,
    const int* __restrict__ lengths,
    f16* __restrict__ Oh, f16* __restrict__ Ol) {
    extern __shared__ f16 sm[];
    uint32_t smb = (uint32_t)__cvta_generic_to_shared(sm);
    int b = blockIdx.z, h = blockIdx.y, qt = blockIdx.x;
    int len = lengths[b];
    int tid = threadIdx.x, lane = tid & 31, wid = tid >> 5;
    size_t qrow0 = (size_t)(b * SEQL + qt * FBR);
    size_t hoff = (size_t)h * DHEAD;

    auto load_kv = [&](int kt, int stg) {
        uint32_t sb = smb + (uint32_t)(FKV0 + stg * FKV_STRIDE) * 2;
        int kb = kt * FBC;
#pragma unroll
        for (int p = 0; p < 2; p++) {
            int f = p * 256 + tid;
            int r = f >> 3, c = f & 7;
            uint32_t d = (uint32_t)((r * 64 + ((c ^ (r & 7)) << 3)) * 2);
            size_t src = (size_t)(b * SEQL + kb + r) * QKVS + hoff + (c << 3);
            cp16(sb + FK_H * 2 + d, QKVh + src + 512);
            cp16(sb + FV_H * 2 + d, QKVh + src + 1024);
        }
        cp_commit();
    };

    load_kv(0, 0);

#pragma unroll
    for (int p = 0; p < 4; p++) {
        int f = p * 256 + tid;
        int r = f >> 3, c = f & 7;
        uint32_t d = (uint32_t)(r * 64 + ((c ^ (r & 7)) << 3));
        size_t src = (qrow0 + r) * QKVS + hoff + (c << 3);
        *(uint4*)(sm + FQ_H + d) = *(const uint4*)(QKVh + src);
        *(uint4*)(sm + FQ_L + d) = *(const uint4*)(QKVl + src);
    }
    __syncthreads();

    uint32_t qh[4][4], ql[4][4];
#pragma unroll
    for (int ks = 0; ks < 4; ks++) {
        int row = wid * 16 + (lane & 15);
        int kc = ks * 2 + (lane >> 4);
        uint32_t off = (uint32_t)(row * 64 + ((kc ^ (row & 7)) << 3)) * 2;
        ldsm4(qh[ks], smb + FQ_H * 2 + off);
        ldsm4(ql[ks], smb + FQ_L * 2 + off);
    }

    float o[8][4];
#pragma unroll
    for (int i = 0; i < 8; i++)
#pragma unroll
        for (int j = 0; j < 4; j++) o[i][j] = 0.0f;
    float m0 = -3.0e38f, m1 = -3.0e38f, l0 = 0.0f, l1 = 0.0f;

    int nkt = (len + FBC - 1) / FBC;
    for (int kt = 0; kt < nkt; kt++) {
        if (kt + 1 < nkt) { load_kv(kt + 1, (kt + 1) & 1); cp_wait<1>(); }
        else              { cp_wait<0>(); }
        __syncthreads();
        uint32_t sb = smb + (uint32_t)(FKV0 + (kt & 1) * FKV_STRIDE) * 2;

        float s[8][4];
#pragma unroll
        for (int i = 0; i < 8; i++)
#pragma unroll
            for (int j = 0; j < 4; j++) s[i][j] = 0.0f;

        // S = (Qh + Ql) Kh^T   (4 MMAs per kg)
#pragma unroll
        for (int ks = 0; ks < 4; ks++) {
#pragma unroll
            for (int kg = 0; kg < 4; kg++) {
                int key = kg * 16 + (lane & 15);
                int kc = ks * 2 + (lane >> 4);
                uint32_t off = (uint32_t)(key * 64 + ((kc ^ (key & 7)) << 3)) * 2;
                uint32_t rh[4];
                ldsm4(rh, sb + FK_H * 2 + off);
                uint32_t bh0[2] = {rh[0], rh[2]}, bh1[2] = {rh[1], rh[3]};
                mma16816(s[kg * 2],     qh[ks], bh0);
                mma16816(s[kg * 2 + 1], qh[ks], bh1);
                mma16816(s[kg * 2],     ql[ks], bh0);
                mma16816(s[kg * 2 + 1], ql[ks], bh1);
            }
        }

        int colbase = kt * FBC + (lane & 3) * 2;
        float mx0 = -3.0e38f, mx1 = -3.0e38f;
#pragma unroll
        for (int nf = 0; nf < 8; nf++) {
            int c = colbase + nf * 8;
            float b0 = (c     >= len) ? -1e9f : 0.0f;
            float b1 = (c + 1 >= len) ? -1e9f : 0.0f;
            s[nf][0] = s[nf][0] * 0.125f + b0;
            s[nf][1] = s[nf][1] * 0.125f + b1;
            s[nf][2] = s[nf][2] * 0.125f + b0;
            s[nf][3] = s[nf][3] * 0.125f + b1;
            mx0 = fmaxf(mx0, fmaxf(s[nf][0], s[nf][1]));
            mx1 = fmaxf(mx1, fmaxf(s[nf][2], s[nf][3]));
        }
        mx0 = fmaxf(mx0, __shfl_xor_sync(0xffffffffu, mx0, 1));
        mx0 = fmaxf(mx0, __shfl_xor_sync(0xffffffffu, mx0, 2));
        mx1 = fmaxf(mx1, __shfl_xor_sync(0xffffffffu, mx1, 1));
        mx1 = fmaxf(mx1, __shfl_xor_sync(0xffffffffu, mx1, 2));
        float mn0 = fmaxf(m0, mx0), mn1 = fmaxf(m1, mx1);
        float a0 = __expf(m0 - mn0), a1 = __expf(m1 - mn1);
        float ls0 = 0.0f, ls1 = 0.0f;
#pragma unroll
        for (int nf = 0; nf < 8; nf++) {
            s[nf][0] = __expf(s[nf][0] - mn0);
            s[nf][1] = __expf(s[nf][1] - mn0);
            s[nf][2] = __expf(s[nf][2] - mn1);
            s[nf][3] = __expf(s[nf][3] - mn1);
            ls0 += s[nf][0] + s[nf][1];
            ls1 += s[nf][2] + s[nf][3];
        }
        ls0 += __shfl_xor_sync(0xffffffffu, ls0, 1);
        ls0 += __shfl_xor_sync(0xffffffffu, ls0, 2);
        ls1 += __shfl_xor_sync(0xffffffffu, ls1, 1);
        ls1 += __shfl_xor_sync(0xffffffffu, ls1, 2);
        l0 = l0 * a0 + ls0;
        l1 = l1 * a1 + ls1;
        m0 = mn0; m1 = mn1;
#pragma unroll
        for (int nf = 0; nf < 8; nf++) {
            o[nf][0] *= a0; o[nf][1] *= a0;
            o[nf][2] *= a1; o[nf][3] *= a1;
        }

        // P V : 2-term (Ph + Pl) x Vh
#pragma unroll
        for (int kg = 0; kg < 4; kg++) {
            uint32_t ph[4], pl[4];
            split2(s[2 * kg][0], s[2 * kg][1], ph[0], pl[0]);
            split2(s[2 * kg][2], s[2 * kg][3], ph[1], pl[1]);
            split2(s[2 * kg + 1][0], s[2 * kg + 1][1], ph[2], pl[2]);
            split2(s[2 * kg + 1][2], s[2 * kg + 1][3], ph[3], pl[3]);
#pragma unroll
            for (int np = 0; np < 4; np++) {
                int krow = kg * 16 + (lane & 15);
                int nc = np * 2 + (lane >> 4);
                uint32_t off = (uint32_t)(krow * 64 + ((nc ^ (krow & 7)) << 3)) * 2;
                uint32_t rh[4];
                ldsm4t(rh, sb + FV_H * 2 + off);
                uint32_t vh0[2] = {rh[0], rh[1]}, vh1[2] = {rh[2], rh[3]};
                mma16816(o[np * 2],     ph, vh0);
                mma16816(o[np * 2 + 1], ph, vh1);
                mma16816(o[np * 2],     pl, vh0);
                mma16816(o[np * 2 + 1], pl, vh1);
            }
        }
        __syncthreads();
    }

    float li0 = 1.0f / l0, li1 = 1.0f / l1;
    int r0 = wid * 16 + (lane >> 2);
    size_t row0 = (qrow0 + r0) * DMODEL + hoff + (lane & 3) * 2;
    size_t row1 = (qrow0 + r0 + 8) * DMODEL + hoff + (lane & 3) * 2;
#pragma unroll
    for (int nf = 0; nf < 8; nf++) {
        uint32_t hi, lo;
        split2(o[nf][0] * li0, o[nf][1] * li0, hi, lo);
        *(uint32_t*)(Oh + row0 + nf * 8) = hi;
        *(uint32_t*)(Ol + row0 + nf * 8) = lo;
        split2(o[nf][2] * li1, o[nf][3] * li1, hi, lo);
        *(uint32_t*)(Oh + row1 + nf * 8) = hi;
        *(uint32_t*)(Ol + row1 + nf * 8) = lo;
    }
}

// ---------------- orchestration -------------------------------------------
extern "C" void kernel_launch(void* const* d_in, const int* in_sizes, int n_in,
                              void* d_out, int out_size) {
    (void)in_sizes; (void)n_in; (void)out_size;
    const float* x_in    = (const float*)d_in[0];
    const int*   lengths = (const int*)d_in[1];
    const float* Wq = (const float*)d_in[2];
    const float* Wk = (const float*)d_in[3];
    const float* Wv = (const float*)d_in[4];
    const float* Wo = (const float*)d_in[5];
    const float* ln1g = (const float*)d_in[6];
    const float* ln1b = (const float*)d_in[7];
    const float* ln2g = (const float*)d_in[8];
    const float* ln2b = (const float*)d_in[9];
    const float* w1 = (const float*)d_in[10];
    const float* b1 = (const float*)d_in[11];
    const float* w2 = (const float*)d_in[12];
    const float* b2 = (const float*)d_in[13];

    float* px;
    f16 *phh, *phl, *pqkvh, *pqkvl, *pfh, *pfl, *pwh;
    cudaGetSymbolAddress((void**)&px, g_x);
    cudaGetSymbolAddress((void**)&phh, g_hh);
    cudaGetSymbolAddress((void**)&phl, g_hl);
    cudaGetSymbolAddress((void**)&pqkvh, g_qkvh);
    cudaGetSymbolAddress((void**)&pqkvl, g_qkvl);
    cudaGetSymbolAddress((void**)&pfh, g_fh);
    cudaGetSymbolAddress((void**)&pfl, g_fl);
    cudaGetSymbolAddress((void**)&pwh, g_wh);

    cudaFuncSetAttribute(k_fattn, cudaFuncAttributeMaxDynamicSharedMemorySize, FSMEM);
    cudaFuncSetAttribute(k_mm<false, false, false, true>,
                         cudaFuncAttributeMaxDynamicSharedMemorySize, GSMEM);
    cudaFuncSetAttribute(k_mm<false, false, true, false>,
                         cudaFuncAttributeMaxDynamicSharedMemorySize, GSMEM);
    cudaFuncSetAttribute(k_mm<true, true, false, true>,
                         cudaFuncAttributeMaxDynamicSharedMemorySize, GSMEM);
    cudaFuncSetAttribute(k_mm<true, false, true, false>,
                         cudaFuncAttributeMaxDynamicSharedMemorySize, GSMEM);

    k_wsplit<<<(WTOT / 4 + 255) / 256, 256>>>(Wq, Wk, Wv, Wo, w1, w2, pwh);
    k_pos<<<(BL * DMODEL) / 256, 256>>>(x_in, px);

    dim3 gQKV(QKVS / GBN, BL / GBM);   // (12, 64)
    dim3 gD(DMODEL / GBN, BL / GBM);   // (4, 64)
    dim3 gF(DFF / GBN, BL / GBM);      // (16, 64)
    dim3 gA(SEQL / FBR, NHEAD, BATCH);

    for (int layer = 0; layer < NLAYER; layer++) {
        const f16* qkvw = pwh + OFF_QKV + (size_t)layer * DMODEL * QKVS;
        const f16* wow  = pwh + OFF_WO + (size_t)layer * DMODEL * DMODEL;
        const f16* w1w  = pwh + OFF_W1 + (size_t)layer * DMODEL * DFF;
        const f16* w2w  = pwh + OFF_W2 + (size_t)layer * DFF * DMODEL;

        k_ln<<<BL, 128>>>(px, ln1g + (size_t)layer * DMODEL, ln1b + (size_t)layer * DMODEL,
                          phh, phl);
        k_mm<false, false, false, true><<<gQKV, 256, GSMEM>>>(
            phh, phl, qkvw, nullptr, nullptr, nullptr, pqkvh, pqkvl,
            BL, QKVS, DMODEL);
        k_fattn<<<gA, 256, FSMEM>>>(pqkvh, pqkvl, lengths, phh, phl);
        k_mm<false, false, true, false><<<gD, 256, GSMEM>>>(
            phh, phl, wow, nullptr, px, px, nullptr, nullptr, BL, DMODEL, DMODEL);

        k_ln<<<BL, 128>>>(px, ln2g + (size_t)layer * DMODEL, ln2b + (size_t)layer * DMODEL,
                          phh, phl);
        k_mm<true, true, false, true><<<gF, 256, GSMEM>>>(
            phh, phl, w1w, b1 + (size_t)layer * DFF, nullptr,
            nullptr, pfh, pfl, BL, DFF, DMODEL);
        float* dst = (layer == NLAYER - 1) ? (float*)d_out : px;
        k_mm<true, false, true, false><<<gD, 256, GSMEM>>>(
            pfh, pfl, w2w, b2 + (size_t)layer * DMODEL, px,
            dst, nullptr, nullptr, BL, DMODEL, DFF);
    }
}

// round 12
// speedup vs baseline: 1.7199x; 1.3400x over previous
#include <cuda_runtime.h>
#include <cuda_fp16.h>
#include <math.h>
#include <stdint.h>

#define BATCH 8
#define SEQL 1024
#define DMODEL 512
#define NHEAD 8
#define DHEAD 64
#define DFF 2048
#define NLAYER 6
#define BL (BATCH * SEQL)   // 8192
#define QKVS 1536           // fused QKV row stride

typedef __half f16;

// ---------------- scratch (device globals: no allocs allowed) -------------
__device__ __align__(128) float g_x[BL * DMODEL];
__device__ __align__(128) f16   g_hh[BL * DMODEL];
__device__ __align__(128) f16   g_hl[BL * DMODEL];
__device__ __align__(128) f16   g_qkv[BL * QKVS];     // single fp16 now
__device__ __align__(128) f16   g_f[BL * DFF];        // single fp16 now

// weight regions (all [K][N] row-major, fp16 HI only)
#define SZ_QKV (NLAYER * DMODEL * QKVS)
#define SZ_WO  (NLAYER * DMODEL * DMODEL)
#define SZ_W1  (NLAYER * DMODEL * DFF)
#define SZ_W2  (NLAYER * DFF * DMODEL)
#define OFF_QKV 0
#define OFF_WO  (OFF_QKV + SZ_QKV)
#define OFF_W1  (OFF_WO + SZ_WO)
#define OFF_W2  (OFF_W1 + SZ_W1)
#define WTOT    (OFF_W2 + SZ_W2)
__device__ __align__(128) f16   g_wh[WTOT];

// ---------------- helpers --------------------------------------------------
__device__ __forceinline__ void cp16(uint32_t s, const void* g) {
    asm volatile("cp.async.cg.shared.global [%0], [%1], 16;\n" :: "r"(s), "l"(g));
}
__device__ __forceinline__ void cp_commit() {
    asm volatile("cp.async.commit_group;\n" ::: "memory");
}
template <int N_>
__device__ __forceinline__ void cp_wait() {
    asm volatile("cp.async.wait_group %0;\n" :: "n"(N_) : "memory");
}
__device__ __forceinline__ void ldsm4(uint32_t* r, uint32_t addr) {
    asm volatile("ldmatrix.sync.aligned.m8n8.x4.shared.b16 {%0,%1,%2,%3}, [%4];"
                 : "=r"(r[0]), "=r"(r[1]), "=r"(r[2]), "=r"(r[3]) : "r"(addr));
}
__device__ __forceinline__ void ldsm4t(uint32_t* r, uint32_t addr) {
    asm volatile("ldmatrix.sync.aligned.m8n8.x4.trans.shared.b16 {%0,%1,%2,%3}, [%4];"
                 : "=r"(r[0]), "=r"(r[1]), "=r"(r[2]), "=r"(r[3]) : "r"(addr));
}
__device__ __forceinline__ void mma16816(float* c, const uint32_t* a, const uint32_t* b) {
    asm volatile(
        "mma.sync.aligned.m16n8k16.row.col.f32.f16.f16.f32 "
        "{%0,%1,%2,%3}, {%4,%5,%6,%7}, {%8,%9}, {%0,%1,%2,%3};"
        : "+f"(c[0]), "+f"(c[1]), "+f"(c[2]), "+f"(c[3])
        : "r"(a[0]), "r"(a[1]), "r"(a[2]), "r"(a[3]), "r"(b[0]), "r"(b[1]));
}
__device__ __forceinline__ uint32_t packh(f16 a, f16 b) {
    return ((uint32_t)__half_as_ushort(b) << 16) | __half_as_ushort(a);
}
__device__ __forceinline__ void split2(float a, float b, uint32_t& hi, uint32_t& lo) {
    f16 ha = __float2half_rn(a), hb = __float2half_rn(b);
    f16 la = __float2half_rn(a - __half2float(ha));
    f16 lb = __float2half_rn(b - __half2float(hb));
    hi = packh(ha, hb);
    lo = packh(la, lb);
}

// ---------------- positional embedding + add ------------------------------
__global__ void k_pos(const float* __restrict__ xin, float* __restrict__ xout) {
    int idx = blockIdx.x * 256 + threadIdx.x;
    if (idx >= BL * DMODEL) return;
    int d = idx % DMODEL;
    int l = (idx / DMODEL) % SEQL;
    int half = DMODEL / 2;
    int i = (d < half) ? d : d - half;
    float inv = powf(10000.0f, -2.0f * (float)i / (float)DMODEL);
    float ang = (float)l * inv;
    float pe = (d < half) ? sinf(ang) : cosf(ang);
    xout[idx] = xin[idx] + pe;
}

// ---------------- combined weight convert (hi only) ------------------------
__global__ void __launch_bounds__(256) k_wsplit(
    const float* __restrict__ Wq, const float* __restrict__ Wk,
    const float* __restrict__ Wv, const float* __restrict__ Wo,
    const float* __restrict__ w1, const float* __restrict__ w2,
    f16* __restrict__ dh) {
    uint32_t idx = (blockIdx.x * 256 + threadIdx.x) * 4;
    if (idx >= WTOT) return;
    const float* src;
    if (idx < OFF_WO) {
        uint32_t rel = idx;
        uint32_t l = rel / (DMODEL * QKVS);
        uint32_t r2 = rel - l * (DMODEL * QKVS);
        uint32_t k = r2 / QKVS;
        uint32_t j = r2 - k * QKVS;
        uint32_t sel = j >> 9;
        uint32_t jj = j & 511;
        const float* W = (sel == 0) ? Wq : (sel == 1) ? Wk : Wv;
        src = W + (size_t)l * DMODEL * DMODEL + (size_t)k * DMODEL + jj;
    } else if (idx < OFF_W1) {
        src = Wo + (idx - OFF_WO);
    } else if (idx < OFF_W2) {
        src = w1 + (idx - OFF_W1);
    } else {
        src = w2 + (idx - OFF_W2);
    }
    float4 v = *(const float4*)src;
    uint32_t h0 = packh(__float2half_rn(v.x), __float2half_rn(v.y));
    uint32_t h1 = packh(__float2half_rn(v.z), __float2half_rn(v.w));
    uint32_t* hp = (uint32_t*)(dh + idx);
    hp[0] = h0; hp[1] = h1;
}

// ---------------- layernorm -> split fp16 output --------------------------
__global__ void __launch_bounds__(128) k_ln(const float* __restrict__ x,
                                            const float* __restrict__ g,
                                            const float* __restrict__ b,
                                            f16* __restrict__ ohi,
                                            f16* __restrict__ olo) {
    int row = blockIdx.x;
    int tid = threadIdx.x;
    const float4* xr = (const float4*)(x + (size_t)row * DMODEL);
    float4 v = xr[tid];
    __shared__ float sh[4];

    float s = v.x + v.y + v.z + v.w;
    for (int o = 16; o; o >>= 1) s += __shfl_xor_sync(0xffffffffu, s, o);
    if ((tid & 31) == 0) sh[tid >> 5] = s;
    __syncthreads();
    float mean = (sh[0] + sh[1] + sh[2] + sh[3]) * (1.0f / DMODEL);
    __syncthreads();

    float dx0 = v.x - mean, dx1 = v.y - mean, dx2 = v.z - mean, dx3 = v.w - mean;
    float s2 = dx0 * dx0 + dx1 * dx1 + dx2 * dx2 + dx3 * dx3;
    for (int o = 16; o; o >>= 1) s2 += __shfl_xor_sync(0xffffffffu, s2, o);
    if ((tid & 31) == 0) sh[tid >> 5] = s2;
    __syncthreads();
    float var = (sh[0] + sh[1] + sh[2] + sh[3]) * (1.0f / DMODEL);
    float r = rsqrtf(var + 1e-3f);

    float4 gg = ((const float4*)g)[tid];
    float4 bb = ((const float4*)b)[tid];
    float o0 = dx0 * r * gg.x + bb.x;
    float o1 = dx1 * r * gg.y + bb.y;
    float o2 = dx2 * r * gg.z + bb.z;
    float o3 = dx3 * r * gg.w + bb.w;

    uint32_t h0, l0, h1, l1;
    split2(o0, o1, h0, l0);
    split2(o2, o3, h1, l1);
    size_t off = (size_t)row * DMODEL + tid * 4;
    uint32_t* hp = (uint32_t*)(ohi + off);
    uint32_t* lp = (uint32_t*)(olo + off);
    hp[0] = h0; hp[1] = h1;
    lp[0] = l0; lp[1] = l1;
}

// ---------------- fp16 HMMA GEMM: 128x128, GBK=32, 3-stage -----------------
// TERMS==2: C = (Ah + Al) * B ;  TERMS==1: C = A * B (pure fp16)
// OUT: 0 = fp32 (Cf), 1 = fp16 (Ch), 2 = split (Ch+Cl)
#define GBM 128
#define GBN 128
#define GBK 32
#define NSTAGE 3
#define STAGE2_ELEMS (2 * GBM * GBK + GBK * GBN)      // 12288 f16 = 24 KB
#define STAGE1_ELEMS (GBM * GBK + GBK * GBN)          // 8192 f16 = 16 KB
#define SOFF_AH 0
#define GSMEM2 (NSTAGE * STAGE2_ELEMS * 2)            // 73728 bytes
#define GSMEM1 (NSTAGE * STAGE1_ELEMS * 2)            // 49152 bytes

template <int TERMS, int OUT, bool BIAS, bool RELU, bool RES>
__global__ void __launch_bounds__(256, 2) k_mm(
    const f16* __restrict__ Ah, const f16* __restrict__ Al,
    const f16* __restrict__ B,
    const float* __restrict__ bias, const float* __restrict__ res,
    float* __restrict__ Cf, f16* __restrict__ Ch, f16* __restrict__ Cl,
    int M, int N, int K) {
    extern __shared__ f16 sm[];
    const int STAGE_ELEMS = (TERMS == 2) ? STAGE2_ELEMS : STAGE1_ELEMS;
    const int SOFF_AL = GBM * GBK;                     // only for TERMS==2
    const int SOFF_B  = TERMS * GBM * GBK;
    int tid = threadIdx.x;
    int lane = tid & 31, wid = tid >> 5;
    int wm = wid >> 2;            // 0..1  (64 rows)
    int wn = wid & 3;             // 0..3  (32 cols)
    int m0 = blockIdx.y * GBM, n0 = blockIdx.x * GBN;
    uint32_t smbase = (uint32_t)__cvta_generic_to_shared(sm);

    float acc[4][4][4];
#pragma unroll
    for (int i = 0; i < 4; i++)
#pragma unroll
        for (int j = 0; j < 4; j++)
#pragma unroll
            for (int q = 0; q < 4; q++) acc[i][j][q] = 0.0f;

    int nk = K / GBK;

    auto load_stage = [&](int kt) {
        int buf = kt % NSTAGE;
        uint32_t sb = smbase + (uint32_t)(buf * STAGE_ELEMS) * 2;
#pragma unroll
        for (int p = 0; p < 2; p++) {       // A: 128 rows x 4 16B-chunks
            int f = p * 256 + tid;
            int r = f >> 2, c = f & 3;
            uint32_t dst = (uint32_t)(r * GBK + ((c ^ ((r >> 1) & 3)) << 3));
            size_t src = (size_t)(m0 + r) * K + kt * GBK + (c << 3);
            cp16(sb + (SOFF_AH + dst) * 2, Ah + src);
            if (TERMS == 2) cp16(sb + (SOFF_AL + dst) * 2, Al + src);
        }
#pragma unroll
        for (int p = 0; p < 2; p++) {       // B: 32 k-rows x 16 16B-chunks
            int f = p * 256 + tid;
            int k = f >> 4, c = f & 15;
            int cs = (c & 8) | ((c ^ (k & 7)) & 7);
            uint32_t dst = (uint32_t)(k * GBN + (cs << 3));
            size_t src = (size_t)(kt * GBK + k) * N + n0 + (c << 3);
            cp16(sb + (SOFF_B + dst) * 2, B + src);
        }
        cp_commit();
    };

    load_stage(0);
    if (nk > 1) load_stage(1);

    for (int kt = 0; kt < nk; kt++) {
        if (kt == nk - 1) cp_wait<0>();
        else              cp_wait<1>();
        __syncthreads();
        if (kt + 2 < nk) load_stage(kt + 2);
        uint32_t sb = smbase + (uint32_t)((kt % NSTAGE) * STAGE_ELEMS) * 2;

#pragma unroll
        for (int ks = 0; ks < GBK / 16; ks++) {
            uint32_t ah[4][4], al[4][4];
#pragma unroll
            for (int mt = 0; mt < 4; mt++) {
                int row = wm * 64 + mt * 16 + (lane & 15);
                int kc = ks * 2 + (lane >> 4);
                uint32_t off = (uint32_t)(row * GBK + ((kc ^ ((row >> 1) & 3)) << 3)) * 2;
                ldsm4(ah[mt], sb + SOFF_AH * 2 + off);
                if (TERMS == 2) ldsm4(al[mt], sb + SOFF_AL * 2 + off);
            }
#pragma unroll
            for (int np = 0; np < 2; np++) {
                uint32_t bb[2][2];
                {
                    int krow = ks * 16 + (lane & 15);
                    int nc = wn * 4 + np * 2 + (lane >> 4);
                    int ncs = (nc & 8) | ((nc ^ (krow & 7)) & 7);
                    uint32_t off = (uint32_t)(krow * GBN + (ncs << 3)) * 2;
                    uint32_t r[4];
                    ldsm4t(r, sb + SOFF_B * 2 + off);
                    bb[0][0] = r[0]; bb[0][1] = r[1];
                    bb[1][0] = r[2]; bb[1][1] = r[3];
                }
#pragma unroll
                for (int mt = 0; mt < 4; mt++)
#pragma unroll
                    for (int j = 0; j < 2; j++)
                        mma16816(acc[mt][np * 2 + j], ah[mt], bb[j]);
                if (TERMS == 2) {
#pragma unroll
                    for (int mt = 0; mt < 4; mt++)
#pragma unroll
                        for (int j = 0; j < 2; j++)
                            mma16816(acc[mt][np * 2 + j], al[mt], bb[j]);
                }
            }
        }
    }

#pragma unroll
    for (int mt = 0; mt < 4; mt++)
#pragma unroll
        for (int nt = 0; nt < 4; nt++) {
            int rbase = m0 + wm * 64 + mt * 16 + (lane >> 2);
            int cbase = n0 + wn * 32 + nt * 8 + (lane & 3) * 2;
#pragma unroll
            for (int half = 0; half < 2; half++) {
                int r = rbase + half * 8;
                float c0 = acc[mt][nt][half * 2 + 0];
                float c1 = acc[mt][nt][half * 2 + 1];
                size_t off = (size_t)r * N + cbase;
                if (BIAS) { c0 += bias[cbase]; c1 += bias[cbase + 1]; }
                if (RES)  { float2 rv = *(const float2*)(res + off); c0 += rv.x; c1 += rv.y; }
                if (RELU) { c0 = fmaxf(c0, 0.f); c1 = fmaxf(c1, 0.f); }
                if (OUT == 0) {
                    *(float2*)(Cf + off) = make_float2(c0, c1);
                } else if (OUT == 1) {
                    *(uint32_t*)(Ch + off) = packh(__float2half_rn(c0), __float2half_rn(c1));
                } else {
                    uint32_t hi, lo;
                    split2(c0, c1, hi, lo);
                    *(uint32_t*)(Ch + off) = hi;
                    *(uint32_t*)(Cl + off) = lo;
                }
            }
        }
}

// ---------------- flash attention: pure fp16 S, split-P PV -----------------
// S = Q Kh^T (fp16);  O = (Ph+Pl) Vh;  output written split for WO 2-term.
#define FBR 128
#define FBC 64
#define FQ 0
#define FKV0 (FBR * 64)
#define FKV_STRIDE (2 * FBC * 64)
#define FK 0
#define FV (FBC * 64)
#define FSMEM ((FBR * 64 + 2 * FKV_STRIDE) * 2)   // 49152 bytes

__global__ void __launch_bounds__(256, 2) k_fattn(
    const f16* __restrict__ QKV,
    const int* __restrict__ lengths,
    f16* __restrict__ Oh, f16* __restrict__ Ol) {
    extern __shared__ f16 sm[];
    uint32_t smb = (uint32_t)__cvta_generic_to_shared(sm);
    int b = blockIdx.z, h = blockIdx.y, qt = blockIdx.x;
    int len = lengths[b];
    int tid = threadIdx.x, lane = tid & 31, wid = tid >> 5;
    size_t qrow0 = (size_t)(b * SEQL + qt * FBR);
    size_t hoff = (size_t)h * DHEAD;

    auto load_kv = [&](int kt, int stg) {
        uint32_t sb = smb + (uint32_t)(FKV0 + stg * FKV_STRIDE) * 2;
        int kb = kt * FBC;
#pragma unroll
        for (int p = 0; p < 2; p++) {
            int f = p * 256 + tid;
            int r = f >> 3, c = f & 7;
            uint32_t d = (uint32_t)((r * 64 + ((c ^ (r & 7)) << 3)) * 2);
            size_t src = (size_t)(b * SEQL + kb + r) * QKVS + hoff + (c << 3);
            cp16(sb + FK * 2 + d, QKV + src + 512);
            cp16(sb + FV * 2 + d, QKV + src + 1024);
        }
        cp_commit();
    };

    load_kv(0, 0);

#pragma unroll
    for (int p = 0; p < 4; p++) {
        int f = p * 256 + tid;
        int r = f >> 3, c = f & 7;
        uint32_t d = (uint32_t)(r * 64 + ((c ^ (r & 7)) << 3));
        size_t src = (qrow0 + r) * QKVS + hoff + (c << 3);
        *(uint4*)(sm + FQ + d) = *(const uint4*)(QKV + src);
    }
    __syncthreads();

    uint32_t qh[4][4];
#pragma unroll
    for (int ks = 0; ks < 4; ks++) {
        int row = wid * 16 + (lane & 15);
        int kc = ks * 2 + (lane >> 4);
        uint32_t off = (uint32_t)(row * 64 + ((kc ^ (row & 7)) << 3)) * 2;
        ldsm4(qh[ks], smb + FQ * 2 + off);
    }

    float o[8][4];
#pragma unroll
    for (int i = 0; i < 8; i++)
#pragma unroll
        for (int j = 0; j < 4; j++) o[i][j] = 0.0f;
    float m0 = -3.0e38f, m1 = -3.0e38f, l0 = 0.0f, l1 = 0.0f;

    int nkt = (len + FBC - 1) / FBC;
    for (int kt = 0; kt < nkt; kt++) {
        if (kt + 1 < nkt) { load_kv(kt + 1, (kt + 1) & 1); cp_wait<1>(); }
        else              { cp_wait<0>(); }
        __syncthreads();
        uint32_t sb = smb + (uint32_t)(FKV0 + (kt & 1) * FKV_STRIDE) * 2;

        float s[8][4];
#pragma unroll
        for (int i = 0; i < 8; i++)
#pragma unroll
            for (int j = 0; j < 4; j++) s[i][j] = 0.0f;

        // S = Q Kh^T  (2 MMAs per (ks,kg))
#pragma unroll
        for (int ks = 0; ks < 4; ks++) {
#pragma unroll
            for (int kg = 0; kg < 4; kg++) {
                int key = kg * 16 + (lane & 15);
                int kc = ks * 2 + (lane >> 4);
                uint32_t off = (uint32_t)(key * 64 + ((kc ^ (key & 7)) << 3)) * 2;
                uint32_t rh[4];
                ldsm4(rh, sb + FK * 2 + off);
                uint32_t bh0[2] = {rh[0], rh[2]}, bh1[2] = {rh[1], rh[3]};
                mma16816(s[kg * 2],     qh[ks], bh0);
                mma16816(s[kg * 2 + 1], qh[ks], bh1);
            }
        }

        int colbase = kt * FBC + (lane & 3) * 2;
        float mx0 = -3.0e38f, mx1 = -3.0e38f;
#pragma unroll
        for (int nf = 0; nf < 8; nf++) {
            int c = colbase + nf * 8;
            float b0 = (c     >= len) ? -1e9f : 0.0f;
            float b1 = (c + 1 >= len) ? -1e9f : 0.0f;
            s[nf][0] = s[nf][0] * 0.125f + b0;
            s[nf][1] = s[nf][1] * 0.125f + b1;
            s[nf][2] = s[nf][2] * 0.125f + b0;
            s[nf][3] = s[nf][3] * 0.125f + b1;
            mx0 = fmaxf(mx0, fmaxf(s[nf][0], s[nf][1]));
            mx1 = fmaxf(mx1, fmaxf(s[nf][2], s[nf][3]));
        }
        mx0 = fmaxf(mx0, __shfl_xor_sync(0xffffffffu, mx0, 1));
        mx0 = fmaxf(mx0, __shfl_xor_sync(0xffffffffu, mx0, 2));
        mx1 = fmaxf(mx1, __shfl_xor_sync(0xffffffffu, mx1, 1));
        mx1 = fmaxf(mx1, __shfl_xor_sync(0xffffffffu, mx1, 2));
        float mn0 = fmaxf(m0, mx0), mn1 = fmaxf(m1, mx1);
        float a0 = __expf(m0 - mn0), a1 = __expf(m1 - mn1);
        float ls0 = 0.0f, ls1 = 0.0f;
#pragma unroll
        for (int nf = 0; nf < 8; nf++) {
            s[nf][0] = __expf(s[nf][0] - mn0);
            s[nf][1] = __expf(s[nf][1] - mn0);
            s[nf][2] = __expf(s[nf][2] - mn1);
            s[nf][3] = __expf(s[nf][3] - mn1);
            ls0 += s[nf][0] + s[nf][1];
            ls1 += s[nf][2] + s[nf][3];
        }
        ls0 += __shfl_xor_sync(0xffffffffu, ls0, 1);
        ls0 += __shfl_xor_sync(0xffffffffu, ls0, 2);
        ls1 += __shfl_xor_sync(0xffffffffu, ls1, 1);
        ls1 += __shfl_xor_sync(0xffffffffu, ls1, 2);
        l0 = l0 * a0 + ls0;
        l1 = l1 * a1 + ls1;
        m0 = mn0; m1 = mn1;
#pragma unroll
        for (int nf = 0; nf < 8; nf++) {
            o[nf][0] *= a0; o[nf][1] *= a0;
            o[nf][2] *= a1; o[nf][3] *= a1;
        }

        // P V : 2-term (Ph + Pl) x Vh
#pragma unroll
        for (int kg = 0; kg < 4; kg++) {
            uint32_t ph[4], pl[4];
            split2(s[2 * kg][0], s[2 * kg][1], ph[0], pl[0]);
            split2(s[2 * kg][2], s[2 * kg][3], ph[1], pl[1]);
            split2(s[2 * kg + 1][0], s[2 * kg + 1][1], ph[2], pl[2]);
            split2(s[2 * kg + 1][2], s[2 * kg + 1][3], ph[3], pl[3]);
#pragma unroll
            for (int np = 0; np < 4; np++) {
                int krow = kg * 16 + (lane & 15);
                int nc = np * 2 + (lane >> 4);
                uint32_t off = (uint32_t)(krow * 64 + ((nc ^ (krow & 7)) << 3)) * 2;
                uint32_t rh[4];
                ldsm4t(rh, sb + FV * 2 + off);
                uint32_t vh0[2] = {rh[0], rh[1]}, vh1[2] = {rh[2], rh[3]};
                mma16816(o[np * 2],     ph, vh0);
                mma16816(o[np * 2 + 1], ph, vh1);
                mma16816(o[np * 2],     pl, vh0);
                mma16816(o[np * 2 + 1], pl, vh1);
            }
        }
        __syncthreads();
    }

    float li0 = 1.0f / l0, li1 = 1.0f / l1;
    int r0 = wid * 16 + (lane >> 2);
    size_t row0 = (qrow0 + r0) * DMODEL + hoff + (lane & 3) * 2;
    size_t row1 = (qrow0 + r0 + 8) * DMODEL + hoff + (lane & 3) * 2;
#pragma unroll
    for (int nf = 0; nf < 8; nf++) {
        uint32_t hi, lo;
        split2(o[nf][0] * li0, o[nf][1] * li0, hi, lo);
        *(uint32_t*)(Oh + row0 + nf * 8) = hi;
        *(uint32_t*)(Ol + row0 + nf * 8) = lo;
        split2(o[nf][2] * li1, o[nf][3] * li1, hi, lo);
        *(uint32_t*)(Oh + row1 + nf * 8) = hi;
        *(uint32_t*)(Ol + row1 + nf * 8) = lo;
    }
}

// ---------------- orchestration -------------------------------------------
extern "C" void kernel_launch(void* const* d_in, const int* in_sizes, int n_in,
                              void* d_out, int out_size) {
    (void)in_sizes; (void)n_in; (void)out_size;
    const float* x_in    = (const float*)d_in[0];
    const int*   lengths = (const int*)d_in[1];
    const float* Wq = (const float*)d_in[2];
    const float* Wk = (const float*)d_in[3];
    const float* Wv = (const float*)d_in[4];
    const float* Wo = (const float*)d_in[5];
    const float* ln1g = (const float*)d_in[6];
    const float* ln1b = (const float*)d_in[7];
    const float* ln2g = (const float*)d_in[8];
    const float* ln2b = (const float*)d_in[9];
    const float* w1 = (const float*)d_in[10];
    const float* b1 = (const float*)d_in[11];
    const float* w2 = (const float*)d_in[12];
    const float* b2 = (const float*)d_in[13];

    float* px;
    f16 *phh, *phl, *pqkv, *pf, *pwh;
    cudaGetSymbolAddress((void**)&px, g_x);
    cudaGetSymbolAddress((void**)&phh, g_hh);
    cudaGetSymbolAddress((void**)&phl, g_hl);
    cudaGetSymbolAddress((void**)&pqkv, g_qkv);
    cudaGetSymbolAddress((void**)&pf, g_f);
    cudaGetSymbolAddress((void**)&pwh, g_wh);

    cudaFuncSetAttribute(k_fattn, cudaFuncAttributeMaxDynamicSharedMemorySize, FSMEM);
    cudaFuncSetAttribute(k_mm<2, 1, false, false, false>,
                         cudaFuncAttributeMaxDynamicSharedMemorySize, GSMEM2);
    cudaFuncSetAttribute(k_mm<2, 0, false, false, true>,
                         cudaFuncAttributeMaxDynamicSharedMemorySize, GSMEM2);
    cudaFuncSetAttribute(k_mm<1, 1, true, true, false>,
                         cudaFuncAttributeMaxDynamicSharedMemorySize, GSMEM1);
    cudaFuncSetAttribute(k_mm<1, 0, true, false, true>,
                         cudaFuncAttributeMaxDynamicSharedMemorySize, GSMEM1);

    k_wsplit<<<(WTOT / 4 + 255) / 256, 256>>>(Wq, Wk, Wv, Wo, w1, w2, pwh);
    k_pos<<<(BL * DMODEL) / 256, 256>>>(x_in, px);

    dim3 gQKV(QKVS / GBN, BL / GBM);   // (12, 64)
    dim3 gD(DMODEL / GBN, BL / GBM);   // (4, 64)
    dim3 gF(DFF / GBN, BL / GBM);      // (16, 64)
    dim3 gA(SEQL / FBR, NHEAD, BATCH);

    for (int layer = 0; layer < NLAYER; layer++) {
        const f16* qkvw = pwh + OFF_QKV + (size_t)layer * DMODEL * QKVS;
        const f16* wow  = pwh + OFF_WO + (size_t)layer * DMODEL * DMODEL;
        const f16* w1w  = pwh + OFF_W1 + (size_t)layer * DMODEL * DFF;
        const f16* w2w  = pwh + OFF_W2 + (size_t)layer * DFF * DMODEL;

        k_ln<<<BL, 128>>>(px, ln1g + (size_t)layer * DMODEL, ln1b + (size_t)layer * DMODEL,
                          phh, phl);
        // QKV: 2-term input, single fp16 output
        k_mm<2, 1, false, false, false><<<gQKV, 256, GSMEM2>>>(
            phh, phl, qkvw, nullptr, nullptr, nullptr, pqkv, nullptr,
            BL, QKVS, DMODEL);
        k_fattn<<<gA, 256, FSMEM>>>(pqkv, lengths, phh, phl);
        // WO: 2-term input (split O), fp32 output + residual
        k_mm<2, 0, false, false, true><<<gD, 256, GSMEM2>>>(
            phh, phl, wow, nullptr, px, px, nullptr, nullptr, BL, DMODEL, DMODEL);

        k_ln<<<BL, 128>>>(px, ln2g + (size_t)layer * DMODEL, ln2b + (size_t)layer * DMODEL,
                          phh, phl);
        // FFN1: 1-term (pure fp16), fp16 output, bias+relu
        k_mm<1, 1, true, true, false><<<gF, 256, GSMEM1>>>(
            phh, nullptr, w1w, b1 + (size_t)layer * DFF, nullptr,
            nullptr, pf, nullptr, BL, DFF, DMODEL);
        float* dst = (layer == NLAYER - 1) ? (float*)d_out : px;
        // FFN2: 1-term (pure fp16), fp32 output + bias + residual
        k_mm<1, 0, true, false, true><<<gD, 256, GSMEM1>>>(
            pf, nullptr, w2w, b2 + (size_t)layer * DMODEL, px,
            dst, nullptr, nullptr, BL, DMODEL, DFF);
    }
}

// round 13
// speedup vs baseline: 1.9860x; 1.1547x over previous
#include <cuda_runtime.h>
#include <cuda_fp16.h>
#include <math.h>
#include <stdint.h>

#define BATCH 8
#define SEQL 1024
#define DMODEL 512
#define NHEAD 8
#define DHEAD 64
#define DFF 2048
#define NLAYER 6
#define BL (BATCH * SEQL)   // 8192
#define QKVS 1536           // fused QKV row stride

typedef __half f16;

// ---------------- scratch (device globals: no allocs allowed) -------------
__device__ __align__(128) float g_x[BL * DMODEL];
__device__ __align__(128) f16   g_h[BL * DMODEL];     // LN out / attention O
__device__ __align__(128) f16   g_qkv[BL * QKVS];
__device__ __align__(128) f16   g_f[BL * DFF];

// weight regions (all [K][N] row-major, fp16)
#define SZ_QKV (NLAYER * DMODEL * QKVS)
#define SZ_WO  (NLAYER * DMODEL * DMODEL)
#define SZ_W1  (NLAYER * DMODEL * DFF)
#define SZ_W2  (NLAYER * DFF * DMODEL)
#define OFF_QKV 0
#define OFF_WO  (OFF_QKV + SZ_QKV)
#define OFF_W1  (OFF_WO + SZ_WO)
#define OFF_W2  (OFF_W1 + SZ_W1)
#define WTOT    (OFF_W2 + SZ_W2)
__device__ __align__(128) f16   g_wh[WTOT];

// ---------------- helpers --------------------------------------------------
__device__ __forceinline__ void cp16(uint32_t s, const void* g) {
    asm volatile("cp.async.cg.shared.global [%0], [%1], 16;\n" :: "r"(s), "l"(g));
}
__device__ __forceinline__ void cp_commit() {
    asm volatile("cp.async.commit_group;\n" ::: "memory");
}
template <int N_>
__device__ __forceinline__ void cp_wait() {
    asm volatile("cp.async.wait_group %0;\n" :: "n"(N_) : "memory");
}
__device__ __forceinline__ void ldsm4(uint32_t* r, uint32_t addr) {
    asm volatile("ldmatrix.sync.aligned.m8n8.x4.shared.b16 {%0,%1,%2,%3}, [%4];"
                 : "=r"(r[0]), "=r"(r[1]), "=r"(r[2]), "=r"(r[3]) : "r"(addr));
}
__device__ __forceinline__ void ldsm4t(uint32_t* r, uint32_t addr) {
    asm volatile("ldmatrix.sync.aligned.m8n8.x4.trans.shared.b16 {%0,%1,%2,%3}, [%4];"
                 : "=r"(r[0]), "=r"(r[1]), "=r"(r[2]), "=r"(r[3]) : "r"(addr));
}
__device__ __forceinline__ void mma16816(float* c, const uint32_t* a, const uint32_t* b) {
    asm volatile(
        "mma.sync.aligned.m16n8k16.row.col.f32.f16.f16.f32 "
        "{%0,%1,%2,%3}, {%4,%5,%6,%7}, {%8,%9}, {%0,%1,%2,%3};"
        : "+f"(c[0]), "+f"(c[1]), "+f"(c[2]), "+f"(c[3])
        : "r"(a[0]), "r"(a[1]), "r"(a[2]), "r"(a[3]), "r"(b[0]), "r"(b[1]));
}
__device__ __forceinline__ uint32_t packh(f16 a, f16 b) {
    return ((uint32_t)__half_as_ushort(b) << 16) | __half_as_ushort(a);
}
__device__ __forceinline__ void split2(float a, float b, uint32_t& hi, uint32_t& lo) {
    f16 ha = __float2half_rn(a), hb = __float2half_rn(b);
    f16 la = __float2half_rn(a - __half2float(ha));
    f16 lb = __float2half_rn(b - __half2float(hb));
    hi = packh(ha, hb);
    lo = packh(la, lb);
}

// ---------------- positional embedding + add ------------------------------
__global__ void k_pos(const float* __restrict__ xin, float* __restrict__ xout) {
    int idx = blockIdx.x * 256 + threadIdx.x;
    if (idx >= BL * DMODEL) return;
    int d = idx % DMODEL;
    int l = (idx / DMODEL) % SEQL;
    int half = DMODEL / 2;
    int i = (d < half) ? d : d - half;
    float inv = powf(10000.0f, -2.0f * (float)i / (float)DMODEL);
    float ang = (float)l * inv;
    float pe = (d < half) ? sinf(ang) : cosf(ang);
    xout[idx] = xin[idx] + pe;
}

// ---------------- combined weight convert ----------------------------------
__global__ void __launch_bounds__(256) k_wsplit(
    const float* __restrict__ Wq, const float* __restrict__ Wk,
    const float* __restrict__ Wv, const float* __restrict__ Wo,
    const float* __restrict__ w1, const float* __restrict__ w2,
    f16* __restrict__ dh) {
    uint32_t idx = (blockIdx.x * 256 + threadIdx.x) * 4;
    if (idx >= WTOT) return;
    const float* src;
    if (idx < OFF_WO) {
        uint32_t rel = idx;
        uint32_t l = rel / (DMODEL * QKVS);
        uint32_t r2 = rel - l * (DMODEL * QKVS);
        uint32_t k = r2 / QKVS;
        uint32_t j = r2 - k * QKVS;
        uint32_t sel = j >> 9;
        uint32_t jj = j & 511;
        const float* W = (sel == 0) ? Wq : (sel == 1) ? Wk : Wv;
        src = W + (size_t)l * DMODEL * DMODEL + (size_t)k * DMODEL + jj;
    } else if (idx < OFF_W1) {
        src = Wo + (idx - OFF_WO);
    } else if (idx < OFF_W2) {
        src = w1 + (idx - OFF_W1);
    } else {
        src = w2 + (idx - OFF_W2);
    }
    float4 v = *(const float4*)src;
    uint32_t h0 = packh(__float2half_rn(v.x), __float2half_rn(v.y));
    uint32_t h1 = packh(__float2half_rn(v.z), __float2half_rn(v.w));
    uint32_t* hp = (uint32_t*)(dh + idx);
    hp[0] = h0; hp[1] = h1;
}

// ---------------- layernorm -> fp16 output ---------------------------------
__global__ void __launch_bounds__(128) k_ln(const float* __restrict__ x,
                                            const float* __restrict__ g,
                                            const float* __restrict__ b,
                                            f16* __restrict__ oh) {
    int row = blockIdx.x;
    int tid = threadIdx.x;
    const float4* xr = (const float4*)(x + (size_t)row * DMODEL);
    float4 v = xr[tid];
    __shared__ float sh[4];

    float s = v.x + v.y + v.z + v.w;
    for (int o = 16; o; o >>= 1) s += __shfl_xor_sync(0xffffffffu, s, o);
    if ((tid & 31) == 0) sh[tid >> 5] = s;
    __syncthreads();
    float mean = (sh[0] + sh[1] + sh[2] + sh[3]) * (1.0f / DMODEL);
    __syncthreads();

    float dx0 = v.x - mean, dx1 = v.y - mean, dx2 = v.z - mean, dx3 = v.w - mean;
    float s2 = dx0 * dx0 + dx1 * dx1 + dx2 * dx2 + dx3 * dx3;
    for (int o = 16; o; o >>= 1) s2 += __shfl_xor_sync(0xffffffffu, s2, o);
    if ((tid & 31) == 0) sh[tid >> 5] = s2;
    __syncthreads();
    float var = (sh[0] + sh[1] + sh[2] + sh[3]) * (1.0f / DMODEL);
    float r = rsqrtf(var + 1e-3f);

    float4 gg = ((const float4*)g)[tid];
    float4 bb = ((const float4*)b)[tid];
    float o0 = dx0 * r * gg.x + bb.x;
    float o1 = dx1 * r * gg.y + bb.y;
    float o2 = dx2 * r * gg.z + bb.z;
    float o3 = dx3 * r * gg.w + bb.w;

    size_t off = (size_t)row * DMODEL + tid * 4;
    uint32_t* hp = (uint32_t*)(oh + off);
    hp[0] = packh(__float2half_rn(o0), __float2half_rn(o1));
    hp[1] = packh(__float2half_rn(o2), __float2half_rn(o3));
}

// ---------------- pure fp16 HMMA GEMM: 128x128, GBK=32, 3-stage ------------
// C = A * B ;  OUT: 0 = fp32 (Cf), 1 = fp16 (Ch)
#define GBM 128
#define GBN 128
#define GBK 32
#define NSTAGE 3
#define STAGE_ELEMS (GBM * GBK + GBK * GBN)          // 8192 f16 = 16 KB
#define SOFF_A 0
#define SOFF_B (GBM * GBK)
#define GSMEM (NSTAGE * STAGE_ELEMS * 2)             // 49152 bytes

template <int OUT, bool BIAS, bool RELU, bool RES>
__global__ void __launch_bounds__(256, 2) k_mm(
    const f16* __restrict__ A, const f16* __restrict__ B,
    const float* __restrict__ bias, const float* __restrict__ res,
    float* __restrict__ Cf, f16* __restrict__ Ch,
    int M, int N, int K) {
    extern __shared__ f16 sm[];
    int tid = threadIdx.x;
    int lane = tid & 31, wid = tid >> 5;
    int wm = wid >> 2;            // 0..1  (64 rows)
    int wn = wid & 3;             // 0..3  (32 cols)
    int m0 = blockIdx.y * GBM, n0 = blockIdx.x * GBN;
    uint32_t smbase = (uint32_t)__cvta_generic_to_shared(sm);

    float acc[4][4][4];
#pragma unroll
    for (int i = 0; i < 4; i++)
#pragma unroll
        for (int j = 0; j < 4; j++)
#pragma unroll
            for (int q = 0; q < 4; q++) acc[i][j][q] = 0.0f;

    int nk = K / GBK;

    auto load_stage = [&](int kt) {
        int buf = kt % NSTAGE;
        uint32_t sb = smbase + (uint32_t)(buf * STAGE_ELEMS) * 2;
#pragma unroll
        for (int p = 0; p < 2; p++) {       // A: 128 rows x 4 16B-chunks
            int f = p * 256 + tid;
            int r = f >> 2, c = f & 3;
            uint32_t dst = (uint32_t)(r * GBK + ((c ^ ((r >> 1) & 3)) << 3));
            size_t src = (size_t)(m0 + r) * K + kt * GBK + (c << 3);
            cp16(sb + (SOFF_A + dst) * 2, A + src);
        }
#pragma unroll
        for (int p = 0; p < 2; p++) {       // B: 32 k-rows x 16 16B-chunks
            int f = p * 256 + tid;
            int k = f >> 4, c = f & 15;
            int cs = (c & 8) | ((c ^ (k & 7)) & 7);
            uint32_t dst = (uint32_t)(k * GBN + (cs << 3));
            size_t src = (size_t)(kt * GBK + k) * N + n0 + (c << 3);
            cp16(sb + (SOFF_B + dst) * 2, B + src);
        }
        cp_commit();
    };

    load_stage(0);
    if (nk > 1) load_stage(1);

    for (int kt = 0; kt < nk; kt++) {
        if (kt == nk - 1) cp_wait<0>();
        else              cp_wait<1>();
        __syncthreads();
        if (kt + 2 < nk) load_stage(kt + 2);
        uint32_t sb = smbase + (uint32_t)((kt % NSTAGE) * STAGE_ELEMS) * 2;

#pragma unroll
        for (int ks = 0; ks < GBK / 16; ks++) {
            uint32_t aa[4][4];
#pragma unroll
            for (int mt = 0; mt < 4; mt++) {
                int row = wm * 64 + mt * 16 + (lane & 15);
                int kc = ks * 2 + (lane >> 4);
                uint32_t off = (uint32_t)(row * GBK + ((kc ^ ((row >> 1) & 3)) << 3)) * 2;
                ldsm4(aa[mt], sb + SOFF_A * 2 + off);
            }
#pragma unroll
            for (int np = 0; np < 2; np++) {
                uint32_t bb[2][2];
                {
                    int krow = ks * 16 + (lane & 15);
                    int nc = wn * 4 + np * 2 + (lane >> 4);
                    int ncs = (nc & 8) | ((nc ^ (krow & 7)) & 7);
                    uint32_t off = (uint32_t)(krow * GBN + (ncs << 3)) * 2;
                    uint32_t r[4];
                    ldsm4t(r, sb + SOFF_B * 2 + off);
                    bb[0][0] = r[0]; bb[0][1] = r[1];
                    bb[1][0] = r[2]; bb[1][1] = r[3];
                }
#pragma unroll
                for (int mt = 0; mt < 4; mt++)
#pragma unroll
                    for (int j = 0; j < 2; j++)
                        mma16816(acc[mt][np * 2 + j], aa[mt], bb[j]);
            }
        }
    }

#pragma unroll
    for (int mt = 0; mt < 4; mt++)
#pragma unroll
        for (int nt = 0; nt < 4; nt++) {
            int rbase = m0 + wm * 64 + mt * 16 + (lane >> 2);
            int cbase = n0 + wn * 32 + nt * 8 + (lane & 3) * 2;
#pragma unroll
            for (int half = 0; half < 2; half++) {
                int r = rbase + half * 8;
                float c0 = acc[mt][nt][half * 2 + 0];
                float c1 = acc[mt][nt][half * 2 + 1];
                size_t off = (size_t)r * N + cbase;
                if (BIAS) { c0 += bias[cbase]; c1 += bias[cbase + 1]; }
                if (RES)  { float2 rv = *(const float2*)(res + off); c0 += rv.x; c1 += rv.y; }
                if (RELU) { c0 = fmaxf(c0, 0.f); c1 = fmaxf(c1, 0.f); }
                if (OUT == 0) {
                    *(float2*)(Cf + off) = make_float2(c0, c1);
                } else {
                    *(uint32_t*)(Ch + off) = packh(__float2half_rn(c0), __float2half_rn(c1));
                }
            }
        }
}

// ---------------- flash attention: pure fp16 S, split-P PV -----------------
#define FBR 128
#define FBC 64
#define FQ 0
#define FKV0 (FBR * 64)
#define FKV_STRIDE (2 * FBC * 64)
#define FK 0
#define FV (FBC * 64)
#define FSMEM ((FBR * 64 + 2 * FKV_STRIDE) * 2)   // 49152 bytes

__global__ void __launch_bounds__(256, 2) k_fattn(
    const f16* __restrict__ QKV,
    const int* __restrict__ lengths,
    f16* __restrict__ O) {
    extern __shared__ f16 sm[];
    uint32_t smb = (uint32_t)__cvta_generic_to_shared(sm);
    int b = blockIdx.z, h = blockIdx.y, qt = blockIdx.x;
    int len = lengths[b];
    int tid = threadIdx.x, lane = tid & 31, wid = tid >> 5;
    size_t qrow0 = (size_t)(b * SEQL + qt * FBR);
    size_t hoff = (size_t)h * DHEAD;

    auto load_kv = [&](int kt, int stg) {
        uint32_t sb = smb + (uint32_t)(FKV0 + stg * FKV_STRIDE) * 2;
        int kb = kt * FBC;
#pragma unroll
        for (int p = 0; p < 2; p++) {
            int f = p * 256 + tid;
            int r = f >> 3, c = f & 7;
            uint32_t d = (uint32_t)((r * 64 + ((c ^ (r & 7)) << 3)) * 2);
            size_t src = (size_t)(b * SEQL + kb + r) * QKVS + hoff + (c << 3);
            cp16(sb + FK * 2 + d, QKV + src + 512);
            cp16(sb + FV * 2 + d, QKV + src + 1024);
        }
        cp_commit();
    };

    load_kv(0, 0);

#pragma unroll
    for (int p = 0; p < 4; p++) {
        int f = p * 256 + tid;
        int r = f >> 3, c = f & 7;
        uint32_t d = (uint32_t)(r * 64 + ((c ^ (r & 7)) << 3));
        size_t src = (qrow0 + r) * QKVS + hoff + (c << 3);
        *(uint4*)(sm + FQ + d) = *(const uint4*)(QKV + src);
    }
    __syncthreads();

    uint32_t qh[4][4];
#pragma unroll
    for (int ks = 0; ks < 4; ks++) {
        int row = wid * 16 + (lane & 15);
        int kc = ks * 2 + (lane >> 4);
        uint32_t off = (uint32_t)(row * 64 + ((kc ^ (row & 7)) << 3)) * 2;
        ldsm4(qh[ks], smb + FQ * 2 + off);
    }

    float o[8][4];
#pragma unroll
    for (int i = 0; i < 8; i++)
#pragma unroll
        for (int j = 0; j < 4; j++) o[i][j] = 0.0f;
    float m0 = -3.0e38f, m1 = -3.0e38f, l0 = 0.0f, l1 = 0.0f;

    int nkt = (len + FBC - 1) / FBC;
    for (int kt = 0; kt < nkt; kt++) {
        if (kt + 1 < nkt) { load_kv(kt + 1, (kt + 1) & 1); cp_wait<1>(); }
        else              { cp_wait<0>(); }
        __syncthreads();
        uint32_t sb = smb + (uint32_t)(FKV0 + (kt & 1) * FKV_STRIDE) * 2;

        float s[8][4];
#pragma unroll
        for (int i = 0; i < 8; i++)
#pragma unroll
            for (int j = 0; j < 4; j++) s[i][j] = 0.0f;

#pragma unroll
        for (int ks = 0; ks < 4; ks++) {
#pragma unroll
            for (int kg = 0; kg < 4; kg++) {
                int key = kg * 16 + (lane & 15);
                int kc = ks * 2 + (lane >> 4);
                uint32_t off = (uint32_t)(key * 64 + ((kc ^ (key & 7)) << 3)) * 2;
                uint32_t rh[4];
                ldsm4(rh, sb + FK * 2 + off);
                uint32_t bh0[2] = {rh[0], rh[2]}, bh1[2] = {rh[1], rh[3]};
                mma16816(s[kg * 2],     qh[ks], bh0);
                mma16816(s[kg * 2 + 1], qh[ks], bh1);
            }
        }

        int colbase = kt * FBC + (lane & 3) * 2;
        float mx0 = -3.0e38f, mx1 = -3.0e38f;
#pragma unroll
        for (int nf = 0; nf < 8; nf++) {
            int c = colbase + nf * 8;
            float b0 = (c     >= len) ? -1e9f : 0.0f;
            float b1 = (c + 1 >= len) ? -1e9f : 0.0f;
            s[nf][0] = s[nf][0] * 0.125f + b0;
            s[nf][1] = s[nf][1] * 0.125f + b1;
            s[nf][2] = s[nf][2] * 0.125f + b0;
            s[nf][3] = s[nf][3] * 0.125f + b1;
            mx0 = fmaxf(mx0, fmaxf(s[nf][0], s[nf][1]));
            mx1 = fmaxf(mx1, fmaxf(s[nf][2], s[nf][3]));
        }
        mx0 = fmaxf(mx0, __shfl_xor_sync(0xffffffffu, mx0, 1));
        mx0 = fmaxf(mx0, __shfl_xor_sync(0xffffffffu, mx0, 2));
        mx1 = fmaxf(mx1, __shfl_xor_sync(0xffffffffu, mx1, 1));
        mx1 = fmaxf(mx1, __shfl_xor_sync(0xffffffffu, mx1, 2));
        float mn0 = fmaxf(m0, mx0), mn1 = fmaxf(m1, mx1);
        float a0 = __expf(m0 - mn0), a1 = __expf(m1 - mn1);
        float ls0 = 0.0f, ls1 = 0.0f;
#pragma unroll
        for (int nf = 0; nf < 8; nf++) {
            s[nf][0] = __expf(s[nf][0] - mn0);
            s[nf][1] = __expf(s[nf][1] - mn0);
            s[nf][2] = __expf(s[nf][2] - mn1);
            s[nf][3] = __expf(s[nf][3] - mn1);
            ls0 += s[nf][0] + s[nf][1];
            ls1 += s[nf][2] + s[nf][3];
        }
        ls0 += __shfl_xor_sync(0xffffffffu, ls0, 1);
        ls0 += __shfl_xor_sync(0xffffffffu, ls0, 2);
        ls1 += __shfl_xor_sync(0xffffffffu, ls1, 1);
        ls1 += __shfl_xor_sync(0xffffffffu, ls1, 2);
        l0 = l0 * a0 + ls0;
        l1 = l1 * a1 + ls1;
        m0 = mn0; m1 = mn1;
#pragma unroll
        for (int nf = 0; nf < 8; nf++) {
            o[nf][0] *= a0; o[nf][1] *= a0;
            o[nf][2] *= a1; o[nf][3] *= a1;
        }

        // P V : 2-term (Ph + Pl) x Vh
#pragma unroll
        for (int kg = 0; kg < 4; kg++) {
            uint32_t ph[4], pl[4];
            split2(s[2 * kg][0], s[2 * kg][1], ph[0], pl[0]);
            split2(s[2 * kg][2], s[2 * kg][3], ph[1], pl[1]);
            split2(s[2 * kg + 1][0], s[2 * kg + 1][1], ph[2], pl[2]);
            split2(s[2 * kg + 1][2], s[2 * kg + 1][3], ph[3], pl[3]);
#pragma unroll
            for (int np = 0; np < 4; np++) {
                int krow = kg * 16 + (lane & 15);
                int nc = np * 2 + (lane >> 4);
                uint32_t off = (uint32_t)(krow * 64 + ((nc ^ (krow & 7)) << 3)) * 2;
                uint32_t rh[4];
                ldsm4t(rh, sb + FV * 2 + off);
                uint32_t vh0[2] = {rh[0], rh[1]}, vh1[2] = {rh[2], rh[3]};
                mma16816(o[np * 2],     ph, vh0);
                mma16816(o[np * 2 + 1], ph, vh1);
                mma16816(o[np * 2],     pl, vh0);
                mma16816(o[np * 2 + 1], pl, vh1);
            }
        }
        __syncthreads();
    }

    float li0 = 1.0f / l0, li1 = 1.0f / l1;
    int r0 = wid * 16 + (lane >> 2);
    size_t row0 = (qrow0 + r0) * DMODEL + hoff + (lane & 3) * 2;
    size_t row1 = (qrow0 + r0 + 8) * DMODEL + hoff + (lane & 3) * 2;
#pragma unroll
    for (int nf = 0; nf < 8; nf++) {
        *(uint32_t*)(O + row0 + nf * 8) =
            packh(__float2half_rn(o[nf][0] * li0), __float2half_rn(o[nf][1] * li0));
        *(uint32_t*)(O + row1 + nf * 8) =
            packh(__float2half_rn(o[nf][2] * li1), __float2half_rn(o[nf][3] * li1));
    }
}

// ---------------- orchestration -------------------------------------------
extern "C" void kernel_launch(void* const* d_in, const int* in_sizes, int n_in,
                              void* d_out, int out_size) {
    (void)in_sizes; (void)n_in; (void)out_size;
    const float* x_in    = (const float*)d_in[0];
    const int*   lengths = (const int*)d_in[1];
    const float* Wq = (const float*)d_in[2];
    const float* Wk = (const float*)d_in[3];
    const float* Wv = (const float*)d_in[4];
    const float* Wo = (const float*)d_in[5];
    const float* ln1g = (const float*)d_in[6];
    const float* ln1b = (const float*)d_in[7];
    const float* ln2g = (const float*)d_in[8];
    const float* ln2b = (const float*)d_in[9];
    const float* w1 = (const float*)d_in[10];
    const float* b1 = (const float*)d_in[11];
    const float* w2 = (const float*)d_in[12];
    const float* b2 = (const float*)d_in[13];

    float* px;
    f16 *ph, *pqkv, *pf, *pwh;
    cudaGetSymbolAddress((void**)&px, g_x);
    cudaGetSymbolAddress((void**)&ph, g_h);
    cudaGetSymbolAddress((void**)&pqkv, g_qkv);
    cudaGetSymbolAddress((void**)&pf, g_f);
    cudaGetSymbolAddress((void**)&pwh, g_wh);

    cudaFuncSetAttribute(k_fattn, cudaFuncAttributeMaxDynamicSharedMemorySize, FSMEM);
    cudaFuncSetAttribute(k_mm<1, false, false, false>,
                         cudaFuncAttributeMaxDynamicSharedMemorySize, GSMEM);
    cudaFuncSetAttribute(k_mm<0, false, false, true>,
                         cudaFuncAttributeMaxDynamicSharedMemorySize, GSMEM);
    cudaFuncSetAttribute(k_mm<1, true, true, false>,
                         cudaFuncAttributeMaxDynamicSharedMemorySize, GSMEM);
    cudaFuncSetAttribute(k_mm<0, true, false, true>,
                         cudaFuncAttributeMaxDynamicSharedMemorySize, GSMEM);

    k_wsplit<<<(WTOT / 4 + 255) / 256, 256>>>(Wq, Wk, Wv, Wo, w1, w2, pwh);
    k_pos<<<(BL * DMODEL) / 256, 256>>>(x_in, px);

    dim3 gQKV(QKVS / GBN, BL / GBM);   // (12, 64)
    dim3 gD(DMODEL / GBN, BL / GBM);   // (4, 64)
    dim3 gF(DFF / GBN, BL / GBM);      // (16, 64)
    dim3 gA(SEQL / FBR, NHEAD, BATCH);

    for (int layer = 0; layer < NLAYER; layer++) {
        const f16* qkvw = pwh + OFF_QKV + (size_t)layer * DMODEL * QKVS;
        const f16* wow  = pwh + OFF_WO + (size_t)layer * DMODEL * DMODEL;
        const f16* w1w  = pwh + OFF_W1 + (size_t)layer * DMODEL * DFF;
        const f16* w2w  = pwh + OFF_W2 + (size_t)layer * DFF * DMODEL;

        k_ln<<<BL, 128>>>(px, ln1g + (size_t)layer * DMODEL, ln1b + (size_t)layer * DMODEL, ph);
        k_mm<1, false, false, false><<<gQKV, 256, GSMEM>>>(
            ph, qkvw, nullptr, nullptr, nullptr, pqkv, BL, QKVS, DMODEL);
        k_fattn<<<gA, 256, FSMEM>>>(pqkv, lengths, ph);
        k_mm<0, false, false, true><<<gD, 256, GSMEM>>>(
            ph, wow, nullptr, px, px, nullptr, BL, DMODEL, DMODEL);

        k_ln<<<BL, 128>>>(px, ln2g + (size_t)layer * DMODEL, ln2b + (size_t)layer * DMODEL, ph);
        k_mm<1, true, true, false><<<gF, 256, GSMEM>>>(
            ph, w1w, b1 + (size_t)layer * DFF, nullptr, nullptr, pf, BL, DFF, DMODEL);
        float* dst = (layer == NLAYER - 1) ? (float*)d_out : px;
        k_mm<0, true, false, true><<<gD, 256, GSMEM>>>(
            pf, w2w, b2 + (size_t)layer * DMODEL, px, dst, nullptr, BL, DMODEL, DFF);
    }
}

// round 14
// speedup vs baseline: 2.2278x; 1.1217x over previous
#include <cuda_runtime.h>
#include <cuda_fp16.h>
#include <math.h>
#include <stdint.h>

#define BATCH 8
#define SEQL 1024
#define DMODEL 512
#define NHEAD 8
#define DHEAD 64
#define DFF 2048
#define NLAYER 6
#define BL (BATCH * SEQL)   // 8192
#define QKVS 1536           // fused QKV row stride

typedef __half f16;

// ---------------- scratch (device globals: no allocs allowed) -------------
__device__ __align__(128) float g_x[BL * DMODEL];
__device__ __align__(128) f16   g_h[BL * DMODEL];     // LN out / attention O
__device__ __align__(128) f16   g_qkv[BL * QKVS];
__device__ __align__(128) f16   g_f[BL * DFF];

// weight regions (all [K][N] row-major, fp16)
#define SZ_QKV (NLAYER * DMODEL * QKVS)
#define SZ_WO  (NLAYER * DMODEL * DMODEL)
#define SZ_W1  (NLAYER * DMODEL * DFF)
#define SZ_W2  (NLAYER * DFF * DMODEL)
#define OFF_QKV 0
#define OFF_WO  (OFF_QKV + SZ_QKV)
#define OFF_W1  (OFF_WO + SZ_WO)
#define OFF_W2  (OFF_W1 + SZ_W1)
#define WTOT    (OFF_W2 + SZ_W2)
__device__ __align__(128) f16   g_wh[WTOT];

// ---------------- helpers --------------------------------------------------
__device__ __forceinline__ void cp16(uint32_t s, const void* g) {
    asm volatile("cp.async.cg.shared.global [%0], [%1], 16;\n" :: "r"(s), "l"(g));
}
__device__ __forceinline__ void cp_commit() {
    asm volatile("cp.async.commit_group;\n" ::: "memory");
}
template <int N_>
__device__ __forceinline__ void cp_wait() {
    asm volatile("cp.async.wait_group %0;\n" :: "n"(N_) : "memory");
}
__device__ __forceinline__ void ldsm4(uint32_t* r, uint32_t addr) {
    asm volatile("ldmatrix.sync.aligned.m8n8.x4.shared.b16 {%0,%1,%2,%3}, [%4];"
                 : "=r"(r[0]), "=r"(r[1]), "=r"(r[2]), "=r"(r[3]) : "r"(addr));
}
__device__ __forceinline__ void ldsm4t(uint32_t* r, uint32_t addr) {
    asm volatile("ldmatrix.sync.aligned.m8n8.x4.trans.shared.b16 {%0,%1,%2,%3}, [%4];"
                 : "=r"(r[0]), "=r"(r[1]), "=r"(r[2]), "=r"(r[3]) : "r"(addr));
}
__device__ __forceinline__ void mma16816(float* c, const uint32_t* a, const uint32_t* b) {
    asm volatile(
        "mma.sync.aligned.m16n8k16.row.col.f32.f16.f16.f32 "
        "{%0,%1,%2,%3}, {%4,%5,%6,%7}, {%8,%9}, {%0,%1,%2,%3};"
        : "+f"(c[0]), "+f"(c[1]), "+f"(c[2]), "+f"(c[3])
        : "r"(a[0]), "r"(a[1]), "r"(a[2]), "r"(a[3]), "r"(b[0]), "r"(b[1]));
}
__device__ __forceinline__ uint32_t packh(f16 a, f16 b) {
    return ((uint32_t)__half_as_ushort(b) << 16) | __half_as_ushort(a);
}

// ---------------- positional embedding + add ------------------------------
__global__ void k_pos(const float* __restrict__ xin, float* __restrict__ xout) {
    int idx = blockIdx.x * 256 + threadIdx.x;
    if (idx >= BL * DMODEL) return;
    int d = idx % DMODEL;
    int l = (idx / DMODEL) % SEQL;
    int half = DMODEL / 2;
    int i = (d < half) ? d : d - half;
    float inv = powf(10000.0f, -2.0f * (float)i / (float)DMODEL);
    float ang = (float)l * inv;
    float pe = (d < half) ? sinf(ang) : cosf(ang);
    xout[idx] = xin[idx] + pe;
}

// ---------------- combined weight convert ----------------------------------
__global__ void __launch_bounds__(256) k_wsplit(
    const float* __restrict__ Wq, const float* __restrict__ Wk,
    const float* __restrict__ Wv, const float* __restrict__ Wo,
    const float* __restrict__ w1, const float* __restrict__ w2,
    f16* __restrict__ dh) {
    uint32_t idx = (blockIdx.x * 256 + threadIdx.x) * 4;
    if (idx >= WTOT) return;
    const float* src;
    if (idx < OFF_WO) {
        uint32_t rel = idx;
        uint32_t l = rel / (DMODEL * QKVS);
        uint32_t r2 = rel - l * (DMODEL * QKVS);
        uint32_t k = r2 / QKVS;
        uint32_t j = r2 - k * QKVS;
        uint32_t sel = j >> 9;
        uint32_t jj = j & 511;
        const float* W = (sel == 0) ? Wq : (sel == 1) ? Wk : Wv;
        src = W + (size_t)l * DMODEL * DMODEL + (size_t)k * DMODEL + jj;
    } else if (idx < OFF_W1) {
        src = Wo + (idx - OFF_WO);
    } else if (idx < OFF_W2) {
        src = w1 + (idx - OFF_W1);
    } else {
        src = w2 + (idx - OFF_W2);
    }
    float4 v = *(const float4*)src;
    uint32_t h0 = packh(__float2half_rn(v.x), __float2half_rn(v.y));
    uint32_t h1 = packh(__float2half_rn(v.z), __float2half_rn(v.w));
    uint32_t* hp = (uint32_t*)(dh + idx);
    hp[0] = h0; hp[1] = h1;
}

// ---------------- layernorm -> fp16 output ---------------------------------
__global__ void __launch_bounds__(128) k_ln(const float* __restrict__ x,
                                            const float* __restrict__ g,
                                            const float* __restrict__ b,
                                            f16* __restrict__ oh) {
    int row = blockIdx.x;
    int tid = threadIdx.x;
    const float4* xr = (const float4*)(x + (size_t)row * DMODEL);
    float4 v = xr[tid];
    __shared__ float sh[4];

    float s = v.x + v.y + v.z + v.w;
    for (int o = 16; o; o >>= 1) s += __shfl_xor_sync(0xffffffffu, s, o);
    if ((tid & 31) == 0) sh[tid >> 5] = s;
    __syncthreads();
    float mean = (sh[0] + sh[1] + sh[2] + sh[3]) * (1.0f / DMODEL);
    __syncthreads();

    float dx0 = v.x - mean, dx1 = v.y - mean, dx2 = v.z - mean, dx3 = v.w - mean;
    float s2 = dx0 * dx0 + dx1 * dx1 + dx2 * dx2 + dx3 * dx3;
    for (int o = 16; o; o >>= 1) s2 += __shfl_xor_sync(0xffffffffu, s2, o);
    if ((tid & 31) == 0) sh[tid >> 5] = s2;
    __syncthreads();
    float var = (sh[0] + sh[1] + sh[2] + sh[3]) * (1.0f / DMODEL);
    float r = rsqrtf(var + 1e-3f);

    float4 gg = ((const float4*)g)[tid];
    float4 bb = ((const float4*)b)[tid];
    float o0 = dx0 * r * gg.x + bb.x;
    float o1 = dx1 * r * gg.y + bb.y;
    float o2 = dx2 * r * gg.z + bb.z;
    float o3 = dx3 * r * gg.w + bb.w;

    size_t off = (size_t)row * DMODEL + tid * 4;
    uint32_t* hp = (uint32_t*)(oh + off);
    hp[0] = packh(__float2half_rn(o0), __float2half_rn(o1));
    hp[1] = packh(__float2half_rn(o2), __float2half_rn(o3));
}

// ---------------- pure fp16 HMMA GEMM: 128x128, GBK=64, 3-stage ------------
// C = A * B ;  OUT: 0 = fp32 (Cf), 1 = fp16 (Ch)
#define GBM 128
#define GBN 128
#define GBK 64
#define NSTAGE 3
#define STAGE_ELEMS (GBM * GBK + GBK * GBN)          // 16384 f16 = 32 KB
#define SOFF_A 0
#define SOFF_B (GBM * GBK)
#define GSMEM (NSTAGE * STAGE_ELEMS * 2)             // 196608 bytes

template <int OUT, bool BIAS, bool RELU, bool RES>
__global__ void __launch_bounds__(256, 2) k_mm(
    const f16* __restrict__ A, const f16* __restrict__ B,
    const float* __restrict__ bias, const float* __restrict__ res,
    float* __restrict__ Cf, f16* __restrict__ Ch,
    int M, int N, int K) {
    extern __shared__ f16 sm[];
    int tid = threadIdx.x;
    int lane = tid & 31, wid = tid >> 5;
    int wm = wid >> 2;            // 0..1  (64 rows)
    int wn = wid & 3;             // 0..3  (32 cols)
    int m0 = blockIdx.y * GBM, n0 = blockIdx.x * GBN;
    uint32_t smbase = (uint32_t)__cvta_generic_to_shared(sm);

    float acc[4][4][4];
#pragma unroll
    for (int i = 0; i < 4; i++)
#pragma unroll
        for (int j = 0; j < 4; j++)
#pragma unroll
            for (int q = 0; q < 4; q++) acc[i][j][q] = 0.0f;

    int nk = K / GBK;

    auto load_stage = [&](int kt) {
        int buf = kt % NSTAGE;
        uint32_t sb = smbase + (uint32_t)(buf * STAGE_ELEMS) * 2;
#pragma unroll
        for (int p = 0; p < 4; p++) {       // A: 128 rows x 8 16B-chunks
            int f = p * 256 + tid;
            int r = f >> 3, c = f & 7;
            uint32_t dst = (uint32_t)(r * GBK + ((c ^ (r & 7)) << 3));
            size_t src = (size_t)(m0 + r) * K + kt * GBK + (c << 3);
            cp16(sb + (SOFF_A + dst) * 2, A + src);
        }
#pragma unroll
        for (int p = 0; p < 4; p++) {       // B: 64 k-rows x 16 16B-chunks
            int f = p * 256 + tid;
            int k = f >> 4, c = f & 15;
            int cs = (c & 8) | ((c ^ (k & 7)) & 7);
            uint32_t dst = (uint32_t)(k * GBN + (cs << 3));
            size_t src = (size_t)(kt * GBK + k) * N + n0 + (c << 3);
            cp16(sb + (SOFF_B + dst) * 2, B + src);
        }
        cp_commit();
    };

    load_stage(0);
    if (nk > 1) load_stage(1);

    for (int kt = 0; kt < nk; kt++) {
        if (kt == nk - 1) cp_wait<0>();
        else              cp_wait<1>();
        __syncthreads();
        if (kt + 2 < nk) load_stage(kt + 2);
        uint32_t sb = smbase + (uint32_t)((kt % NSTAGE) * STAGE_ELEMS) * 2;

#pragma unroll
        for (int ks = 0; ks < GBK / 16; ks++) {
            uint32_t aa[4][4];
#pragma unroll
            for (int mt = 0; mt < 4; mt++) {
                int row = wm * 64 + mt * 16 + (lane & 15);
                int kc = ks * 2 + (lane >> 4);           // 0..7
                uint32_t off = (uint32_t)(row * GBK + ((kc ^ (row & 7)) << 3)) * 2;
                ldsm4(aa[mt], sb + SOFF_A * 2 + off);
            }
#pragma unroll
            for (int np = 0; np < 2; np++) {
                uint32_t bb[2][2];
                {
                    int krow = ks * 16 + (lane & 15);
                    int nc = wn * 4 + np * 2 + (lane >> 4);
                    int ncs = (nc & 8) | ((nc ^ (krow & 7)) & 7);
                    uint32_t off = (uint32_t)(krow * GBN + (ncs << 3)) * 2;
                    uint32_t r[4];
                    ldsm4t(r, sb + SOFF_B * 2 + off);
                    bb[0][0] = r[0]; bb[0][1] = r[1];
                    bb[1][0] = r[2]; bb[1][1] = r[3];
                }
#pragma unroll
                for (int mt = 0; mt < 4; mt++)
#pragma unroll
                    for (int j = 0; j < 2; j++)
                        mma16816(acc[mt][np * 2 + j], aa[mt], bb[j]);
            }
        }
    }

#pragma unroll
    for (int mt = 0; mt < 4; mt++)
#pragma unroll
        for (int nt = 0; nt < 4; nt++) {
            int rbase = m0 + wm * 64 + mt * 16 + (lane >> 2);
            int cbase = n0 + wn * 32 + nt * 8 + (lane & 3) * 2;
#pragma unroll
            for (int half = 0; half < 2; half++) {
                int r = rbase + half * 8;
                float c0 = acc[mt][nt][half * 2 + 0];
                float c1 = acc[mt][nt][half * 2 + 1];
                size_t off = (size_t)r * N + cbase;
                if (BIAS) { c0 += bias[cbase]; c1 += bias[cbase + 1]; }
                if (RES)  { float2 rv = *(const float2*)(res + off); c0 += rv.x; c1 += rv.y; }
                if (RELU) { c0 = fmaxf(c0, 0.f); c1 = fmaxf(c1, 0.f); }
                if (OUT == 0) {
                    *(float2*)(Cf + off) = make_float2(c0, c1);
                } else {
                    *(uint32_t*)(Ch + off) = packh(__float2half_rn(c0), __float2half_rn(c1));
                }
            }
        }
}

// ---------------- flash attention: pure fp16 S and PV ----------------------
// Q pre-scaled by 0.125 (exact in fp16). S = Qs Kh^T; O = P16 Vh.
#define FBR 128
#define FBC 64
#define FQ 0
#define FKV0 (FBR * 64)
#define FKV_STRIDE (2 * FBC * 64)
#define FK 0
#define FV (FBC * 64)
#define FSMEM ((FBR * 64 + 2 * FKV_STRIDE) * 2)   // 49152 bytes

__global__ void __launch_bounds__(256, 2) k_fattn(
    const f16* __restrict__ QKV,
    const int* __restrict__ lengths,
    f16* __restrict__ O) {
    extern __shared__ f16 sm[];
    uint32_t smb = (uint32_t)__cvta_generic_to_shared(sm);
    int b = blockIdx.z, h = blockIdx.y, qt = blockIdx.x;
    int len = lengths[b];
    int tid = threadIdx.x, lane = tid & 31, wid = tid >> 5;
    size_t qrow0 = (size_t)(b * SEQL + qt * FBR);
    size_t hoff = (size_t)h * DHEAD;

    auto load_kv = [&](int kt, int stg) {
        uint32_t sb = smb + (uint32_t)(FKV0 + stg * FKV_STRIDE) * 2;
        int kb = kt * FBC;
#pragma unroll
        for (int p = 0; p < 2; p++) {
            int f = p * 256 + tid;
            int r = f >> 3, c = f & 7;
            uint32_t d = (uint32_t)((r * 64 + ((c ^ (r & 7)) << 3)) * 2);
            size_t src = (size_t)(b * SEQL + kb + r) * QKVS + hoff + (c << 3);
            cp16(sb + FK * 2 + d, QKV + src + 512);
            cp16(sb + FV * 2 + d, QKV + src + 1024);
        }
        cp_commit();
    };

    load_kv(0, 0);

    // Q -> smem, pre-scaled by 1/8 (exact power-of-two scale in fp16)
    {
        __half2 sc = __half2half2(__float2half_rn(0.125f));
#pragma unroll
        for (int p = 0; p < 4; p++) {
            int f = p * 256 + tid;
            int r = f >> 3, c = f & 7;
            uint32_t d = (uint32_t)(r * 64 + ((c ^ (r & 7)) << 3));
            size_t src = (qrow0 + r) * QKVS + hoff + (c << 3);
            uint4 v = *(const uint4*)(QKV + src);
            __half2* hv = (__half2*)&v;
#pragma unroll
            for (int j = 0; j < 4; j++) hv[j] = __hmul2(hv[j], sc);
            *(uint4*)(sm + FQ + d) = v;
        }
    }
    __syncthreads();

    uint32_t qh[4][4];
#pragma unroll
    for (int ks = 0; ks < 4; ks++) {
        int row = wid * 16 + (lane & 15);
        int kc = ks * 2 + (lane >> 4);
        uint32_t off = (uint32_t)(row * 64 + ((kc ^ (row & 7)) << 3)) * 2;
        ldsm4(qh[ks], smb + FQ * 2 + off);
    }

    float o[8][4];
#pragma unroll
    for (int i = 0; i < 8; i++)
#pragma unroll
        for (int j = 0; j < 4; j++) o[i][j] = 0.0f;
    float m0 = -3.0e38f, m1 = -3.0e38f, l0 = 0.0f, l1 = 0.0f;

    int nkt = (len + FBC - 1) / FBC;
    for (int kt = 0; kt < nkt; kt++) {
        if (kt + 1 < nkt) { load_kv(kt + 1, (kt + 1) & 1); cp_wait<1>(); }
        else              { cp_wait<0>(); }
        __syncthreads();
        uint32_t sb = smb + (uint32_t)(FKV0 + (kt & 1) * FKV_STRIDE) * 2;

        float s[8][4];
#pragma unroll
        for (int i = 0; i < 8; i++)
#pragma unroll
            for (int j = 0; j < 4; j++) s[i][j] = 0.0f;

        // S = Qs Kh^T
#pragma unroll
        for (int ks = 0; ks < 4; ks++) {
#pragma unroll
            for (int kg = 0; kg < 4; kg++) {
                int key = kg * 16 + (lane & 15);
                int kc = ks * 2 + (lane >> 4);
                uint32_t off = (uint32_t)(key * 64 + ((kc ^ (key & 7)) << 3)) * 2;
                uint32_t rh[4];
                ldsm4(rh, sb + FK * 2 + off);
                uint32_t bh0[2] = {rh[0], rh[2]}, bh1[2] = {rh[1], rh[3]};
                mma16816(s[kg * 2],     qh[ks], bh0);
                mma16816(s[kg * 2 + 1], qh[ks], bh1);
            }
        }

        int colbase = kt * FBC + (lane & 3) * 2;
        float mx0 = -3.0e38f, mx1 = -3.0e38f;
#pragma unroll
        for (int nf = 0; nf < 8; nf++) {
            int c = colbase + nf * 8;
            float b0 = (c     >= len) ? -1e9f : 0.0f;
            float b1 = (c + 1 >= len) ? -1e9f : 0.0f;
            s[nf][0] += b0;
            s[nf][1] += b1;
            s[nf][2] += b0;
            s[nf][3] += b1;
            mx0 = fmaxf(mx0, fmaxf(s[nf][0], s[nf][1]));
            mx1 = fmaxf(mx1, fmaxf(s[nf][2], s[nf][3]));
        }
        mx0 = fmaxf(mx0, __shfl_xor_sync(0xffffffffu, mx0, 1));
        mx0 = fmaxf(mx0, __shfl_xor_sync(0xffffffffu, mx0, 2));
        mx1 = fmaxf(mx1, __shfl_xor_sync(0xffffffffu, mx1, 1));
        mx1 = fmaxf(mx1, __shfl_xor_sync(0xffffffffu, mx1, 2));
        float mn0 = fmaxf(m0, mx0), mn1 = fmaxf(m1, mx1);
        float a0 = __expf(m0 - mn0), a1 = __expf(m1 - mn1);
        float ls0 = 0.0f, ls1 = 0.0f;
#pragma unroll
        for (int nf = 0; nf < 8; nf++) {
            s[nf][0] = __expf(s[nf][0] - mn0);
            s[nf][1] = __expf(s[nf][1] - mn0);
            s[nf][2] = __expf(s[nf][2] - mn1);
            s[nf][3] = __expf(s[nf][3] - mn1);
            ls0 += s[nf][0] + s[nf][1];
            ls1 += s[nf][2] + s[nf][3];
        }
        ls0 += __shfl_xor_sync(0xffffffffu, ls0, 1);
        ls0 += __shfl_xor_sync(0xffffffffu, ls0, 2);
        ls1 += __shfl_xor_sync(0xffffffffu, ls1, 1);
        ls1 += __shfl_xor_sync(0xffffffffu, ls1, 2);
        l0 = l0 * a0 + ls0;
        l1 = l1 * a1 + ls1;
        m0 = mn0; m1 = mn1;
#pragma unroll
        for (int nf = 0; nf < 8; nf++) {
            o[nf][0] *= a0; o[nf][1] *= a0;
            o[nf][2] *= a1; o[nf][3] *= a1;
        }

        // O += P16 Vh  (pure fp16 P)
#pragma unroll
        for (int kg = 0; kg < 4; kg++) {
            uint32_t pp[4];
            pp[0] = packh(__float2half_rn(s[2 * kg][0]), __float2half_rn(s[2 * kg][1]));
            pp[1] = packh(__float2half_rn(s[2 * kg][2]), __float2half_rn(s[2 * kg][3]));
            pp[2] = packh(__float2half_rn(s[2 * kg + 1][0]), __float2half_rn(s[2 * kg + 1][1]));
            pp[3] = packh(__float2half_rn(s[2 * kg + 1][2]), __float2half_rn(s[2 * kg + 1][3]));
#pragma unroll
            for (int np = 0; np < 4; np++) {
                int krow = kg * 16 + (lane & 15);
                int nc = np * 2 + (lane >> 4);
                uint32_t off = (uint32_t)(krow * 64 + ((nc ^ (krow & 7)) << 3)) * 2;
                uint32_t rh[4];
                ldsm4t(rh, sb + FV * 2 + off);
                uint32_t vh0[2] = {rh[0], rh[1]}, vh1[2] = {rh[2], rh[3]};
                mma16816(o[np * 2],     pp, vh0);
                mma16816(o[np * 2 + 1], pp, vh1);
            }
        }
        __syncthreads();
    }

    float li0 = 1.0f / l0, li1 = 1.0f / l1;
    int r0 = wid * 16 + (lane >> 2);
    size_t row0 = (qrow0 + r0) * DMODEL + hoff + (lane & 3) * 2;
    size_t row1 = (qrow0 + r0 + 8) * DMODEL + hoff + (lane & 3) * 2;
#pragma unroll
    for (int nf = 0; nf < 8; nf++) {
        *(uint32_t*)(O + row0 + nf * 8) =
            packh(__float2half_rn(o[nf][0] * li0), __float2half_rn(o[nf][1] * li0));
        *(uint32_t*)(O + row1 + nf * 8) =
            packh(__float2half_rn(o[nf][2] * li1), __float2half_rn(o[nf][3] * li1));
    }
}

// ---------------- orchestration -------------------------------------------
extern "C" void kernel_launch(void* const* d_in, const int* in_sizes, int n_in,
                              void* d_out, int out_size) {
    (void)in_sizes; (void)n_in; (void)out_size;
    const float* x_in    = (const float*)d_in[0];
    const int*   lengths = (const int*)d_in[1];
    const float* Wq = (const float*)d_in[2];
    const float* Wk = (const float*)d_in[3];
    const float* Wv = (const float*)d_in[4];
    const float* Wo = (const float*)d_in[5];
    const float* ln1g = (const float*)d_in[6];
    const float* ln1b = (const float*)d_in[7];
    const float* ln2g = (const float*)d_in[8];
    const float* ln2b = (const float*)d_in[9];
    const float* w1 = (const float*)d_in[10];
    const float* b1 = (const float*)d_in[11];
    const float* w2 = (const float*)d_in[12];
    const float* b2 = (const float*)d_in[13];

    float* px;
    f16 *ph, *pqkv, *pf, *pwh;
    cudaGetSymbolAddress((void**)&px, g_x);
    cudaGetSymbolAddress((void**)&ph, g_h);
    cudaGetSymbolAddress((void**)&pqkv, g_qkv);
    cudaGetSymbolAddress((void**)&pf, g_f);
    cudaGetSymbolAddress((void**)&pwh, g_wh);

    cudaFuncSetAttribute(k_fattn, cudaFuncAttributeMaxDynamicSharedMemorySize, FSMEM);
    cudaFuncSetAttribute(k_mm<1, false, false, false>,
                         cudaFuncAttributeMaxDynamicSharedMemorySize, GSMEM);
    cudaFuncSetAttribute(k_mm<0, false, false, true>,
                         cudaFuncAttributeMaxDynamicSharedMemorySize, GSMEM);
    cudaFuncSetAttribute(k_mm<1, true, true, false>,
                         cudaFuncAttributeMaxDynamicSharedMemorySize, GSMEM);
    cudaFuncSetAttribute(k_mm<0, true, false, true>,
                         cudaFuncAttributeMaxDynamicSharedMemorySize, GSMEM);

    k_wsplit<<<(WTOT / 4 + 255) / 256, 256>>>(Wq, Wk, Wv, Wo, w1, w2, pwh);
    k_pos<<<(BL * DMODEL) / 256, 256>>>(x_in, px);

    dim3 gQKV(QKVS / GBN, BL / GBM);   // (12, 64)
    dim3 gD(DMODEL / GBN, BL / GBM);   // (4, 64)
    dim3 gF(DFF / GBN, BL / GBM);      // (16, 64)
    dim3 gA(SEQL / FBR, NHEAD, BATCH);

    for (int layer = 0; layer < NLAYER; layer++) {
        const f16* qkvw = pwh + OFF_QKV + (size_t)layer * DMODEL * QKVS;
        const f16* wow  = pwh + OFF_WO + (size_t)layer * DMODEL * DMODEL;
        const f16* w1w  = pwh + OFF_W1 + (size_t)layer * DMODEL * DFF;
        const f16* w2w  = pwh + OFF_W2 + (size_t)layer * DFF * DMODEL;

        k_ln<<<BL, 128>>>(px, ln1g + (size_t)layer * DMODEL, ln1b + (size_t)layer * DMODEL, ph);
        k_mm<1, false, false, false><<<gQKV, 256, GSMEM>>>(
            ph, qkvw, nullptr, nullptr, nullptr, pqkv, BL, QKVS, DMODEL);
        k_fattn<<<gA, 256, FSMEM>>>(pqkv, lengths, ph);
        k_mm<0, false, false, true><<<gD, 256, GSMEM>>>(
            ph, wow, nullptr, px, px, nullptr, BL, DMODEL, DMODEL);

        k_ln<<<BL, 128>>>(px, ln2g + (size_t)layer * DMODEL, ln2b + (size_t)layer * DMODEL, ph);
        k_mm<1, true, true, false><<<gF, 256, GSMEM>>>(
            ph, w1w, b1 + (size_t)layer * DFF, nullptr, nullptr, pf, BL, DFF, DMODEL);
        float* dst = (layer == NLAYER - 1) ? (float*)d_out : px;
        k_mm<0, true, false, true><<<gD, 256, GSMEM>>>(
            pf, w2w, b2 + (size_t)layer * DMODEL, px, dst, nullptr, BL, DMODEL, DFF);
    }
}

// round 15
// speedup vs baseline: 2.2454x; 1.0079x over previous
#include <cuda_runtime.h>
#include <cuda_fp16.h>
#include <math.h>
#include <stdint.h>

#define BATCH 8
#define SEQL 1024
#define DMODEL 512
#define NHEAD 8
#define DHEAD 64
#define DFF 2048
#define NLAYER 6
#define BL (BATCH * SEQL)   // 8192
#define QKVS 1536           // fused QKV row stride

typedef __half f16;

// ---------------- scratch (device globals: no allocs allowed) -------------
__device__ __align__(128) float g_x[BL * DMODEL];
__device__ __align__(128) f16   g_h[BL * DMODEL];     // LN out / attention O
__device__ __align__(128) f16   g_qkv[BL * QKVS];
__device__ __align__(128) f16   g_f[BL * DFF];

// weight regions (all [K][N] row-major, fp16)
#define SZ_QKV (NLAYER * DMODEL * QKVS)
#define SZ_WO  (NLAYER * DMODEL * DMODEL)
#define SZ_W1  (NLAYER * DMODEL * DFF)
#define SZ_W2  (NLAYER * DFF * DMODEL)
#define OFF_QKV 0
#define OFF_WO  (OFF_QKV + SZ_QKV)
#define OFF_W1  (OFF_WO + SZ_WO)
#define OFF_W2  (OFF_W1 + SZ_W1)
#define WTOT    (OFF_W2 + SZ_W2)
__device__ __align__(128) f16   g_wh[WTOT];

// ---------------- helpers --------------------------------------------------
__device__ __forceinline__ void cp16(uint32_t s, const void* g) {
    asm volatile("cp.async.cg.shared.global [%0], [%1], 16;\n" :: "r"(s), "l"(g));
}
__device__ __forceinline__ void cp_commit() {
    asm volatile("cp.async.commit_group;\n" ::: "memory");
}
template <int N_>
__device__ __forceinline__ void cp_wait() {
    asm volatile("cp.async.wait_group %0;\n" :: "n"(N_) : "memory");
}
__device__ __forceinline__ void ldsm4(uint32_t* r, uint32_t addr) {
    asm volatile("ldmatrix.sync.aligned.m8n8.x4.shared.b16 {%0,%1,%2,%3}, [%4];"
                 : "=r"(r[0]), "=r"(r[1]), "=r"(r[2]), "=r"(r[3]) : "r"(addr));
}
__device__ __forceinline__ void ldsm4t(uint32_t* r, uint32_t addr) {
    asm volatile("ldmatrix.sync.aligned.m8n8.x4.trans.shared.b16 {%0,%1,%2,%3}, [%4];"
                 : "=r"(r[0]), "=r"(r[1]), "=r"(r[2]), "=r"(r[3]) : "r"(addr));
}
__device__ __forceinline__ void mma16816(float* c, const uint32_t* a, const uint32_t* b) {
    asm volatile(
        "mma.sync.aligned.m16n8k16.row.col.f32.f16.f16.f32 "
        "{%0,%1,%2,%3}, {%4,%5,%6,%7}, {%8,%9}, {%0,%1,%2,%3};"
        : "+f"(c[0]), "+f"(c[1]), "+f"(c[2]), "+f"(c[3])
        : "r"(a[0]), "r"(a[1]), "r"(a[2]), "r"(a[3]), "r"(b[0]), "r"(b[1]));
}
__device__ __forceinline__ uint32_t packh(f16 a, f16 b) {
    return ((uint32_t)__half_as_ushort(b) << 16) | __half_as_ushort(a);
}

// ---------------- init: weight convert + positional embedding --------------
#define NB_W ((WTOT / 4 + 255) / 256)
#define NB_P ((BL * DMODEL) / 256)
__global__ void __launch_bounds__(256) k_init(
    const float* __restrict__ Wq, const float* __restrict__ Wk,
    const float* __restrict__ Wv, const float* __restrict__ Wo,
    const float* __restrict__ w1, const float* __restrict__ w2,
    f16* __restrict__ dh,
    const float* __restrict__ xin, float* __restrict__ xout) {
    if (blockIdx.x < NB_W) {
        uint32_t idx = (blockIdx.x * 256 + threadIdx.x) * 4;
        if (idx >= WTOT) return;
        const float* src;
        if (idx < OFF_WO) {
            uint32_t rel = idx;
            uint32_t l = rel / (DMODEL * QKVS);
            uint32_t r2 = rel - l * (DMODEL * QKVS);
            uint32_t k = r2 / QKVS;
            uint32_t j = r2 - k * QKVS;
            uint32_t sel = j >> 9;
            uint32_t jj = j & 511;
            const float* W = (sel == 0) ? Wq : (sel == 1) ? Wk : Wv;
            src = W + (size_t)l * DMODEL * DMODEL + (size_t)k * DMODEL + jj;
        } else if (idx < OFF_W1) {
            src = Wo + (idx - OFF_WO);
        } else if (idx < OFF_W2) {
            src = w1 + (idx - OFF_W1);
        } else {
            src = w2 + (idx - OFF_W2);
        }
        float4 v = *(const float4*)src;
        uint32_t* hp = (uint32_t*)(dh + idx);
        hp[0] = packh(__float2half_rn(v.x), __float2half_rn(v.y));
        hp[1] = packh(__float2half_rn(v.z), __float2half_rn(v.w));
    } else {
        int idx = (blockIdx.x - NB_W) * 256 + threadIdx.x;
        if (idx >= BL * DMODEL) return;
        int d = idx % DMODEL;
        int l = (idx / DMODEL) % SEQL;
        int half = DMODEL / 2;
        int i = (d < half) ? d : d - half;
        float inv = powf(10000.0f, -2.0f * (float)i / (float)DMODEL);
        float ang = (float)l * inv;
        float pe = (d < half) ? sinf(ang) : cosf(ang);
        xout[idx] = xin[idx] + pe;
    }
}

// ---------------- layernorm -> fp16 output ---------------------------------
__global__ void __launch_bounds__(128) k_ln(const float* __restrict__ x,
                                            const float* __restrict__ g,
                                            const float* __restrict__ b,
                                            f16* __restrict__ oh) {
    int row = blockIdx.x;
    int tid = threadIdx.x;
    const float4* xr = (const float4*)(x + (size_t)row * DMODEL);
    float4 v = xr[tid];
    __shared__ float sh[4];

    float s = v.x + v.y + v.z + v.w;
    for (int o = 16; o; o >>= 1) s += __shfl_xor_sync(0xffffffffu, s, o);
    if ((tid & 31) == 0) sh[tid >> 5] = s;
    __syncthreads();
    float mean = (sh[0] + sh[1] + sh[2] + sh[3]) * (1.0f / DMODEL);
    __syncthreads();

    float dx0 = v.x - mean, dx1 = v.y - mean, dx2 = v.z - mean, dx3 = v.w - mean;
    float s2 = dx0 * dx0 + dx1 * dx1 + dx2 * dx2 + dx3 * dx3;
    for (int o = 16; o; o >>= 1) s2 += __shfl_xor_sync(0xffffffffu, s2, o);
    if ((tid & 31) == 0) sh[tid >> 5] = s2;
    __syncthreads();
    float var = (sh[0] + sh[1] + sh[2] + sh[3]) * (1.0f / DMODEL);
    float r = rsqrtf(var + 1e-3f);

    float4 gg = ((const float4*)g)[tid];
    float4 bb = ((const float4*)b)[tid];
    float o0 = dx0 * r * gg.x + bb.x;
    float o1 = dx1 * r * gg.y + bb.y;
    float o2 = dx2 * r * gg.z + bb.z;
    float o3 = dx3 * r * gg.w + bb.w;

    size_t off = (size_t)row * DMODEL + tid * 4;
    uint32_t* hp = (uint32_t*)(oh + off);
    hp[0] = packh(__float2half_rn(o0), __float2half_rn(o1));
    hp[1] = packh(__float2half_rn(o2), __float2half_rn(o3));
}

// ---------------- pure fp16 HMMA GEMM: 128x128, GBK=64, 3-stage ------------
// C = A * B ;  OUT: 0 = fp32 (Cf), 1 = fp16 (Ch)
#define GBM 128
#define GBN 128
#define GBK 64
#define NSTAGE 3
#define STAGE_ELEMS (GBM * GBK + GBK * GBN)          // 16384 f16 = 32 KB
#define SOFF_A 0
#define SOFF_B (GBM * GBK)
#define GSMEM (NSTAGE * STAGE_ELEMS * 2)             // 98304 bytes

template <int OUT, bool BIAS, bool RELU, bool RES>
__global__ void __launch_bounds__(256, 2) k_mm(
    const f16* __restrict__ A, const f16* __restrict__ B,
    const float* __restrict__ bias, const float* __restrict__ res,
    float* __restrict__ Cf, f16* __restrict__ Ch,
    int M, int N, int K) {
    extern __shared__ f16 sm[];
    int tid = threadIdx.x;
    int lane = tid & 31, wid = tid >> 5;
    int wm = wid >> 2;            // 0..1  (64 rows)
    int wn = wid & 3;             // 0..3  (32 cols)
    int m0 = blockIdx.y * GBM, n0 = blockIdx.x * GBN;
    uint32_t smbase = (uint32_t)__cvta_generic_to_shared(sm);

    float acc[4][4][4];
#pragma unroll
    for (int i = 0; i < 4; i++)
#pragma unroll
        for (int j = 0; j < 4; j++)
#pragma unroll
            for (int q = 0; q < 4; q++) acc[i][j][q] = 0.0f;

    int nk = K / GBK;

    auto load_stage = [&](int kt) {
        int buf = kt % NSTAGE;
        uint32_t sb = smbase + (uint32_t)(buf * STAGE_ELEMS) * 2;
#pragma unroll
        for (int p = 0; p < 4; p++) {       // A: 128 rows x 8 16B-chunks
            int f = p * 256 + tid;
            int r = f >> 3, c = f & 7;
            uint32_t dst = (uint32_t)(r * GBK + ((c ^ (r & 7)) << 3));
            size_t src = (size_t)(m0 + r) * K + kt * GBK + (c << 3);
            cp16(sb + (SOFF_A + dst) * 2, A + src);
        }
#pragma unroll
        for (int p = 0; p < 4; p++) {       // B: 64 k-rows x 16 16B-chunks
            int f = p * 256 + tid;
            int k = f >> 4, c = f & 15;
            int cs = (c & 8) | ((c ^ (k & 7)) & 7);
            uint32_t dst = (uint32_t)(k * GBN + (cs << 3));
            size_t src = (size_t)(kt * GBK + k) * N + n0 + (c << 3);
            cp16(sb + (SOFF_B + dst) * 2, B + src);
        }
        cp_commit();
    };

    load_stage(0);
    if (nk > 1) load_stage(1);

    for (int kt = 0; kt < nk; kt++) {
        if (kt == nk - 1) cp_wait<0>();
        else              cp_wait<1>();
        __syncthreads();
        if (kt + 2 < nk) load_stage(kt + 2);
        uint32_t sb = smbase + (uint32_t)((kt % NSTAGE) * STAGE_ELEMS) * 2;

#pragma unroll
        for (int ks = 0; ks < GBK / 16; ks++) {
            // hoist ALL frag loads (A x4 + B both np) before the MMA block
            uint32_t aa[4][4];
#pragma unroll
            for (int mt = 0; mt < 4; mt++) {
                int row = wm * 64 + mt * 16 + (lane & 15);
                int kc = ks * 2 + (lane >> 4);           // 0..7
                uint32_t off = (uint32_t)(row * GBK + ((kc ^ (row & 7)) << 3)) * 2;
                ldsm4(aa[mt], sb + SOFF_A * 2 + off);
            }
            uint32_t bb[2][2][2];
#pragma unroll
            for (int np = 0; np < 2; np++) {
                int krow = ks * 16 + (lane & 15);
                int nc = wn * 4 + np * 2 + (lane >> 4);
                int ncs = (nc & 8) | ((nc ^ (krow & 7)) & 7);
                uint32_t off = (uint32_t)(krow * GBN + (ncs << 3)) * 2;
                uint32_t r[4];
                ldsm4t(r, sb + SOFF_B * 2 + off);
                bb[np][0][0] = r[0]; bb[np][0][1] = r[1];
                bb[np][1][0] = r[2]; bb[np][1][1] = r[3];
            }
#pragma unroll
            for (int np = 0; np < 2; np++)
#pragma unroll
                for (int mt = 0; mt < 4; mt++)
#pragma unroll
                    for (int j = 0; j < 2; j++)
                        mma16816(acc[mt][np * 2 + j], aa[mt], bb[np][j]);
        }
    }

#pragma unroll
    for (int mt = 0; mt < 4; mt++)
#pragma unroll
        for (int nt = 0; nt < 4; nt++) {
            int rbase = m0 + wm * 64 + mt * 16 + (lane >> 2);
            int cbase = n0 + wn * 32 + nt * 8 + (lane & 3) * 2;
#pragma unroll
            for (int half = 0; half < 2; half++) {
                int r = rbase + half * 8;
                float c0 = acc[mt][nt][half * 2 + 0];
                float c1 = acc[mt][nt][half * 2 + 1];
                size_t off = (size_t)r * N + cbase;
                if (BIAS) { c0 += bias[cbase]; c1 += bias[cbase + 1]; }
                if (RES)  { float2 rv = *(const float2*)(res + off); c0 += rv.x; c1 += rv.y; }
                if (RELU) { c0 = fmaxf(c0, 0.f); c1 = fmaxf(c1, 0.f); }
                if (OUT == 0) {
                    *(float2*)(Cf + off) = make_float2(c0, c1);
                } else {
                    *(uint32_t*)(Ch + off) = packh(__float2half_rn(c0), __float2half_rn(c1));
                }
            }
        }
}

// ---------------- flash attention: fp16 S/PV, 4-buffer ring ----------------
// Q pre-scaled by 0.125. One barrier per k-tile.
#define FBR 128
#define FBC 64
#define FQ 0
#define FKV0 (FBR * 64)
#define FNBUF 4
#define FBUF_STRIDE (2 * FBC * 64)     // K + V per buffer (8192 elems)
#define FK 0
#define FV (FBC * 64)
#define FSMEM ((FBR * 64 + FNBUF * FBUF_STRIDE) * 2)   // 81920 bytes

__global__ void __launch_bounds__(256, 2) k_fattn(
    const f16* __restrict__ QKV,
    const int* __restrict__ lengths,
    f16* __restrict__ O) {
    extern __shared__ f16 sm[];
    uint32_t smb = (uint32_t)__cvta_generic_to_shared(sm);
    int b = blockIdx.z, h = blockIdx.y, qt = blockIdx.x;
    int len = lengths[b];
    int tid = threadIdx.x, lane = tid & 31, wid = tid >> 5;
    size_t qrow0 = (size_t)(b * SEQL + qt * FBR);
    size_t hoff = (size_t)h * DHEAD;

    auto load_kv = [&](int kt) {
        uint32_t sb = smb + (uint32_t)(FKV0 + (kt & (FNBUF - 1)) * FBUF_STRIDE) * 2;
        int kb = kt * FBC;
#pragma unroll
        for (int p = 0; p < 2; p++) {
            int f = p * 256 + tid;
            int r = f >> 3, c = f & 7;
            uint32_t d = (uint32_t)((r * 64 + ((c ^ (r & 7)) << 3)) * 2);
            size_t src = (size_t)(b * SEQL + kb + r) * QKVS + hoff + (c << 3);
            cp16(sb + FK * 2 + d, QKV + src + 512);
            cp16(sb + FV * 2 + d, QKV + src + 1024);
        }
        cp_commit();
    };

    int nkt = (len + FBC - 1) / FBC;   // len >= 512 -> nkt >= 8
    load_kv(0); load_kv(1); load_kv(2);

    // Q -> smem, pre-scaled by 1/8 (exact power-of-two scale in fp16)
    {
        __half2 sc = __half2half2(__float2half_rn(0.125f));
#pragma unroll
        for (int p = 0; p < 4; p++) {
            int f = p * 256 + tid;
            int r = f >> 3, c = f & 7;
            uint32_t d = (uint32_t)(r * 64 + ((c ^ (r & 7)) << 3));
            size_t src = (qrow0 + r) * QKVS + hoff + (c << 3);
            uint4 v = *(const uint4*)(QKV + src);
            __half2* hv = (__half2*)&v;
#pragma unroll
            for (int j = 0; j < 4; j++) hv[j] = __hmul2(hv[j], sc);
            *(uint4*)(sm + FQ + d) = v;
        }
    }
    __syncthreads();

    uint32_t qh[4][4];
#pragma unroll
    for (int ks = 0; ks < 4; ks++) {
        int row = wid * 16 + (lane & 15);
        int kc = ks * 2 + (lane >> 4);
        uint32_t off = (uint32_t)(row * 64 + ((kc ^ (row & 7)) << 3)) * 2;
        ldsm4(qh[ks], smb + FQ * 2 + off);
    }

    float o[8][4];
#pragma unroll
    for (int i = 0; i < 8; i++)
#pragma unroll
        for (int j = 0; j < 4; j++) o[i][j] = 0.0f;
    float m0 = -3.0e38f, m1 = -3.0e38f, l0 = 0.0f, l1 = 0.0f;

    for (int kt = 0; kt < nkt; kt++) {
        // wait so that tile kt is complete for THIS warp's groups
        if (kt + 2 < nkt)      cp_wait<2>();
        else if (kt + 1 < nkt) cp_wait<1>();
        else                   cp_wait<0>();
        __syncthreads();   // tile kt visible to all; all warps done with kt-1
        if (kt + 3 < nkt) load_kv(kt + 3);
        uint32_t sb = smb + (uint32_t)(FKV0 + (kt & (FNBUF - 1)) * FBUF_STRIDE) * 2;

        float s[8][4];
#pragma unroll
        for (int i = 0; i < 8; i++)
#pragma unroll
            for (int j = 0; j < 4; j++) s[i][j] = 0.0f;

        // S = Qs Kh^T
#pragma unroll
        for (int ks = 0; ks < 4; ks++) {
#pragma unroll
            for (int kg = 0; kg < 4; kg++) {
                int key = kg * 16 + (lane & 15);
                int kc = ks * 2 + (lane >> 4);
                uint32_t off = (uint32_t)(key * 64 + ((kc ^ (key & 7)) << 3)) * 2;
                uint32_t rh[4];
                ldsm4(rh, sb + FK * 2 + off);
                uint32_t bh0[2] = {rh[0], rh[2]}, bh1[2] = {rh[1], rh[3]};
                mma16816(s[kg * 2],     qh[ks], bh0);
                mma16816(s[kg * 2 + 1], qh[ks], bh1);
            }
        }

        int colbase = kt * FBC + (lane & 3) * 2;
        float mx0 = -3.0e38f, mx1 = -3.0e38f;
#pragma unroll
        for (int nf = 0; nf < 8; nf++) {
            int c = colbase + nf * 8;
            float b0 = (c     >= len) ? -1e9f : 0.0f;
            float b1 = (c + 1 >= len) ? -1e9f : 0.0f;
            s[nf][0] += b0;
            s[nf][1] += b1;
            s[nf][2] += b0;
            s[nf][3] += b1;
            mx0 = fmaxf(mx0, fmaxf(s[nf][0], s[nf][1]));
            mx1 = fmaxf(mx1, fmaxf(s[nf][2], s[nf][3]));
        }
        mx0 = fmaxf(mx0, __shfl_xor_sync(0xffffffffu, mx0, 1));
        mx0 = fmaxf(mx0, __shfl_xor_sync(0xffffffffu, mx0, 2));
        mx1 = fmaxf(mx1, __shfl_xor_sync(0xffffffffu, mx1, 1));
        mx1 = fmaxf(mx1, __shfl_xor_sync(0xffffffffu, mx1, 2));
        float mn0 = fmaxf(m0, mx0), mn1 = fmaxf(m1, mx1);
        float a0 = __expf(m0 - mn0), a1 = __expf(m1 - mn1);
        float ls0 = 0.0f, ls1 = 0.0f;
#pragma unroll
        for (int nf = 0; nf < 8; nf++) {
            s[nf][0] = __expf(s[nf][0] - mn0);
            s[nf][1] = __expf(s[nf][1] - mn0);
            s[nf][2] = __expf(s[nf][2] - mn1);
            s[nf][3] = __expf(s[nf][3] - mn1);
            ls0 += s[nf][0] + s[nf][1];
            ls1 += s[nf][2] + s[nf][3];
        }
        ls0 += __shfl_xor_sync(0xffffffffu, ls0, 1);
        ls0 += __shfl_xor_sync(0xffffffffu, ls0, 2);
        ls1 += __shfl_xor_sync(0xffffffffu, ls1, 1);
        ls1 += __shfl_xor_sync(0xffffffffu, ls1, 2);
        l0 = l0 * a0 + ls0;
        l1 = l1 * a1 + ls1;
        m0 = mn0; m1 = mn1;
#pragma unroll
        for (int nf = 0; nf < 8; nf++) {
            o[nf][0] *= a0; o[nf][1] *= a0;
            o[nf][2] *= a1; o[nf][3] *= a1;
        }

        // O += P16 Vh  (pure fp16 P)
#pragma unroll
        for (int kg = 0; kg < 4; kg++) {
            uint32_t pp[4];
            pp[0] = packh(__float2half_rn(s[2 * kg][0]), __float2half_rn(s[2 * kg][1]));
            pp[1] = packh(__float2half_rn(s[2 * kg][2]), __float2half_rn(s[2 * kg][3]));
            pp[2] = packh(__float2half_rn(s[2 * kg + 1][0]), __float2half_rn(s[2 * kg + 1][1]));
            pp[3] = packh(__float2half_rn(s[2 * kg + 1][2]), __float2half_rn(s[2 * kg + 1][3]));
#pragma unroll
            for (int np = 0; np < 4; np++) {
                int krow = kg * 16 + (lane & 15);
                int nc = np * 2 + (lane >> 4);
                uint32_t off = (uint32_t)(krow * 64 + ((nc ^ (krow & 7)) << 3)) * 2;
                uint32_t rh[4];
                ldsm4t(rh, sb + FV * 2 + off);
                uint32_t vh0[2] = {rh[0], rh[1]}, vh1[2] = {rh[2], rh[3]};
                mma16816(o[np * 2],     pp, vh0);
                mma16816(o[np * 2 + 1], pp, vh1);
            }
        }
    }

    float li0 = 1.0f / l0, li1 = 1.0f / l1;
    int r0 = wid * 16 + (lane >> 2);
    size_t row0 = (qrow0 + r0) * DMODEL + hoff + (lane & 3) * 2;
    size_t row1 = (qrow0 + r0 + 8) * DMODEL + hoff + (lane & 3) * 2;
#pragma unroll
    for (int nf = 0; nf < 8; nf++) {
        *(uint32_t*)(O + row0 + nf * 8) =
            packh(__float2half_rn(o[nf][0] * li0), __float2half_rn(o[nf][1] * li0));
        *(uint32_t*)(O + row1 + nf * 8) =
            packh(__float2half_rn(o[nf][2] * li1), __float2half_rn(o[nf][3] * li1));
    }
}

// ---------------- orchestration -------------------------------------------
extern "C" void kernel_launch(void* const* d_in, const int* in_sizes, int n_in,
                              void* d_out, int out_size) {
    (void)in_sizes; (void)n_in; (void)out_size;
    const float* x_in    = (const float*)d_in[0];
    const int*   lengths = (const int*)d_in[1];
    const float* Wq = (const float*)d_in[2];
    const float* Wk = (const float*)d_in[3];
    const float* Wv = (const float*)d_in[4];
    const float* Wo = (const float*)d_in[5];
    const float* ln1g = (const float*)d_in[6];
    const float* ln1b = (const float*)d_in[7];
    const float* ln2g = (const float*)d_in[8];
    const float* ln2b = (const float*)d_in[9];
    const float* w1 = (const float*)d_in[10];
    const float* b1 = (const float*)d_in[11];
    const float* w2 = (const float*)d_in[12];
    const float* b2 = (const float*)d_in[13];

    float* px;
    f16 *ph, *pqkv, *pf, *pwh;
    cudaGetSymbolAddress((void**)&px, g_x);
    cudaGetSymbolAddress((void**)&ph, g_h);
    cudaGetSymbolAddress((void**)&pqkv, g_qkv);
    cudaGetSymbolAddress((void**)&pf, g_f);
    cudaGetSymbolAddress((void**)&pwh, g_wh);

    cudaFuncSetAttribute(k_fattn, cudaFuncAttributeMaxDynamicSharedMemorySize, FSMEM);
    cudaFuncSetAttribute(k_mm<1, false, false, false>,
                         cudaFuncAttributeMaxDynamicSharedMemorySize, GSMEM);
    cudaFuncSetAttribute(k_mm<0, false, false, true>,
                         cudaFuncAttributeMaxDynamicSharedMemorySize, GSMEM);
    cudaFuncSetAttribute(k_mm<1, true, true, false>,
                         cudaFuncAttributeMaxDynamicSharedMemorySize, GSMEM);
    cudaFuncSetAttribute(k_mm<0, true, false, true>,
                         cudaFuncAttributeMaxDynamicSharedMemorySize, GSMEM);

    k_init<<<NB_W + NB_P, 256>>>(Wq, Wk, Wv, Wo, w1, w2, pwh, x_in, px);

    dim3 gQKV(QKVS / GBN, BL / GBM);   // (12, 64)
    dim3 gD(DMODEL / GBN, BL / GBM);   // (4, 64)
    dim3 gF(DFF / GBN, BL / GBM);      // (16, 64)
    dim3 gA(SEQL / FBR, NHEAD, BATCH);

    for (int layer = 0; layer < NLAYER; layer++) {
        const f16* qkvw = pwh + OFF_QKV + (size_t)layer * DMODEL * QKVS;
        const f16* wow  = pwh + OFF_WO + (size_t)layer * DMODEL * DMODEL;
        const f16* w1w  = pwh + OFF_W1 + (size_t)layer * DMODEL * DFF;
        const f16* w2w  = pwh + OFF_W2 + (size_t)layer * DFF * DMODEL;

        k_ln<<<BL, 128>>>(px, ln1g + (size_t)layer * DMODEL, ln1b + (size_t)layer * DMODEL, ph);
        k_mm<1, false, false, false><<<gQKV, 256, GSMEM>>>(
            ph, qkvw, nullptr, nullptr, nullptr, pqkv, BL, QKVS, DMODEL);
        k_fattn<<<gA, 256, FSMEM>>>(pqkv, lengths, ph);
        k_mm<0, false, false, true><<<gD, 256, GSMEM>>>(
            ph, wow, nullptr, px, px, nullptr, BL, DMODEL, DMODEL);

        k_ln<<<BL, 128>>>(px, ln2g + (size_t)layer * DMODEL, ln2b + (size_t)layer * DMODEL, ph);
        k_mm<1, true, true, false><<<gF, 256, GSMEM>>>(
            ph, w1w, b1 + (size_t)layer * DFF, nullptr, nullptr, pf, BL, DFF, DMODEL);
        float* dst = (layer == NLAYER - 1) ? (float*)d_out : px;
        k_mm<0, true, false, true><<<gD, 256, GSMEM>>>(
            pf, w2w, b2 + (size_t)layer * DMODEL, px, dst, nullptr, BL, DMODEL, DFF);
    }
}

// round 16
// speedup vs baseline: 2.2812x; 1.0159x over previous
#include <cuda_runtime.h>
#include <cuda_fp16.h>
#include <math.h>
#include <stdint.h>

#define BATCH 8
#define SEQL 1024
#define DMODEL 512
#define NHEAD 8
#define DHEAD 64
#define DFF 2048
#define NLAYER 6
#define BL (BATCH * SEQL)   // 8192
#define QKVS 1536           // fused QKV row stride

typedef __half f16;

// ---------------- scratch (device globals: no allocs allowed) -------------
__device__ __align__(128) float g_x[BL * DMODEL];
__device__ __align__(128) f16   g_h[BL * DMODEL];     // LN out / attention O
__device__ __align__(128) f16   g_qkv[BL * QKVS];
__device__ __align__(128) f16   g_f[BL * DFF];

// weight regions (all [K][N] row-major, fp16)
#define SZ_QKV (NLAYER * DMODEL * QKVS)
#define SZ_WO  (NLAYER * DMODEL * DMODEL)
#define SZ_W1  (NLAYER * DMODEL * DFF)
#define SZ_W2  (NLAYER * DFF * DMODEL)
#define OFF_QKV 0
#define OFF_WO  (OFF_QKV + SZ_QKV)
#define OFF_W1  (OFF_WO + SZ_WO)
#define OFF_W2  (OFF_W1 + SZ_W1)
#define WTOT    (OFF_W2 + SZ_W2)
__device__ __align__(128) f16   g_wh[WTOT];

// ---------------- helpers --------------------------------------------------
__device__ __forceinline__ void cp16(uint32_t s, const void* g) {
    asm volatile("cp.async.cg.shared.global [%0], [%1], 16;\n" :: "r"(s), "l"(g));
}
__device__ __forceinline__ void cp_commit() {
    asm volatile("cp.async.commit_group;\n" ::: "memory");
}
template <int N_>
__device__ __forceinline__ void cp_wait() {
    asm volatile("cp.async.wait_group %0;\n" :: "n"(N_) : "memory");
}
__device__ __forceinline__ void ldsm4(uint32_t* r, uint32_t addr) {
    asm volatile("ldmatrix.sync.aligned.m8n8.x4.shared.b16 {%0,%1,%2,%3}, [%4];"
                 : "=r"(r[0]), "=r"(r[1]), "=r"(r[2]), "=r"(r[3]) : "r"(addr));
}
__device__ __forceinline__ void ldsm4t(uint32_t* r, uint32_t addr) {
    asm volatile("ldmatrix.sync.aligned.m8n8.x4.trans.shared.b16 {%0,%1,%2,%3}, [%4];"
                 : "=r"(r[0]), "=r"(r[1]), "=r"(r[2]), "=r"(r[3]) : "r"(addr));
}
__device__ __forceinline__ void mma16816(float* c, const uint32_t* a, const uint32_t* b) {
    asm volatile(
        "mma.sync.aligned.m16n8k16.row.col.f32.f16.f16.f32 "
        "{%0,%1,%2,%3}, {%4,%5,%6,%7}, {%8,%9}, {%0,%1,%2,%3};"
        : "+f"(c[0]), "+f"(c[1]), "+f"(c[2]), "+f"(c[3])
        : "r"(a[0]), "r"(a[1]), "r"(a[2]), "r"(a[3]), "r"(b[0]), "r"(b[1]));
}
__device__ __forceinline__ uint32_t packh(f16 a, f16 b) {
    return ((uint32_t)__half_as_ushort(b) << 16) | __half_as_ushort(a);
}

// ---------------- init: weight convert + positional embedding --------------
#define NB_W ((WTOT / 4 + 255) / 256)
#define NB_P ((BL * DMODEL) / 256)
__global__ void __launch_bounds__(256) k_init(
    const float* __restrict__ Wq, const float* __restrict__ Wk,
    const float* __restrict__ Wv, const float* __restrict__ Wo,
    const float* __restrict__ w1, const float* __restrict__ w2,
    f16* __restrict__ dh,
    const float* __restrict__ xin, float* __restrict__ xout) {
    if (blockIdx.x < NB_W) {
        uint32_t idx = (blockIdx.x * 256 + threadIdx.x) * 4;
        if (idx >= WTOT) return;
        const float* src;
        if (idx < OFF_WO) {
            uint32_t rel = idx;
            uint32_t l = rel / (DMODEL * QKVS);
            uint32_t r2 = rel - l * (DMODEL * QKVS);
            uint32_t k = r2 / QKVS;
            uint32_t j = r2 - k * QKVS;
            uint32_t sel = j >> 9;
            uint32_t jj = j & 511;
            const float* W = (sel == 0) ? Wq : (sel == 1) ? Wk : Wv;
            src = W + (size_t)l * DMODEL * DMODEL + (size_t)k * DMODEL + jj;
        } else if (idx < OFF_W1) {
            src = Wo + (idx - OFF_WO);
        } else if (idx < OFF_W2) {
            src = w1 + (idx - OFF_W1);
        } else {
            src = w2 + (idx - OFF_W2);
        }
        float4 v = *(const float4*)src;
        uint32_t* hp = (uint32_t*)(dh + idx);
        hp[0] = packh(__float2half_rn(v.x), __float2half_rn(v.y));
        hp[1] = packh(__float2half_rn(v.z), __float2half_rn(v.w));
    } else {
        int idx = (blockIdx.x - NB_W) * 256 + threadIdx.x;
        if (idx >= BL * DMODEL) return;
        int d = idx % DMODEL;
        int l = (idx / DMODEL) % SEQL;
        int half = DMODEL / 2;
        int i = (d < half) ? d : d - half;
        float inv = powf(10000.0f, -2.0f * (float)i / (float)DMODEL);
        float ang = (float)l * inv;
        float pe = (d < half) ? sinf(ang) : cosf(ang);
        xout[idx] = xin[idx] + pe;
    }
}

// ---------------- layernorm -> fp16 output ---------------------------------
__global__ void __launch_bounds__(128) k_ln(const float* __restrict__ x,
                                            const float* __restrict__ g,
                                            const float* __restrict__ b,
                                            f16* __restrict__ oh) {
    int row = blockIdx.x;
    int tid = threadIdx.x;
    const float4* xr = (const float4*)(x + (size_t)row * DMODEL);
    float4 v = xr[tid];
    __shared__ float sh[4];

    float s = v.x + v.y + v.z + v.w;
    for (int o = 16; o; o >>= 1) s += __shfl_xor_sync(0xffffffffu, s, o);
    if ((tid & 31) == 0) sh[tid >> 5] = s;
    __syncthreads();
    float mean = (sh[0] + sh[1] + sh[2] + sh[3]) * (1.0f / DMODEL);
    __syncthreads();

    float dx0 = v.x - mean, dx1 = v.y - mean, dx2 = v.z - mean, dx3 = v.w - mean;
    float s2 = dx0 * dx0 + dx1 * dx1 + dx2 * dx2 + dx3 * dx3;
    for (int o = 16; o; o >>= 1) s2 += __shfl_xor_sync(0xffffffffu, s2, o);
    if ((tid & 31) == 0) sh[tid >> 5] = s2;
    __syncthreads();
    float var = (sh[0] + sh[1] + sh[2] + sh[3]) * (1.0f / DMODEL);
    float r = rsqrtf(var + 1e-3f);

    float4 gg = ((const float4*)g)[tid];
    float4 bb = ((const float4*)b)[tid];
    float o0 = dx0 * r * gg.x + bb.x;
    float o1 = dx1 * r * gg.y + bb.y;
    float o2 = dx2 * r * gg.z + bb.z;
    float o3 = dx3 * r * gg.w + bb.w;

    size_t off = (size_t)row * DMODEL + tid * 4;
    uint32_t* hp = (uint32_t*)(oh + off);
    hp[0] = packh(__float2half_rn(o0), __float2half_rn(o1));
    hp[1] = packh(__float2half_rn(o2), __float2half_rn(o3));
}

// ---------------- pure fp16 HMMA GEMM: 128x128, GBK=64, 3-stage ------------
// C = A * B ;  OUT: 0 = fp32 (Cf), 1 = fp16 (Ch)
#define GBM 128
#define GBN 128
#define GBK 64
#define NSTAGE 3
#define STAGE_ELEMS (GBM * GBK + GBK * GBN)          // 16384 f16 = 32 KB
#define SOFF_A 0
#define SOFF_B (GBM * GBK)
#define GSMEM (NSTAGE * STAGE_ELEMS * 2)             // 98304 bytes

template <int OUT, bool BIAS, bool RELU, bool RES>
__global__ void __launch_bounds__(256, 2) k_mm(
    const f16* __restrict__ A, const f16* __restrict__ B,
    const float* __restrict__ bias, const float* __restrict__ res,
    float* __restrict__ Cf, f16* __restrict__ Ch,
    int M, int N, int K) {
    extern __shared__ f16 sm[];
    int tid = threadIdx.x;
    int lane = tid & 31, wid = tid >> 5;
    int wm = wid >> 2;            // 0..1  (64 rows)
    int wn = wid & 3;             // 0..3  (32 cols)
    int m0 = blockIdx.y * GBM, n0 = blockIdx.x * GBN;
    uint32_t smbase = (uint32_t)__cvta_generic_to_shared(sm);

    float acc[4][4][4];
#pragma unroll
    for (int i = 0; i < 4; i++)
#pragma unroll
        for (int j = 0; j < 4; j++)
#pragma unroll
            for (int q = 0; q < 4; q++) acc[i][j][q] = 0.0f;

    int nk = K / GBK;

    auto load_stage = [&](int kt) {
        int buf = kt % NSTAGE;
        uint32_t sb = smbase + (uint32_t)(buf * STAGE_ELEMS) * 2;
#pragma unroll
        for (int p = 0; p < 4; p++) {       // A: 128 rows x 8 16B-chunks
            int f = p * 256 + tid;
            int r = f >> 3, c = f & 7;
            uint32_t dst = (uint32_t)(r * GBK + ((c ^ (r & 7)) << 3));
            size_t src = (size_t)(m0 + r) * K + kt * GBK + (c << 3);
            cp16(sb + (SOFF_A + dst) * 2, A + src);
        }
#pragma unroll
        for (int p = 0; p < 4; p++) {       // B: 64 k-rows x 16 16B-chunks
            int f = p * 256 + tid;
            int k = f >> 4, c = f & 15;
            int cs = (c & 8) | ((c ^ (k & 7)) & 7);
            uint32_t dst = (uint32_t)(k * GBN + (cs << 3));
            size_t src = (size_t)(kt * GBK + k) * N + n0 + (c << 3);
            cp16(sb + (SOFF_B + dst) * 2, B + src);
        }
        cp_commit();
    };

    load_stage(0);
    if (nk > 1) load_stage(1);

    for (int kt = 0; kt < nk; kt++) {
        if (kt == nk - 1) cp_wait<0>();
        else              cp_wait<1>();
        __syncthreads();
        if (kt + 2 < nk) load_stage(kt + 2);
        uint32_t sb = smbase + (uint32_t)((kt % NSTAGE) * STAGE_ELEMS) * 2;

#pragma unroll
        for (int ks = 0; ks < GBK / 16; ks++) {
            uint32_t aa[4][4];
#pragma unroll
            for (int mt = 0; mt < 4; mt++) {
                int row = wm * 64 + mt * 16 + (lane & 15);
                int kc = ks * 2 + (lane >> 4);
                uint32_t off = (uint32_t)(row * GBK + ((kc ^ (row & 7)) << 3)) * 2;
                ldsm4(aa[mt], sb + SOFF_A * 2 + off);
            }
            uint32_t bb[2][2][2];
#pragma unroll
            for (int np = 0; np < 2; np++) {
                int krow = ks * 16 + (lane & 15);
                int nc = wn * 4 + np * 2 + (lane >> 4);
                int ncs = (nc & 8) | ((nc ^ (krow & 7)) & 7);
                uint32_t off = (uint32_t)(krow * GBN + (ncs << 3)) * 2;
                uint32_t r[4];
                ldsm4t(r, sb + SOFF_B * 2 + off);
                bb[np][0][0] = r[0]; bb[np][0][1] = r[1];
                bb[np][1][0] = r[2]; bb[np][1][1] = r[3];
            }
#pragma unroll
            for (int np = 0; np < 2; np++)
#pragma unroll
                for (int mt = 0; mt < 4; mt++)
#pragma unroll
                    for (int j = 0; j < 2; j++)
                        mma16816(acc[mt][np * 2 + j], aa[mt], bb[np][j]);
        }
    }

#pragma unroll
    for (int mt = 0; mt < 4; mt++)
#pragma unroll
        for (int nt = 0; nt < 4; nt++) {
            int rbase = m0 + wm * 64 + mt * 16 + (lane >> 2);
            int cbase = n0 + wn * 32 + nt * 8 + (lane & 3) * 2;
#pragma unroll
            for (int half = 0; half < 2; half++) {
                int r = rbase + half * 8;
                float c0 = acc[mt][nt][half * 2 + 0];
                float c1 = acc[mt][nt][half * 2 + 1];
                size_t off = (size_t)r * N + cbase;
                if (BIAS) { c0 += bias[cbase]; c1 += bias[cbase + 1]; }
                if (RES)  { float2 rv = *(const float2*)(res + off); c0 += rv.x; c1 += rv.y; }
                if (RELU) { c0 = fmaxf(c0, 0.f); c1 = fmaxf(c1, 0.f); }
                if (OUT == 0) {
                    *(float2*)(Cf + off) = make_float2(c0, c1);
                } else {
                    *(uint32_t*)(Ch + off) = packh(__float2half_rn(c0), __float2half_rn(c1));
                }
            }
        }
}

// ---------------- flash attention: log2-domain softmax, 4-buffer ring ------
// Q pre-scaled by 0.125*log2(e); softmax uses exp2f; full-tile mask skip.
#define FBR 128
#define FBC 64
#define FQ 0
#define FKV0 (FBR * 64)
#define FNBUF 4
#define FBUF_STRIDE (2 * FBC * 64)     // K + V per buffer (8192 elems)
#define FK 0
#define FV (FBC * 64)
#define FSMEM ((FBR * 64 + FNBUF * FBUF_STRIDE) * 2)   // 81920 bytes

__global__ void __launch_bounds__(256, 2) k_fattn(
    const f16* __restrict__ QKV,
    const int* __restrict__ lengths,
    f16* __restrict__ O) {
    extern __shared__ f16 sm[];
    uint32_t smb = (uint32_t)__cvta_generic_to_shared(sm);
    int b = blockIdx.z, h = blockIdx.y, qt = blockIdx.x;
    int len = lengths[b];
    int tid = threadIdx.x, lane = tid & 31, wid = tid >> 5;
    size_t qrow0 = (size_t)(b * SEQL + qt * FBR);
    size_t hoff = (size_t)h * DHEAD;

    auto load_kv = [&](int kt) {
        uint32_t sb = smb + (uint32_t)(FKV0 + (kt & (FNBUF - 1)) * FBUF_STRIDE) * 2;
        int kb = kt * FBC;
#pragma unroll
        for (int p = 0; p < 2; p++) {
            int f = p * 256 + tid;
            int r = f >> 3, c = f & 7;
            uint32_t d = (uint32_t)((r * 64 + ((c ^ (r & 7)) << 3)) * 2);
            size_t src = (size_t)(b * SEQL + kb + r) * QKVS + hoff + (c << 3);
            cp16(sb + FK * 2 + d, QKV + src + 512);
            cp16(sb + FV * 2 + d, QKV + src + 1024);
        }
        cp_commit();
    };

    int nkt = (len + FBC - 1) / FBC;
    load_kv(0); load_kv(1); load_kv(2);

    // Q -> smem, pre-scaled by 0.125 * log2(e) (log2-domain logits)
    {
        __half2 sc = __half2half2(__float2half_rn(0.125f * 1.44269504f));
#pragma unroll
        for (int p = 0; p < 4; p++) {
            int f = p * 256 + tid;
            int r = f >> 3, c = f & 7;
            uint32_t d = (uint32_t)(r * 64 + ((c ^ (r & 7)) << 3));
            size_t src = (qrow0 + r) * QKVS + hoff + (c << 3);
            uint4 v = *(const uint4*)(QKV + src);
            __half2* hv = (__half2*)&v;
#pragma unroll
            for (int j = 0; j < 4; j++) hv[j] = __hmul2(hv[j], sc);
            *(uint4*)(sm + FQ + d) = v;
        }
    }
    __syncthreads();

    uint32_t qh[4][4];
#pragma unroll
    for (int ks = 0; ks < 4; ks++) {
        int row = wid * 16 + (lane & 15);
        int kc = ks * 2 + (lane >> 4);
        uint32_t off = (uint32_t)(row * 64 + ((kc ^ (row & 7)) << 3)) * 2;
        ldsm4(qh[ks], smb + FQ * 2 + off);
    }

    // hoisted per-thread ldsm address bases (kg stride = 16 rows * 128B = 2048)
    int l15 = lane & 15, lh = lane >> 4, l7 = lane & 7;
    uint32_t kb_base[4], vb_base[4];
#pragma unroll
    for (int ks = 0; ks < 4; ks++) {
        int kc = ks * 2 + lh;
        kb_base[ks] = (uint32_t)(l15 * 64 + ((kc ^ l7) << 3)) * 2;
    }
#pragma unroll
    for (int np = 0; np < 4; np++) {
        int nc = np * 2 + lh;
        vb_base[np] = (uint32_t)(l15 * 64 + ((nc ^ l7) << 3)) * 2;
    }

    float o[8][4];
#pragma unroll
    for (int i = 0; i < 8; i++)
#pragma unroll
        for (int j = 0; j < 4; j++) o[i][j] = 0.0f;
    float m0 = -3.0e38f, m1 = -3.0e38f, l0 = 0.0f, l1 = 0.0f;

    for (int kt = 0; kt < nkt; kt++) {
        if (kt + 2 < nkt)      cp_wait<2>();
        else if (kt + 1 < nkt) cp_wait<1>();
        else                   cp_wait<0>();
        __syncthreads();
        if (kt + 3 < nkt) load_kv(kt + 3);
        uint32_t sb = smb + (uint32_t)(FKV0 + (kt & (FNBUF - 1)) * FBUF_STRIDE) * 2;

        float s[8][4];
#pragma unroll
        for (int i = 0; i < 8; i++)
#pragma unroll
            for (int j = 0; j < 4; j++) s[i][j] = 0.0f;

        // S = Qs Kh^T   (log2-domain)
#pragma unroll
        for (int ks = 0; ks < 4; ks++) {
#pragma unroll
            for (int kg = 0; kg < 4; kg++) {
                uint32_t rh[4];
                ldsm4(rh, sb + FK * 2 + kb_base[ks] + kg * 2048);
                uint32_t bh0[2] = {rh[0], rh[2]}, bh1[2] = {rh[1], rh[3]};
                mma16816(s[kg * 2],     qh[ks], bh0);
                mma16816(s[kg * 2 + 1], qh[ks], bh1);
            }
        }

        // mask only partial tiles (CTA-uniform branch)
        if ((kt + 1) * FBC > len) {
            int colbase = kt * FBC + (lane & 3) * 2;
#pragma unroll
            for (int nf = 0; nf < 8; nf++) {
                int c = colbase + nf * 8;
                if (c >= len)     { s[nf][0] = -1e9f; s[nf][2] = -1e9f; }
                if (c + 1 >= len) { s[nf][1] = -1e9f; s[nf][3] = -1e9f; }
            }
        }

        float mx0 = -3.0e38f, mx1 = -3.0e38f;
#pragma unroll
        for (int nf = 0; nf < 8; nf++) {
            mx0 = fmaxf(mx0, fmaxf(s[nf][0], s[nf][1]));
            mx1 = fmaxf(mx1, fmaxf(s[nf][2], s[nf][3]));
        }
        mx0 = fmaxf(mx0, __shfl_xor_sync(0xffffffffu, mx0, 1));
        mx0 = fmaxf(mx0, __shfl_xor_sync(0xffffffffu, mx0, 2));
        mx1 = fmaxf(mx1, __shfl_xor_sync(0xffffffffu, mx1, 1));
        mx1 = fmaxf(mx1, __shfl_xor_sync(0xffffffffu, mx1, 2));
        float mn0 = fmaxf(m0, mx0), mn1 = fmaxf(m1, mx1);
        float a0 = exp2f(m0 - mn0), a1 = exp2f(m1 - mn1);
        float ls0 = 0.0f, ls1 = 0.0f;
#pragma unroll
        for (int nf = 0; nf < 8; nf++) {
            s[nf][0] = exp2f(s[nf][0] - mn0);
            s[nf][1] = exp2f(s[nf][1] - mn0);
            s[nf][2] = exp2f(s[nf][2] - mn1);
            s[nf][3] = exp2f(s[nf][3] - mn1);
            ls0 += s[nf][0] + s[nf][1];
            ls1 += s[nf][2] + s[nf][3];
        }
        ls0 += __shfl_xor_sync(0xffffffffu, ls0, 1);
        ls0 += __shfl_xor_sync(0xffffffffu, ls0, 2);
        ls1 += __shfl_xor_sync(0xffffffffu, ls1, 1);
        ls1 += __shfl_xor_sync(0xffffffffu, ls1, 2);
        l0 = l0 * a0 + ls0;
        l1 = l1 * a1 + ls1;
        m0 = mn0; m1 = mn1;
#pragma unroll
        for (int nf = 0; nf < 8; nf++) {
            o[nf][0] *= a0; o[nf][1] *= a0;
            o[nf][2] *= a1; o[nf][3] *= a1;
        }

        // O += P16 Vh  (pure fp16 P)
#pragma unroll
        for (int kg = 0; kg < 4; kg++) {
            uint32_t pp[4];
            pp[0] = packh(__float2half_rn(s[2 * kg][0]), __float2half_rn(s[2 * kg][1]));
            pp[1] = packh(__float2half_rn(s[2 * kg][2]), __float2half_rn(s[2 * kg][3]));
            pp[2] = packh(__float2half_rn(s[2 * kg + 1][0]), __float2half_rn(s[2 * kg + 1][1]));
            pp[3] = packh(__float2half_rn(s[2 * kg + 1][2]), __float2half_rn(s[2 * kg + 1][3]));
#pragma unroll
            for (int np = 0; np < 4; np++) {
                uint32_t rh[4];
                ldsm4t(rh, sb + FV * 2 + vb_base[np] + kg * 2048);
                uint32_t vh0[2] = {rh[0], rh[1]}, vh1[2] = {rh[2], rh[3]};
                mma16816(o[np * 2],     pp, vh0);
                mma16816(o[np * 2 + 1], pp, vh1);
            }
        }
    }

    float li0 = 1.0f / l0, li1 = 1.0f / l1;
    int r0 = wid * 16 + (lane >> 2);
    size_t row0 = (qrow0 + r0) * DMODEL + hoff + (lane & 3) * 2;
    size_t row1 = (qrow0 + r0 + 8) * DMODEL + hoff + (lane & 3) * 2;
#pragma unroll
    for (int nf = 0; nf < 8; nf++) {
        *(uint32_t*)(O + row0 + nf * 8) =
            packh(__float2half_rn(o[nf][0] * li0), __float2half_rn(o[nf][1] * li0));
        *(uint32_t*)(O + row1 + nf * 8) =
            packh(__float2half_rn(o[nf][2] * li1), __float2half_rn(o[nf][3] * li1));
    }
}

// ---------------- orchestration -------------------------------------------
extern "C" void kernel_launch(void* const* d_in, const int* in_sizes, int n_in,
                              void* d_out, int out_size) {
    (void)in_sizes; (void)n_in; (void)out_size;
    const float* x_in    = (const float*)d_in[0];
    const int*   lengths = (const int*)d_in[1];
    const float* Wq = (const float*)d_in[2];
    const float* Wk = (const float*)d_in[3];
    const float* Wv = (const float*)d_in[4];
    const float* Wo = (const float*)d_in[5];
    const float* ln1g = (const float*)d_in[6];
    const float* ln1b = (const float*)d_in[7];
    const float* ln2g = (const float*)d_in[8];
    const float* ln2b = (const float*)d_in[9];
    const float* w1 = (const float*)d_in[10];
    const float* b1 = (const float*)d_in[11];
    const float* w2 = (const float*)d_in[12];
    const float* b2 = (const float*)d_in[13];

    float* px;
    f16 *ph, *pqkv, *pf, *pwh;
    cudaGetSymbolAddress((void**)&px, g_x);
    cudaGetSymbolAddress((void**)&ph, g_h);
    cudaGetSymbolAddress((void**)&pqkv, g_qkv);
    cudaGetSymbolAddress((void**)&pf, g_f);
    cudaGetSymbolAddress((void**)&pwh, g_wh);

    cudaFuncSetAttribute(k_fattn, cudaFuncAttributeMaxDynamicSharedMemorySize, FSMEM);
    cudaFuncSetAttribute(k_mm<1, false, false, false>,
                         cudaFuncAttributeMaxDynamicSharedMemorySize, GSMEM);
    cudaFuncSetAttribute(k_mm<0, false, false, true>,
                         cudaFuncAttributeMaxDynamicSharedMemorySize, GSMEM);
    cudaFuncSetAttribute(k_mm<1, true, true, false>,
                         cudaFuncAttributeMaxDynamicSharedMemorySize, GSMEM);
    cudaFuncSetAttribute(k_mm<0, true, false, true>,
                         cudaFuncAttributeMaxDynamicSharedMemorySize, GSMEM);

    k_init<<<NB_W + NB_P, 256>>>(Wq, Wk, Wv, Wo, w1, w2, pwh, x_in, px);

    dim3 gQKV(QKVS / GBN, BL / GBM);   // (12, 64)
    dim3 gD(DMODEL / GBN, BL / GBM);   // (4, 64)
    dim3 gF(DFF / GBN, BL / GBM);      // (16, 64)
    dim3 gA(SEQL / FBR, NHEAD, BATCH);

    for (int layer = 0; layer < NLAYER; layer++) {
        const f16* qkvw = pwh + OFF_QKV + (size_t)layer * DMODEL * QKVS;
        const f16* wow  = pwh + OFF_WO + (size_t)layer * DMODEL * DMODEL;
        const f16* w1w  = pwh + OFF_W1 + (size_t)layer * DMODEL * DFF;
        const f16* w2w  = pwh + OFF_W2 + (size_t)layer * DFF * DMODEL;

        k_ln<<<BL, 128>>>(px, ln1g + (size_t)layer * DMODEL, ln1b + (size_t)layer * DMODEL, ph);
        k_mm<1, false, false, false><<<gQKV, 256, GSMEM>>>(
            ph, qkvw, nullptr, nullptr, nullptr, pqkv, BL, QKVS, DMODEL);
        k_fattn<<<gA, 256, FSMEM>>>(pqkv, lengths, ph);
        k_mm<0, false, false, true><<<gD, 256, GSMEM>>>(
            ph, wow, nullptr, px, px, nullptr, BL, DMODEL, DMODEL);

        k_ln<<<BL, 128>>>(px, ln2g + (size_t)layer * DMODEL, ln2b + (size_t)layer * DMODEL, ph);
        k_mm<1, true, true, false><<<gF, 256, GSMEM>>>(
            ph, w1w, b1 + (size_t)layer * DFF, nullptr, nullptr, pf, BL, DFF, DMODEL);
        float* dst = (layer == NLAYER - 1) ? (float*)d_out : px;
        k_mm<0, true, false, true><<<gD, 256, GSMEM>>>(
            pf, w2w, b2 + (size_t)layer * DMODEL, px, dst, nullptr, BL, DMODEL, DFF);
    }
}

// round 17
// speedup vs baseline: 2.3234x; 1.0185x over previous
#include <cuda_runtime.h>
#include <cuda_fp16.h>
#include <math.h>
#include <stdint.h>

#define BATCH 8
#define SEQL 1024
#define DMODEL 512
#define NHEAD 8
#define DHEAD 64
#define DFF 2048
#define NLAYER 6
#define BL (BATCH * SEQL)   // 8192
#define QKVS 1536           // fused QKV row stride

typedef __half f16;

// ---------------- scratch (device globals: no allocs allowed) -------------
__device__ __align__(128) float g_x[BL * DMODEL];
__device__ __align__(128) f16   g_h[BL * DMODEL];     // LN out / attention O
__device__ __align__(128) f16   g_qkv[BL * QKVS];
__device__ __align__(128) f16   g_f[BL * DFF];

// weight regions (all [K][N] row-major, fp16)
#define SZ_QKV (NLAYER * DMODEL * QKVS)
#define SZ_WO  (NLAYER * DMODEL * DMODEL)
#define SZ_W1  (NLAYER * DMODEL * DFF)
#define SZ_W2  (NLAYER * DFF * DMODEL)
#define OFF_QKV 0
#define OFF_WO  (OFF_QKV + SZ_QKV)
#define OFF_W1  (OFF_WO + SZ_WO)
#define OFF_W2  (OFF_W1 + SZ_W1)
#define WTOT    (OFF_W2 + SZ_W2)
__device__ __align__(128) f16   g_wh[WTOT];

// ---------------- helpers --------------------------------------------------
__device__ __forceinline__ void cp16(uint32_t s, const void* g) {
    asm volatile("cp.async.cg.shared.global [%0], [%1], 16;\n" :: "r"(s), "l"(g));
}
__device__ __forceinline__ void cp_commit() {
    asm volatile("cp.async.commit_group;\n" ::: "memory");
}
template <int N_>
__device__ __forceinline__ void cp_wait() {
    asm volatile("cp.async.wait_group %0;\n" :: "n"(N_) : "memory");
}
__device__ __forceinline__ void ldsm4(uint32_t* r, uint32_t addr) {
    asm volatile("ldmatrix.sync.aligned.m8n8.x4.shared.b16 {%0,%1,%2,%3}, [%4];"
                 : "=r"(r[0]), "=r"(r[1]), "=r"(r[2]), "=r"(r[3]) : "r"(addr));
}
__device__ __forceinline__ void ldsm4t(uint32_t* r, uint32_t addr) {
    asm volatile("ldmatrix.sync.aligned.m8n8.x4.trans.shared.b16 {%0,%1,%2,%3}, [%4];"
                 : "=r"(r[0]), "=r"(r[1]), "=r"(r[2]), "=r"(r[3]) : "r"(addr));
}
__device__ __forceinline__ void mma16816(float* c, const uint32_t* a, const uint32_t* b) {
    asm volatile(
        "mma.sync.aligned.m16n8k16.row.col.f32.f16.f16.f32 "
        "{%0,%1,%2,%3}, {%4,%5,%6,%7}, {%8,%9}, {%0,%1,%2,%3};"
        : "+f"(c[0]), "+f"(c[1]), "+f"(c[2]), "+f"(c[3])
        : "r"(a[0]), "r"(a[1]), "r"(a[2]), "r"(a[3]), "r"(b[0]), "r"(b[1]));
}
__device__ __forceinline__ uint32_t packh(f16 a, f16 b) {
    return ((uint32_t)__half_as_ushort(b) << 16) | __half_as_ushort(a);
}
// pack two fp32 into f16x2 then exp2 in packed fp16 (one MUFU op for 2 lanes)
__device__ __forceinline__ uint32_t exp2_f16x2(float a, float b) {
    uint32_t p, r;
    asm("cvt.rn.f16x2.f32 %0, %1, %2;" : "=r"(p) : "f"(b), "f"(a));
    asm("ex2.approx.f16x2 %0, %1;" : "=r"(r) : "r"(p));
    return r;
}

// ---------------- init: weight convert + positional embedding --------------
#define NB_W ((WTOT / 4 + 255) / 256)
#define NB_P ((BL * DMODEL) / 256)
__global__ void __launch_bounds__(256) k_init(
    const float* __restrict__ Wq, const float* __restrict__ Wk,
    const float* __restrict__ Wv, const float* __restrict__ Wo,
    const float* __restrict__ w1, const float* __restrict__ w2,
    f16* __restrict__ dh,
    const float* __restrict__ xin, float* __restrict__ xout) {
    if (blockIdx.x < NB_W) {
        uint32_t idx = (blockIdx.x * 256 + threadIdx.x) * 4;
        if (idx >= WTOT) return;
        const float* src;
        if (idx < OFF_WO) {
            uint32_t rel = idx;
            uint32_t l = rel / (DMODEL * QKVS);
            uint32_t r2 = rel - l * (DMODEL * QKVS);
            uint32_t k = r2 / QKVS;
            uint32_t j = r2 - k * QKVS;
            uint32_t sel = j >> 9;
            uint32_t jj = j & 511;
            const float* W = (sel == 0) ? Wq : (sel == 1) ? Wk : Wv;
            src = W + (size_t)l * DMODEL * DMODEL + (size_t)k * DMODEL + jj;
        } else if (idx < OFF_W1) {
            src = Wo + (idx - OFF_WO);
        } else if (idx < OFF_W2) {
            src = w1 + (idx - OFF_W1);
        } else {
            src = w2 + (idx - OFF_W2);
        }
        float4 v = *(const float4*)src;
        uint32_t* hp = (uint32_t*)(dh + idx);
        hp[0] = packh(__float2half_rn(v.x), __float2half_rn(v.y));
        hp[1] = packh(__float2half_rn(v.z), __float2half_rn(v.w));
    } else {
        int idx = (blockIdx.x - NB_W) * 256 + threadIdx.x;
        if (idx >= BL * DMODEL) return;
        int d = idx % DMODEL;
        int l = (idx / DMODEL) % SEQL;
        int half = DMODEL / 2;
        int i = (d < half) ? d : d - half;
        float inv = powf(10000.0f, -2.0f * (float)i / (float)DMODEL);
        float ang = (float)l * inv;
        float pe = (d < half) ? sinf(ang) : cosf(ang);
        xout[idx] = xin[idx] + pe;
    }
}

// ---------------- layernorm -> fp16 output ---------------------------------
__global__ void __launch_bounds__(128) k_ln(const float* __restrict__ x,
                                            const float* __restrict__ g,
                                            const float* __restrict__ b,
                                            f16* __restrict__ oh) {
    int row = blockIdx.x;
    int tid = threadIdx.x;
    const float4* xr = (const float4*)(x + (size_t)row * DMODEL);
    float4 v = xr[tid];
    __shared__ float sh[4];

    float s = v.x + v.y + v.z + v.w;
    for (int o = 16; o; o >>= 1) s += __shfl_xor_sync(0xffffffffu, s, o);
    if ((tid & 31) == 0) sh[tid >> 5] = s;
    __syncthreads();
    float mean = (sh[0] + sh[1] + sh[2] + sh[3]) * (1.0f / DMODEL);
    __syncthreads();

    float dx0 = v.x - mean, dx1 = v.y - mean, dx2 = v.z - mean, dx3 = v.w - mean;
    float s2 = dx0 * dx0 + dx1 * dx1 + dx2 * dx2 + dx3 * dx3;
    for (int o = 16; o; o >>= 1) s2 += __shfl_xor_sync(0xffffffffu, s2, o);
    if ((tid & 31) == 0) sh[tid >> 5] = s2;
    __syncthreads();
    float var = (sh[0] + sh[1] + sh[2] + sh[3]) * (1.0f / DMODEL);
    float r = rsqrtf(var + 1e-3f);

    float4 gg = ((const float4*)g)[tid];
    float4 bb = ((const float4*)b)[tid];
    float o0 = dx0 * r * gg.x + bb.x;
    float o1 = dx1 * r * gg.y + bb.y;
    float o2 = dx2 * r * gg.z + bb.z;
    float o3 = dx3 * r * gg.w + bb.w;

    size_t off = (size_t)row * DMODEL + tid * 4;
    uint32_t* hp = (uint32_t*)(oh + off);
    hp[0] = packh(__float2half_rn(o0), __float2half_rn(o1));
    hp[1] = packh(__float2half_rn(o2), __float2half_rn(o3));
}

// ---------------- pure fp16 HMMA GEMM: 128x128, GBK=64, 3-stage ------------
// C = A * B ;  OUT: 0 = fp32 (Cf), 1 = fp16 (Ch)
#define GBM 128
#define GBN 128
#define GBK 64
#define NSTAGE 3
#define STAGE_ELEMS (GBM * GBK + GBK * GBN)          // 16384 f16 = 32 KB
#define SOFF_A 0
#define SOFF_B (GBM * GBK)
#define GSMEM (NSTAGE * STAGE_ELEMS * 2)             // 98304 bytes

template <int OUT, bool BIAS, bool RELU, bool RES>
__global__ void __launch_bounds__(256, 2) k_mm(
    const f16* __restrict__ A, const f16* __restrict__ B,
    const float* __restrict__ bias, const float* __restrict__ res,
    float* __restrict__ Cf, f16* __restrict__ Ch,
    int M, int N, int K) {
    extern __shared__ f16 sm[];
    int tid = threadIdx.x;
    int lane = tid & 31, wid = tid >> 5;
    int wm = wid >> 2;            // 0..1  (64 rows)
    int wn = wid & 3;             // 0..3  (32 cols)
    int m0 = blockIdx.y * GBM, n0 = blockIdx.x * GBN;
    uint32_t smbase = (uint32_t)__cvta_generic_to_shared(sm);

    float acc[4][4][4];
#pragma unroll
    for (int i = 0; i < 4; i++)
#pragma unroll
        for (int j = 0; j < 4; j++)
#pragma unroll
            for (int q = 0; q < 4; q++) acc[i][j][q] = 0.0f;

    int nk = K / GBK;

    auto load_stage = [&](int kt) {
        int buf = kt % NSTAGE;
        uint32_t sb = smbase + (uint32_t)(buf * STAGE_ELEMS) * 2;
#pragma unroll
        for (int p = 0; p < 4; p++) {       // A: 128 rows x 8 16B-chunks
            int f = p * 256 + tid;
            int r = f >> 3, c = f & 7;
            uint32_t dst = (uint32_t)(r * GBK + ((c ^ (r & 7)) << 3));
            size_t src = (size_t)(m0 + r) * K + kt * GBK + (c << 3);
            cp16(sb + (SOFF_A + dst) * 2, A + src);
        }
#pragma unroll
        for (int p = 0; p < 4; p++) {       // B: 64 k-rows x 16 16B-chunks
            int f = p * 256 + tid;
            int k = f >> 4, c = f & 15;
            int cs = (c & 8) | ((c ^ (k & 7)) & 7);
            uint32_t dst = (uint32_t)(k * GBN + (cs << 3));
            size_t src = (size_t)(kt * GBK + k) * N + n0 + (c << 3);
            cp16(sb + (SOFF_B + dst) * 2, B + src);
        }
        cp_commit();
    };

    load_stage(0);
    if (nk > 1) load_stage(1);

    for (int kt = 0; kt < nk; kt++) {
        if (kt == nk - 1) cp_wait<0>();
        else              cp_wait<1>();
        __syncthreads();
        if (kt + 2 < nk) load_stage(kt + 2);
        uint32_t sb = smbase + (uint32_t)((kt % NSTAGE) * STAGE_ELEMS) * 2;

#pragma unroll
        for (int ks = 0; ks < GBK / 16; ks++) {
            uint32_t aa[4][4];
#pragma unroll
            for (int mt = 0; mt < 4; mt++) {
                int row = wm * 64 + mt * 16 + (lane & 15);
                int kc = ks * 2 + (lane >> 4);
                uint32_t off = (uint32_t)(row * GBK + ((kc ^ (row & 7)) << 3)) * 2;
                ldsm4(aa[mt], sb + SOFF_A * 2 + off);
            }
            uint32_t bb[2][2][2];
#pragma unroll
            for (int np = 0; np < 2; np++) {
                int krow = ks * 16 + (lane & 15);
                int nc = wn * 4 + np * 2 + (lane >> 4);
                int ncs = (nc & 8) | ((nc ^ (krow & 7)) & 7);
                uint32_t off = (uint32_t)(krow * GBN + (ncs << 3)) * 2;
                uint32_t r[4];
                ldsm4t(r, sb + SOFF_B * 2 + off);
                bb[np][0][0] = r[0]; bb[np][0][1] = r[1];
                bb[np][1][0] = r[2]; bb[np][1][1] = r[3];
            }
#pragma unroll
            for (int np = 0; np < 2; np++)
#pragma unroll
                for (int mt = 0; mt < 4; mt++)
#pragma unroll
                    for (int j = 0; j < 2; j++)
                        mma16816(acc[mt][np * 2 + j], aa[mt], bb[np][j]);
        }
    }

#pragma unroll
    for (int mt = 0; mt < 4; mt++)
#pragma unroll
        for (int nt = 0; nt < 4; nt++) {
            int rbase = m0 + wm * 64 + mt * 16 + (lane >> 2);
            int cbase = n0 + wn * 32 + nt * 8 + (lane & 3) * 2;
#pragma unroll
            for (int half = 0; half < 2; half++) {
                int r = rbase + half * 8;
                float c0 = acc[mt][nt][half * 2 + 0];
                float c1 = acc[mt][nt][half * 2 + 1];
                size_t off = (size_t)r * N + cbase;
                if (BIAS) { c0 += bias[cbase]; c1 += bias[cbase + 1]; }
                if (RES)  { float2 rv = *(const float2*)(res + off); c0 += rv.x; c1 += rv.y; }
                if (RELU) { c0 = fmaxf(c0, 0.f); c1 = fmaxf(c1, 0.f); }
                if (OUT == 0) {
                    *(float2*)(Cf + off) = make_float2(c0, c1);
                } else {
                    *(uint32_t*)(Ch + off) = packh(__float2half_rn(c0), __float2half_rn(c1));
                }
            }
        }
}

// ---------------- flash attention: f16x2 exp softmax, 4-buffer ring --------
// Q pre-scaled by 0.125*log2(e); exp via ex2.approx.f16x2 (packed P direct).
#define FBR 128
#define FBC 64
#define FQ 0
#define FKV0 (FBR * 64)
#define FNBUF 4
#define FBUF_STRIDE (2 * FBC * 64)     // K + V per buffer (8192 elems)
#define FK 0
#define FV (FBC * 64)
#define FSMEM ((FBR * 64 + FNBUF * FBUF_STRIDE) * 2)   // 81920 bytes

__global__ void __launch_bounds__(256, 2) k_fattn(
    const f16* __restrict__ QKV,
    const int* __restrict__ lengths,
    f16* __restrict__ O) {
    extern __shared__ f16 sm[];
    uint32_t smb = (uint32_t)__cvta_generic_to_shared(sm);
    int b = blockIdx.z, h = blockIdx.y, qt = blockIdx.x;
    int len = lengths[b];
    int tid = threadIdx.x, lane = tid & 31, wid = tid >> 5;
    size_t qrow0 = (size_t)(b * SEQL + qt * FBR);
    size_t hoff = (size_t)h * DHEAD;

    auto load_kv = [&](int kt) {
        uint32_t sb = smb + (uint32_t)(FKV0 + (kt & (FNBUF - 1)) * FBUF_STRIDE) * 2;
        int kb = kt * FBC;
#pragma unroll
        for (int p = 0; p < 2; p++) {
            int f = p * 256 + tid;
            int r = f >> 3, c = f & 7;
            uint32_t d = (uint32_t)((r * 64 + ((c ^ (r & 7)) << 3)) * 2);
            size_t src = (size_t)(b * SEQL + kb + r) * QKVS + hoff + (c << 3);
            cp16(sb + FK * 2 + d, QKV + src + 512);
            cp16(sb + FV * 2 + d, QKV + src + 1024);
        }
        cp_commit();
    };

    int nkt = (len + FBC - 1) / FBC;
    load_kv(0); load_kv(1); load_kv(2);

    // Q -> smem, pre-scaled by 0.125 * log2(e) (log2-domain logits)
    {
        __half2 sc = __half2half2(__float2half_rn(0.125f * 1.44269504f));
#pragma unroll
        for (int p = 0; p < 4; p++) {
            int f = p * 256 + tid;
            int r = f >> 3, c = f & 7;
            uint32_t d = (uint32_t)(r * 64 + ((c ^ (r & 7)) << 3));
            size_t src = (qrow0 + r) * QKVS + hoff + (c << 3);
            uint4 v = *(const uint4*)(QKV + src);
            __half2* hv = (__half2*)&v;
#pragma unroll
            for (int j = 0; j < 4; j++) hv[j] = __hmul2(hv[j], sc);
            *(uint4*)(sm + FQ + d) = v;
        }
    }
    __syncthreads();

    uint32_t qh[4][4];
#pragma unroll
    for (int ks = 0; ks < 4; ks++) {
        int row = wid * 16 + (lane & 15);
        int kc = ks * 2 + (lane >> 4);
        uint32_t off = (uint32_t)(row * 64 + ((kc ^ (row & 7)) << 3)) * 2;
        ldsm4(qh[ks], smb + FQ * 2 + off);
    }

    int l15 = lane & 15, lh = lane >> 4, l7 = lane & 7;
    uint32_t kb_base[4], vb_base[4];
#pragma unroll
    for (int ks = 0; ks < 4; ks++) {
        int kc = ks * 2 + lh;
        kb_base[ks] = (uint32_t)(l15 * 64 + ((kc ^ l7) << 3)) * 2;
    }
#pragma unroll
    for (int np = 0; np < 4; np++) {
        int nc = np * 2 + lh;
        vb_base[np] = (uint32_t)(l15 * 64 + ((nc ^ l7) << 3)) * 2;
    }

    float o[8][4];
#pragma unroll
    for (int i = 0; i < 8; i++)
#pragma unroll
        for (int j = 0; j < 4; j++) o[i][j] = 0.0f;
    float m0 = -3.0e38f, m1 = -3.0e38f, l0 = 0.0f, l1 = 0.0f;

    for (int kt = 0; kt < nkt; kt++) {
        if (kt + 2 < nkt)      cp_wait<2>();
        else if (kt + 1 < nkt) cp_wait<1>();
        else                   cp_wait<0>();
        __syncthreads();
        if (kt + 3 < nkt) load_kv(kt + 3);
        uint32_t sb = smb + (uint32_t)(FKV0 + (kt & (FNBUF - 1)) * FBUF_STRIDE) * 2;

        float s[8][4];
#pragma unroll
        for (int i = 0; i < 8; i++)
#pragma unroll
            for (int j = 0; j < 4; j++) s[i][j] = 0.0f;

        // S = Qs Kh^T   (log2-domain)
#pragma unroll
        for (int ks = 0; ks < 4; ks++) {
#pragma unroll
            for (int kg = 0; kg < 4; kg++) {
                uint32_t rh[4];
                ldsm4(rh, sb + FK * 2 + kb_base[ks] + kg * 2048);
                uint32_t bh0[2] = {rh[0], rh[2]}, bh1[2] = {rh[1], rh[3]};
                mma16816(s[kg * 2],     qh[ks], bh0);
                mma16816(s[kg * 2 + 1], qh[ks], bh1);
            }
        }

        // mask only partial tiles (CTA-uniform branch)
        if ((kt + 1) * FBC > len) {
            int colbase = kt * FBC + (lane & 3) * 2;
#pragma unroll
            for (int nf = 0; nf < 8; nf++) {
                int c = colbase + nf * 8;
                if (c >= len)     { s[nf][0] = -1e9f; s[nf][2] = -1e9f; }
                if (c + 1 >= len) { s[nf][1] = -1e9f; s[nf][3] = -1e9f; }
            }
        }

        float mx0 = -3.0e38f, mx1 = -3.0e38f;
#pragma unroll
        for (int nf = 0; nf < 8; nf++) {
            mx0 = fmaxf(mx0, fmaxf(s[nf][0], s[nf][1]));
            mx1 = fmaxf(mx1, fmaxf(s[nf][2], s[nf][3]));
        }
        mx0 = fmaxf(mx0, __shfl_xor_sync(0xffffffffu, mx0, 1));
        mx0 = fmaxf(mx0, __shfl_xor_sync(0xffffffffu, mx0, 2));
        mx1 = fmaxf(mx1, __shfl_xor_sync(0xffffffffu, mx1, 1));
        mx1 = fmaxf(mx1, __shfl_xor_sync(0xffffffffu, mx1, 2));
        float mn0 = fmaxf(m0, mx0), mn1 = fmaxf(m1, mx1);
        float a0 = exp2f(m0 - mn0), a1 = exp2f(m1 - mn1);

        // packed-fp16 exp: pe[nf][0] = exp2(s0,s1), pe[nf][1] = exp2(s2,s3)
        uint32_t pe[8][2];
        float ls0 = 0.0f, ls1 = 0.0f;
#pragma unroll
        for (int nf = 0; nf < 8; nf++) {
            pe[nf][0] = exp2_f16x2(s[nf][0] - mn0, s[nf][1] - mn0);
            pe[nf][1] = exp2_f16x2(s[nf][2] - mn1, s[nf][3] - mn1);
            float2 f0 = __half22float2(*(__half2*)&pe[nf][0]);
            float2 f1 = __half22float2(*(__half2*)&pe[nf][1]);
            ls0 += f0.x + f0.y;
            ls1 += f1.x + f1.y;
        }
        ls0 += __shfl_xor_sync(0xffffffffu, ls0, 1);
        ls0 += __shfl_xor_sync(0xffffffffu, ls0, 2);
        ls1 += __shfl_xor_sync(0xffffffffu, ls1, 1);
        ls1 += __shfl_xor_sync(0xffffffffu, ls1, 2);
        l0 = l0 * a0 + ls0;
        l1 = l1 * a1 + ls1;
        m0 = mn0; m1 = mn1;
#pragma unroll
        for (int nf = 0; nf < 8; nf++) {
            o[nf][0] *= a0; o[nf][1] *= a0;
            o[nf][2] *= a1; o[nf][3] *= a1;
        }

        // O += P16 Vh  (packed P straight from exp)
#pragma unroll
        for (int kg = 0; kg < 4; kg++) {
            uint32_t pp[4] = {pe[2 * kg][0], pe[2 * kg][1],
                              pe[2 * kg + 1][0], pe[2 * kg + 1][1]};
#pragma unroll
            for (int np = 0; np < 4; np++) {
                uint32_t rh[4];
                ldsm4t(rh, sb + FV * 2 + vb_base[np] + kg * 2048);
                uint32_t vh0[2] = {rh[0], rh[1]}, vh1[2] = {rh[2], rh[3]};
                mma16816(o[np * 2],     pp, vh0);
                mma16816(o[np * 2 + 1], pp, vh1);
            }
        }
    }

    float li0 = 1.0f / l0, li1 = 1.0f / l1;
    int r0 = wid * 16 + (lane >> 2);
    size_t row0 = (qrow0 + r0) * DMODEL + hoff + (lane & 3) * 2;
    size_t row1 = (qrow0 + r0 + 8) * DMODEL + hoff + (lane & 3) * 2;
#pragma unroll
    for (int nf = 0; nf < 8; nf++) {
        *(uint32_t*)(O + row0 + nf * 8) =
            packh(__float2half_rn(o[nf][0] * li0), __float2half_rn(o[nf][1] * li0));
        *(uint32_t*)(O + row1 + nf * 8) =
            packh(__float2half_rn(o[nf][2] * li1), __float2half_rn(o[nf][3] * li1));
    }
}

// ---------------- orchestration -------------------------------------------
extern "C" void kernel_launch(void* const* d_in, const int* in_sizes, int n_in,
                              void* d_out, int out_size) {
    (void)in_sizes; (void)n_in; (void)out_size;
    const float* x_in    = (const float*)d_in[0];
    const int*   lengths = (const int*)d_in[1];
    const float* Wq = (const float*)d_in[2];
    const float* Wk = (const float*)d_in[3];
    const float* Wv = (const float*)d_in[4];
    const float* Wo = (const float*)d_in[5];
    const float* ln1g = (const float*)d_in[6];
    const float* ln1b = (const float*)d_in[7];
    const float* ln2g = (const float*)d_in[8];
    const float* ln2b = (const float*)d_in[9];
    const float* w1 = (const float*)d_in[10];
    const float* b1 = (const float*)d_in[11];
    const float* w2 = (const float*)d_in[12];
    const float* b2 = (const float*)d_in[13];

    float* px;
    f16 *ph, *pqkv, *pf, *pwh;
    cudaGetSymbolAddress((void**)&px, g_x);
    cudaGetSymbolAddress((void**)&ph, g_h);
    cudaGetSymbolAddress((void**)&pqkv, g_qkv);
    cudaGetSymbolAddress((void**)&pf, g_f);
    cudaGetSymbolAddress((void**)&pwh, g_wh);

    cudaFuncSetAttribute(k_fattn, cudaFuncAttributeMaxDynamicSharedMemorySize, FSMEM);
    cudaFuncSetAttribute(k_mm<1, false, false, false>,
                         cudaFuncAttributeMaxDynamicSharedMemorySize, GSMEM);
    cudaFuncSetAttribute(k_mm<0, false, false, true>,
                         cudaFuncAttributeMaxDynamicSharedMemorySize, GSMEM);
    cudaFuncSetAttribute(k_mm<1, true, true, false>,
                         cudaFuncAttributeMaxDynamicSharedMemorySize, GSMEM);
    cudaFuncSetAttribute(k_mm<0, true, false, true>,
                         cudaFuncAttributeMaxDynamicSharedMemorySize, GSMEM);

    k_init<<<NB_W + NB_P, 256>>>(Wq, Wk, Wv, Wo, w1, w2, pwh, x_in, px);

    dim3 gQKV(QKVS / GBN, BL / GBM);   // (12, 64)
    dim3 gD(DMODEL / GBN, BL / GBM);   // (4, 64)
    dim3 gF(DFF / GBN, BL / GBM);      // (16, 64)
    dim3 gA(SEQL / FBR, NHEAD, BATCH);

    for (int layer = 0; layer < NLAYER; layer++) {
        const f16* qkvw = pwh + OFF_QKV + (size_t)layer * DMODEL * QKVS;
        const f16* wow  = pwh + OFF_WO + (size_t)layer * DMODEL * DMODEL;
        const f16* w1w  = pwh + OFF_W1 + (size_t)layer * DMODEL * DFF;
        const f16* w2w  = pwh + OFF_W2 + (size_t)layer * DFF * DMODEL;

        k_ln<<<BL, 128>>>(px, ln1g + (size_t)layer * DMODEL, ln1b + (size_t)layer * DMODEL, ph);
        k_mm<1, false, false, false><<<gQKV, 256, GSMEM>>>(
            ph, qkvw, nullptr, nullptr, nullptr, pqkv, BL, QKVS, DMODEL);
        k_fattn<<<gA, 256, FSMEM>>>(pqkv, lengths, ph);
        k_mm<0, false, false, true><<<gD, 256, GSMEM>>>(
            ph, wow, nullptr, px, px, nullptr, BL, DMODEL, DMODEL);

        k_ln<<<BL, 128>>>(px, ln2g + (size_t)layer * DMODEL, ln2b + (size_t)layer * DMODEL, ph);
        k_mm<1, true, true, false><<<gF, 256, GSMEM>>>(
            ph, w1w, b1 + (size_t)layer * DFF, nullptr, nullptr, pf, BL, DFF, DMODEL);
        float* dst = (layer == NLAYER - 1) ? (float*)d_out : px;
        k_mm<0, true, false, true><<<gD, 256, GSMEM>>>(
            pf, w2w, b2 + (size_t)layer * DMODEL, px, dst, nullptr, BL, DMODEL, DFF);
    }
}